// round 11
// baseline (speedup 1.0000x reference)
#include <cuda_runtime.h>
#include <cuda_fp16.h>
#include <math.h>
#include <stdint.h>

#define NN 20000
#define NE 320000
#define NHEADS 4
#define NREL 40
#define FIN 768
#define HID 128
#define NCLS 9

// ---------------- scratch ---------------------------------------------------
__device__ __align__(16) float g_h[NN * NHEADS * NCLS];         // final-layer h [N,36]
__device__ __align__(16) __half g_Hh[NN * NHEADS * HID];        // GEMM out fp16 [N,512]
__device__ __align__(16) float g_tmp[NN * NHEADS * HID];
__device__ __align__(16) float g_x[NN * HID];
__device__ __align__(16) float g_hin[NN * HID];
__device__ __align__(16) float g_es[NN * NHEADS];
__device__ __align__(16) float g_ed[NN * NHEADS];
__device__ __align__(16) __half g_A2[NN * 2 * FIN];             // [M,2K] hi|lo fp16
__device__ __align__(16) __half g_B1[(NHEADS * HID) * FIN];     // [512,K] fp16
__device__ int g_cnt[NN];
__device__ int g_rowptr[NN + 1];
__device__ int g_fill[NN];
__device__ int g_eids[NE];
__device__ float g_bsum[4 * HID];
__device__ float g_bsq[4 * HID];

__device__ __forceinline__ int clampi(int v, int lo, int hi) {
    return v < lo ? lo : (v > hi ? hi : v);
}

__device__ __forceinline__ uint32_t smem_u32(const void* p) {
    uint32_t a;
    asm("{ .reg .u64 t; cvta.to.shared.u64 t, %1; cvt.u32.u64 %0, t; }"
        : "=r"(a) : "l"(p));
    return a;
}

__device__ __forceinline__ void ldsm_x4(uint32_t* r, uint32_t addr) {
    asm volatile("ldmatrix.sync.aligned.m8n8.x4.shared.b16 {%0,%1,%2,%3}, [%4];"
                 : "=r"(r[0]), "=r"(r[1]), "=r"(r[2]), "=r"(r[3]) : "r"(addr));
}

__device__ __forceinline__ void mma16816(float* d, const uint32_t* a, uint32_t b0,
                                         uint32_t b1) {
    asm volatile(
        "mma.sync.aligned.m16n8k16.row.col.f32.f16.f16.f32 "
        "{%0,%1,%2,%3}, {%4,%5,%6,%7}, {%8,%9}, {%0,%1,%2,%3};"
        : "+f"(d[0]), "+f"(d[1]), "+f"(d[2]), "+f"(d[3])
        : "r"(a[0]), "r"(a[1]), "r"(a[2]), "r"(a[3]), "r"(b0), "r"(b1));
}

__device__ __forceinline__ void cp16(uint32_t saddr, const void* g, bool pred) {
    int sz = pred ? 16 : 0;
    asm volatile("cp.async.cg.shared.global [%0], [%1], 16, %2;"
                 :: "r"(saddr), "l"(g), "r"(sz));
}
#define CP_COMMIT() asm volatile("cp.async.commit_group;" ::: "memory")
#define CP_WAIT2() asm volatile("cp.async.wait_group 2;" ::: "memory")
#define CP_WAIT1() asm volatile("cp.async.wait_group 1;" ::: "memory")
#define CP_WAIT0() asm volatile("cp.async.wait_group 0;" ::: "memory")

// ---------------- fp16 2-term GEMM, K-chunk 32, 3-stage, fp16 H, es/ed -----
#define SMS 40
#define TILEB 10240
#define STAGEB (3 * TILEB)
#define NSTAGE 3
__global__ void __launch_bounds__(256, 2)
mma_gemm_k(const __half* __restrict__ A2, const __half* __restrict__ B1,
           const float* __restrict__ a_s, const float* __restrict__ a_d,
           __half* __restrict__ H, float* __restrict__ es, float* __restrict__ ed,
           int M, int K) {
    extern __shared__ char sm[];
    uint32_t s0 = smem_u32(sm);
    int tid = threadIdx.x;
    int wid = tid >> 5;
    int lane = tid & 31;
    int warp_m = wid & 3;
    int warp_n = wid >> 2;
    int row0 = blockIdx.y * 128;
    int col0 = blockIdx.x * 128;

    float acc[2][8][4];
#pragma unroll
    for (int i = 0; i < 2; i++)
#pragma unroll
        for (int j = 0; j < 8; j++)
#pragma unroll
            for (int q = 0; q < 4; q++) acc[i][j][q] = 0.f;

    int ksz = K / 32;
    int lr = tid >> 1;
    int lq = (tid & 1) * 16;
    int gr = row0 + lr;
    bool aval = gr < M;
    const __half* Abase = A2 + (size_t)(aval ? gr : 0) * (2 * K);
    const __half* Bbase = B1 + (size_t)(col0 + lr) * K;
    uint32_t sA = (uint32_t)((lr * SMS + lq) * 2);

#define ISSUE_STAGE(c) do {                                              \
        int _kb = (c) * 32;                                              \
        uint32_t _b = s0 + ((c) % NSTAGE) * STAGEB;                      \
        const __half* _g;                                                \
        _g = Abase + _kb + lq;                                           \
        cp16(_b + 0 * TILEB + sA, _g, aval);                             \
        cp16(_b + 0 * TILEB + sA + 16, _g + 8, aval);                    \
        _g = Abase + K + _kb + lq;                                       \
        cp16(_b + 1 * TILEB + sA, _g, aval);                             \
        cp16(_b + 1 * TILEB + sA + 16, _g + 8, aval);                    \
        _g = Bbase + _kb + lq;                                           \
        cp16(_b + 2 * TILEB + sA, _g, true);                             \
        cp16(_b + 2 * TILEB + sA + 16, _g + 8, true);                    \
        CP_COMMIT();                                                     \
    } while (0)

    ISSUE_STAGE(0);
    if (ksz > 1) ISSUE_STAGE(1);
    for (int c = 0; c < ksz; c++) {
        if (c + 2 < ksz) {
            ISSUE_STAGE(c + 2);
            CP_WAIT2();
        } else if (c + 1 < ksz) {
            CP_WAIT1();
        } else {
            CP_WAIT0();
        }
        __syncthreads();
        uint32_t base = s0 + (c % NSTAGE) * STAGEB;
#pragma unroll
        for (int k16 = 0; k16 < 32; k16 += 16) {
            uint32_t koff = (uint32_t)((k16 + ((lane >> 4) << 3)) * 2);
            uint32_t ah[2][4], al[2][4];
#pragma unroll
            for (int mf = 0; mf < 2; mf++) {
                int m = warp_m * 32 + mf * 16 + (lane & 15);
                uint32_t ro = (uint32_t)(m * SMS * 2) + koff;
                ldsm_x4(ah[mf], base + 0 * TILEB + ro);
                ldsm_x4(al[mf], base + 1 * TILEB + ro);
            }
#pragma unroll
            for (int jp = 0; jp < 4; jp++) {
                int n = warp_n * 64 + jp * 16 + (lane & 15);
                uint32_t ro = (uint32_t)(n * SMS * 2) + koff;
                uint32_t bf[4];
                ldsm_x4(bf, base + 2 * TILEB + ro);
#pragma unroll
                for (int mf = 0; mf < 2; mf++) {
                    mma16816(acc[mf][jp * 2 + 0], ah[mf], bf[0], bf[2]);
                    mma16816(acc[mf][jp * 2 + 1], ah[mf], bf[1], bf[3]);
                    mma16816(acc[mf][jp * 2 + 0], al[mf], bf[0], bf[2]);
                    mma16816(acc[mf][jp * 2 + 1], al[mf], bf[1], bf[3]);
                }
            }
        }
        __syncthreads();
    }
#undef ISSUE_STAGE

    int g = lane >> 2, t = lane & 3;
#pragma unroll
    for (int mf = 0; mf < 2; mf++) {
#pragma unroll
        for (int nf = 0; nf < 8; nf++) {
            int col = col0 + warp_n * 64 + nf * 8 + t * 2;
            int r0 = row0 + warp_m * 32 + mf * 16 + g;
            if (r0 < M)
                *(__half2*)(H + (size_t)r0 * 512 + col) =
                    __floats2half2_rn(acc[mf][nf][0], acc[mf][nf][1]);
            int r1 = r0 + 8;
            if (r1 < M)
                *(__half2*)(H + (size_t)r1 * 512 + col) =
                    __floats2half2_rn(acc[mf][nf][2], acc[mf][nf][3]);
        }
    }

    // fused es/ed: head = blockIdx.x
    {
        const float* asg = a_s + blockIdx.x * 128;
        const float* adg = a_d + blockIdx.x * 128;
        float ps[2][2] = {{0.f, 0.f}, {0.f, 0.f}};
        float pd[2][2] = {{0.f, 0.f}, {0.f, 0.f}};
#pragma unroll
        for (int nf = 0; nf < 8; nf++) {
#pragma unroll
            for (int j = 0; j < 2; j++) {
                int cw = warp_n * 64 + nf * 8 + t * 2 + j;
                float av = __ldg(asg + cw);
                float dv = __ldg(adg + cw);
#pragma unroll
                for (int mf = 0; mf < 2; mf++) {
                    ps[mf][0] += acc[mf][nf][j] * av;
                    ps[mf][1] += acc[mf][nf][2 + j] * av;
                    pd[mf][0] += acc[mf][nf][j] * dv;
                    pd[mf][1] += acc[mf][nf][2 + j] * dv;
                }
            }
        }
#pragma unroll
        for (int mf = 0; mf < 2; mf++)
#pragma unroll
            for (int hf = 0; hf < 2; hf++) {
#pragma unroll
                for (int off = 1; off <= 2; off <<= 1) {
                    ps[mf][hf] += __shfl_xor_sync(0xffffffffu, ps[mf][hf], off);
                    pd[mf][hf] += __shfl_xor_sync(0xffffffffu, pd[mf][hf], off);
                }
            }
        float* se = (float*)sm;
        float* sd = se + 256;
        if (t == 0) {
#pragma unroll
            for (int mf = 0; mf < 2; mf++)
#pragma unroll
                for (int hf = 0; hf < 2; hf++) {
                    int row = warp_m * 32 + mf * 16 + g + hf * 8;
                    se[row * 2 + warp_n] = ps[mf][hf];
                    sd[row * 2 + warp_n] = pd[mf][hf];
                }
        }
        __syncthreads();
        if (tid < 128) {
            int grr = row0 + tid;
            if (grr < M) {
                es[grr * 4 + blockIdx.x] = se[tid * 2] + se[tid * 2 + 1];
                ed[grr * 4 + blockIdx.x] = sd[tid * 2] + sd[tid * 2 + 1];
            }
        }
    }
}

// ---------------- fp32 -> fp16 hi/lo split (layer 0 input) -----------------
__global__ void convA_k(const float* __restrict__ X, __half* __restrict__ A2,
                        int M, int K) {
    int i = blockIdx.x * blockDim.x + threadIdx.x;
    if (i >= M * K) return;
    int r = i / K, k = i - r * K;
    float v = X[i];
    __half h = __float2half_rn(v);
    __half l = __float2half_rn(v - __half2float(h));
    size_t base = (size_t)r * 2 * K;
    A2[base + k] = h;
    A2[base + K + k] = l;
}

// W [H,K,O] -> B1 [(h*O+o), K] fp16
__global__ void convB_k(const float* __restrict__ W, __half* __restrict__ B1,
                        int K, int O) {
    int idx = blockIdx.x * blockDim.x + threadIdx.x;
    int tot = NHEADS * K * O;
    if (idx >= tot) return;
    int o = idx % O;
    int f = (idx / O) % K;
    int h = idx / (O * K);
    B1[(size_t)(h * O + o) * K + f] = __float2half_rn(W[idx]);
}

// ---------------- init: zero cnt + bn stat buffers -------------------------
__global__ void init_zero_k(int* cnt, float* bsum, float* bsq) {
    int i = blockIdx.x * blockDim.x + threadIdx.x;
    if (i < NN) cnt[i] = 0;
    if (i < 4 * HID) { bsum[i] = 0.f; bsq[i] = 0.f; }
}

__global__ void count_k(const int* __restrict__ dst, int* __restrict__ cnt) {
    int e = blockIdx.x * blockDim.x + threadIdx.x;
    if (e < NE) atomicAdd(&cnt[clampi(dst[e], 0, NN - 1)], 1);
}

__global__ void scan_k(const int* __restrict__ cnt, int* __restrict__ rowptr,
                       int* __restrict__ fill) {
    __shared__ int sh[1024];
    int tid = threadIdx.x;
    int carry = 0;
    if (tid == 0) rowptr[0] = 0;
    for (int base = 0; base < NN; base += 1024) {
        int i = base + tid;
        int v = (i < NN) ? cnt[i] : 0;
        sh[tid] = v;
        __syncthreads();
        for (int off = 1; off < 1024; off <<= 1) {
            int t = (tid >= off) ? sh[tid - off] : 0;
            __syncthreads();
            sh[tid] += t;
            __syncthreads();
        }
        int incl = sh[tid];
        if (i < NN) {
            rowptr[i + 1] = carry + incl;
            fill[i] = carry + incl - v;
        }
        carry += sh[1023];
        __syncthreads();
    }
}

__global__ void scatter_k(const int* __restrict__ dst, int* __restrict__ fill,
                          int* __restrict__ eids) {
    int e = blockIdx.x * blockDim.x + threadIdx.x;
    if (e < NE) {
        int d = clampi(dst[e], 0, NN - 1);
        int pos = atomicAdd(&fill[d], 1);
        if (pos >= 0 && pos < NE) eids[pos] = e;
    }
}

__device__ __forceinline__ float lrelu02(float v) { return v > 0.f ? v : 0.2f * v; }

// ---------------- fused attention (eetab smem, pipelined gather) -----------
__global__ void attn_k(const __half* __restrict__ H, const float* __restrict__ es,
                       const float* __restrict__ ed, const float* __restrict__ rel,
                       const float* __restrict__ ae, const int* __restrict__ src,
                       const int* __restrict__ etype, const int* __restrict__ edist,
                       const int* __restrict__ rowptr, const int* __restrict__ eids,
                       float4* __restrict__ alpha, const float* __restrict__ b,
                       const float* __restrict__ resid, float* __restrict__ out) {
    __shared__ __align__(16) float eetab[NREL * NHEADS];
    int tid = threadIdx.x;
    if (tid < NREL * NHEADS) {
        int r = tid >> 2, hd = tid & 3;
        eetab[tid] = rel[r * 2] * ae[hd * 2] + rel[r * 2 + 1] * ae[hd * 2 + 1];
    }
    __syncthreads();

    int n = (blockIdx.x * blockDim.x + tid) >> 5;
    int lane = tid & 31;
    if (n >= NN) return;
    int beg = rowptr[n], end = rowptr[n + 1];
    float4 edn = *(const float4*)(ed + n * 4);

    // pass 1: logits + max
    float4 m = make_float4(-3.4e38f, -3.4e38f, -3.4e38f, -3.4e38f);
    for (int i = beg + lane; i < end; i += 32) {
        int e = eids[i];
        int s = clampi(src[e], 0, NN - 1);
        int t = clampi(etype[e], 0, NREL - 1);
        float4 a = *(const float4*)(es + s * 4);
        float4 c = *(const float4*)(eetab + t * 4);
        float4 lg;
        lg.x = lrelu02(a.x + edn.x + c.x);
        lg.y = lrelu02(a.y + edn.y + c.y);
        lg.z = lrelu02(a.z + edn.z + c.z);
        lg.w = lrelu02(a.w + edn.w + c.w);
        alpha[i] = lg;
        m.x = fmaxf(m.x, lg.x); m.y = fmaxf(m.y, lg.y);
        m.z = fmaxf(m.z, lg.z); m.w = fmaxf(m.w, lg.w);
    }
#pragma unroll
    for (int off = 16; off; off >>= 1) {
        m.x = fmaxf(m.x, __shfl_xor_sync(0xffffffffu, m.x, off));
        m.y = fmaxf(m.y, __shfl_xor_sync(0xffffffffu, m.y, off));
        m.z = fmaxf(m.z, __shfl_xor_sync(0xffffffffu, m.z, off));
        m.w = fmaxf(m.w, __shfl_xor_sync(0xffffffffu, m.w, off));
    }
    // pass 2: exp + den
    float4 den = make_float4(0.f, 0.f, 0.f, 0.f);
    for (int i = beg + lane; i < end; i += 32) {
        float4 v = alpha[i];
        float4 ex;
        ex.x = __expf(v.x - m.x); ex.y = __expf(v.y - m.y);
        ex.z = __expf(v.z - m.z); ex.w = __expf(v.w - m.w);
        alpha[i] = ex;
        den.x += ex.x; den.y += ex.y; den.z += ex.z; den.w += ex.w;
    }
#pragma unroll
    for (int off = 16; off; off >>= 1) {
        den.x += __shfl_xor_sync(0xffffffffu, den.x, off);
        den.y += __shfl_xor_sync(0xffffffffu, den.y, off);
        den.z += __shfl_xor_sync(0xffffffffu, den.z, off);
        den.w += __shfl_xor_sync(0xffffffffu, den.w, off);
    }
    float4 inv;
    inv.x = 1.0f / (den.x + 1e-16f); inv.y = 1.0f / (den.y + 1e-16f);
    inv.z = 1.0f / (den.z + 1e-16f); inv.w = 1.0f / (den.w + 1e-16f);
    __syncwarp();

    // pass 3: software-pipelined gather + head-mean + bias + residual
    float2 accA[NHEADS], accB[NHEADS];
#pragma unroll
    for (int q = 0; q < NHEADS; q++) {
        accA[q] = make_float2(0.f, 0.f);
        accB[q] = make_float2(0.f, 0.f);
    }
    if (beg < end) {
        // preload edge beg
        float4 a; float w; __half2 hv[8];
        {
            int e = eids[beg];
            int s = clampi(src[e], 0, NN - 1);
            a = alpha[beg];
            w = 1.0f / (1.0f + (float)edist[e]);
            const __half2* hs2 = (const __half2*)(H + (size_t)s * 512);
#pragma unroll
            for (int q = 0; q < NHEADS; q++) {
                hv[q * 2] = hs2[q * 64 + lane];
                hv[q * 2 + 1] = hs2[q * 64 + 32 + lane];
            }
        }
        for (int i = beg; i < end; i++) {
            float aw[4] = {a.x * inv.x * w, a.y * inv.y * w, a.z * inv.z * w,
                           a.w * inv.w * w};
            // prefetch next edge
            float4 a1 = a; float w1 = w; __half2 hv1[8];
#pragma unroll
            for (int q = 0; q < 8; q++) hv1[q] = hv[q];
            if (i + 1 < end) {
                int e1 = eids[i + 1];
                int s1 = clampi(src[e1], 0, NN - 1);
                a1 = alpha[i + 1];
                w1 = 1.0f / (1.0f + (float)edist[e1]);
                const __half2* hs2n = (const __half2*)(H + (size_t)s1 * 512);
#pragma unroll
                for (int q = 0; q < NHEADS; q++) {
                    hv1[q * 2] = hs2n[q * 64 + lane];
                    hv1[q * 2 + 1] = hs2n[q * 64 + 32 + lane];
                }
            }
            // accumulate current
#pragma unroll
            for (int q = 0; q < NHEADS; q++) {
                float2 fa = __half22float2(hv[q * 2]);
                float2 fb = __half22float2(hv[q * 2 + 1]);
                accA[q].x += aw[q] * fa.x; accA[q].y += aw[q] * fa.y;
                accB[q].x += aw[q] * fb.x; accB[q].y += aw[q] * fb.y;
            }
            a = a1; w = w1;
#pragma unroll
            for (int q = 0; q < 8; q++) hv[q] = hv1[q];
        }
    }
    {
        int oA = 2 * lane, oB = 64 + 2 * lane;
        float2 bA = *(const float2*)(b + oA);
        float2 bB = *(const float2*)(b + oB);
        float2 vA, vB;
        vA.x = 0.25f * (accA[0].x + accA[1].x + accA[2].x + accA[3].x) + bA.x;
        vA.y = 0.25f * (accA[0].y + accA[1].y + accA[2].y + accA[3].y) + bA.y;
        vB.x = 0.25f * (accB[0].x + accB[1].x + accB[2].x + accB[3].x) + bB.x;
        vB.y = 0.25f * (accB[0].y + accB[1].y + accB[2].y + accB[3].y) + bB.y;
        if (resid) {
            float2 rA = *(const float2*)(resid + (size_t)n * 128 + oA);
            float2 rB = *(const float2*)(resid + (size_t)n * 128 + oB);
            vA.x += rA.x; vA.y += rA.y; vB.x += rB.x; vB.y += rB.y;
        }
        *(float2*)(out + (size_t)n * 128 + oA) = vA;
        *(float2*)(out + (size_t)n * 128 + oB) = vB;
    }
}

// ---------------- final-layer linear + es/ed (warp per node) ---------------
__global__ void __launch_bounds__(256)
finL_k(const float* __restrict__ hin, const float* __restrict__ WL,
       const float* __restrict__ asrcL, const float* __restrict__ adstL,
       float* __restrict__ h, float* __restrict__ es, float* __restrict__ ed) {
    __shared__ float Wsm[HID][NHEADS * NCLS];
    __shared__ float asm_[NHEADS * NCLS], adm_[NHEADS * NCLS];
    int tid = threadIdx.x;
    for (int idx = tid; idx < HID * NHEADS * NCLS; idx += blockDim.x) {
        int j = idx % (NHEADS * NCLS);
        int k = idx / (NHEADS * NCLS);
        int hh = j / NCLS, c = j % NCLS;
        Wsm[k][j] = WL[((size_t)hh * HID + k) * NCLS + c];
    }
    if (tid < NHEADS * NCLS) { asm_[tid] = asrcL[tid]; adm_[tid] = adstL[tid]; }
    __syncthreads();

    int n = blockIdx.x * (blockDim.x >> 5) + (tid >> 5);
    int lane = tid & 31;
    if (n >= NN) return;
    const float* row = hin + (size_t)n * HID;
    float x0 = row[lane], x1 = row[lane + 32], x2 = row[lane + 64],
          x3 = row[lane + 96];
    float acc[NHEADS * NCLS];
#pragma unroll
    for (int j = 0; j < NHEADS * NCLS; j++)
        acc[j] = x0 * Wsm[lane][j] + x1 * Wsm[lane + 32][j] +
                 x2 * Wsm[lane + 64][j] + x3 * Wsm[lane + 96][j];
#pragma unroll
    for (int j = 0; j < NHEADS * NCLS; j++)
#pragma unroll
        for (int off = 16; off; off >>= 1)
            acc[j] += __shfl_xor_sync(0xffffffffu, acc[j], off);

    float* hout = h + (size_t)n * (NHEADS * NCLS);
#pragma unroll
    for (int j = 0; j < NHEADS * NCLS; j++)
        if (lane == (j & 31)) hout[j] = acc[j];

    if (lane == 0) {
        float esh[NHEADS] = {0.f, 0.f, 0.f, 0.f};
        float edh[NHEADS] = {0.f, 0.f, 0.f, 0.f};
#pragma unroll
        for (int j = 0; j < NHEADS * NCLS; j++) {
            esh[j / NCLS] += acc[j] * asm_[j];
            edh[j / NCLS] += acc[j] * adm_[j];
        }
#pragma unroll
        for (int q = 0; q < NHEADS; q++) {
            es[n * 4 + q] = esh[q];
            ed[n * 4 + q] = edh[q];
        }
    }
}

// ---------------- final-layer softmax (standalone, eetab smem) -------------
__global__ void lsm_k(const float* __restrict__ es, const float* __restrict__ ed,
                      const float* __restrict__ rel, const float* __restrict__ ae,
                      const int* __restrict__ src, const int* __restrict__ etype,
                      const int* __restrict__ edist, const int* __restrict__ rowptr,
                      const int* __restrict__ eids, float4* __restrict__ alpha) {
    __shared__ __align__(16) float eetab[NREL * NHEADS];
    int tid = threadIdx.x;
    if (tid < NREL * NHEADS) {
        int r = tid >> 2, hd = tid & 3;
        eetab[tid] = rel[r * 2] * ae[hd * 2] + rel[r * 2 + 1] * ae[hd * 2 + 1];
    }
    __syncthreads();

    int n = (blockIdx.x * blockDim.x + tid) >> 5;
    int lane = tid & 31;
    if (n >= NN) return;
    int beg = rowptr[n], end = rowptr[n + 1];
    float4 edn = *(const float4*)(ed + n * 4);

    float4 m = make_float4(-3.4e38f, -3.4e38f, -3.4e38f, -3.4e38f);
    for (int i = beg + lane; i < end; i += 32) {
        int e = eids[i];
        int s = clampi(src[e], 0, NN - 1);
        int t = clampi(etype[e], 0, NREL - 1);
        float4 a = *(const float4*)(es + s * 4);
        float4 c = *(const float4*)(eetab + t * 4);
        float4 lg;
        lg.x = lrelu02(a.x + edn.x + c.x);
        lg.y = lrelu02(a.y + edn.y + c.y);
        lg.z = lrelu02(a.z + edn.z + c.z);
        lg.w = lrelu02(a.w + edn.w + c.w);
        alpha[i] = lg;
        m.x = fmaxf(m.x, lg.x); m.y = fmaxf(m.y, lg.y);
        m.z = fmaxf(m.z, lg.z); m.w = fmaxf(m.w, lg.w);
    }
#pragma unroll
    for (int off = 16; off; off >>= 1) {
        m.x = fmaxf(m.x, __shfl_xor_sync(0xffffffffu, m.x, off));
        m.y = fmaxf(m.y, __shfl_xor_sync(0xffffffffu, m.y, off));
        m.z = fmaxf(m.z, __shfl_xor_sync(0xffffffffu, m.z, off));
        m.w = fmaxf(m.w, __shfl_xor_sync(0xffffffffu, m.w, off));
    }
    float4 den = make_float4(0.f, 0.f, 0.f, 0.f);
    for (int i = beg + lane; i < end; i += 32) {
        float4 v = alpha[i];
        float4 ex;
        ex.x = __expf(v.x - m.x); ex.y = __expf(v.y - m.y);
        ex.z = __expf(v.z - m.z); ex.w = __expf(v.w - m.w);
        alpha[i] = ex;
        den.x += ex.x; den.y += ex.y; den.z += ex.z; den.w += ex.w;
    }
#pragma unroll
    for (int off = 16; off; off >>= 1) {
        den.x += __shfl_xor_sync(0xffffffffu, den.x, off);
        den.y += __shfl_xor_sync(0xffffffffu, den.y, off);
        den.z += __shfl_xor_sync(0xffffffffu, den.z, off);
        den.w += __shfl_xor_sync(0xffffffffu, den.w, off);
    }
    float4 inv;
    inv.x = 1.0f / (den.x + 1e-16f); inv.y = 1.0f / (den.y + 1e-16f);
    inv.z = 1.0f / (den.z + 1e-16f); inv.w = 1.0f / (den.w + 1e-16f);
    for (int i = beg + lane; i < end; i += 32) {
        float4 v = alpha[i];
        float w = 1.0f / (1.0f + (float)edist[eids[i]]);
        v.x *= inv.x * w; v.y *= inv.y * w;
        v.z *= inv.z * w; v.w *= inv.w * w;
        alpha[i] = v;
    }
}

// ---------------- final layer gather (O=9) + combine + lrelu ---------------
__global__ void aggF_k(const float* __restrict__ h, const float4* __restrict__ alpha4,
                       const int* __restrict__ src, const int* __restrict__ eids,
                       const int* __restrict__ rowptr, const float* __restrict__ b,
                       float* __restrict__ out) {
    int n = (blockIdx.x * blockDim.x + threadIdx.x) >> 5;
    int lane = threadIdx.x & 31;
    if (n >= NN) return;
    int beg = rowptr[n], end = rowptr[n + 1];
    float acc[NHEADS] = {0.f, 0.f, 0.f, 0.f};
    for (int i = beg; i < end; i++) {
        int e = eids[i];
        int s = clampi(src[e], 0, NN - 1);
        float4 a = alpha4[i];
        float aw[4] = {a.x, a.y, a.z, a.w};
        if (lane < NCLS) {
            const float* hs = h + (size_t)s * (NHEADS * NCLS);
#pragma unroll
            for (int q = 0; q < NHEADS; q++) acc[q] += aw[q] * hs[q * NCLS + lane];
        }
    }
    if (lane < NCLS) {
        float v = 0.25f * (acc[0] + acc[1] + acc[2] + acc[3]) + b[lane];
        out[(size_t)n * NCLS + lane] = v > 0.f ? v : 0.1f * v;
    }
}

// ---------------- batch norm -----------------------------------------------
__global__ void bn_stats_k(const float* __restrict__ x, float* __restrict__ sum,
                           float* __restrict__ sumsq) {
    int t = threadIdx.x;
    int rows_per = (NN + gridDim.x - 1) / gridDim.x;
    int r0 = blockIdx.x * rows_per;
    int r1 = min(r0 + rows_per, NN);
    float s = 0.f, q = 0.f;
    for (int r = r0; r < r1; r++) {
        float v = x[(size_t)r * HID + t];
        s += v;
        q += v * v;
    }
    atomicAdd(&sum[t], s);
    atomicAdd(&sumsq[t], q);
}

__global__ void bn_apply_k(const float* __restrict__ x, const float* __restrict__ sum,
                           const float* __restrict__ sumsq, const float* __restrict__ g,
                           const float* __restrict__ b, float* __restrict__ out,
                           __half* __restrict__ A2) {
    int i = blockIdx.x * blockDim.x + threadIdx.x;
    if (i >= NN * HID) return;
    int o = i & 127;
    int n = i >> 7;
    float mu = sum[o] * (1.0f / NN);
    float var = sumsq[o] * (1.0f / NN) - mu * mu;
    float v = (x[i] - mu) * rsqrtf(var + 1e-5f) * g[o] + b[o];
    v = v > 0.f ? v : 0.1f * v;
    out[i] = v;
    if (A2) {
        __half h = __float2half_rn(v);
        __half l = __float2half_rn(v - __half2float(h));
        size_t base = (size_t)n * 256;
        A2[base + o] = h;
        A2[base + 128 + o] = l;
    }
}

// ---------------- host orchestration ---------------------------------------
struct Bufs {
    float *h_buf, *tmp, *xb, *hin, *es, *ed, *bsum, *bsq;
    __half *Hh, *A2, *B1;
    int *cnt, *rowptr, *fill, *eids;
};

extern "C" void kernel_launch(void* const* d_in, const int* in_sizes, int n_in,
                              void* d_out, int out_size) {
    const float* x = (const float*)d_in[0];
    const int* ei = (const int*)d_in[1];
    const int* etype = (const int*)d_in[2];
    const int* edist = (const int*)d_in[3];
    const float* W0 = (const float*)d_in[4];
    const float* asrc0 = (const float*)d_in[5];
    const float* adst0 = (const float*)d_in[6];
    const float* aedge0 = (const float*)d_in[7];
    const float* b0 = (const float*)d_in[8];
    const float* rel0 = (const float*)d_in[9];
    const float* Wm = (const float*)d_in[10];
    const float* asrcm = (const float*)d_in[11];
    const float* adstm = (const float*)d_in[12];
    const float* aedgem = (const float*)d_in[13];
    const float* bm = (const float*)d_in[14];
    const float* relm = (const float*)d_in[15];
    const float* WL = (const float*)d_in[16];
    const float* asrcL = (const float*)d_in[17];
    const float* adstL = (const float*)d_in[18];
    const float* aedgeL = (const float*)d_in[19];
    const float* bL = (const float*)d_in[20];
    const float* relL = (const float*)d_in[21];
    const float* bn_g = (const float*)d_in[22];
    const float* bn_b = (const float*)d_in[23];

    static bool attr_set = false;
    if (!attr_set) {
        cudaFuncSetAttribute(mma_gemm_k, cudaFuncAttributeMaxDynamicSharedMemorySize,
                             NSTAGE * STAGEB);
        attr_set = true;
    }

    Bufs B;
    cudaGetSymbolAddress((void**)&B.h_buf, g_h);
    cudaGetSymbolAddress((void**)&B.Hh, g_Hh);
    cudaGetSymbolAddress((void**)&B.tmp, g_tmp);
    cudaGetSymbolAddress((void**)&B.xb, g_x);
    cudaGetSymbolAddress((void**)&B.hin, g_hin);
    cudaGetSymbolAddress((void**)&B.es, g_es);
    cudaGetSymbolAddress((void**)&B.ed, g_ed);
    cudaGetSymbolAddress((void**)&B.bsum, g_bsum);
    cudaGetSymbolAddress((void**)&B.bsq, g_bsq);
    cudaGetSymbolAddress((void**)&B.A2, g_A2);
    cudaGetSymbolAddress((void**)&B.B1, g_B1);
    cudaGetSymbolAddress((void**)&B.cnt, g_cnt);
    cudaGetSymbolAddress((void**)&B.rowptr, g_rowptr);
    cudaGetSymbolAddress((void**)&B.fill, g_fill);
    cudaGetSymbolAddress((void**)&B.eids, g_eids);

    const int* src = ei;
    const int* dst = ei + NE;
    float4* lg4 = (float4*)B.tmp;
    dim3 ggrid(4, (NN + 127) / 128);
    int attn_blocks = (NN * 32 + 255) / 256;

    // layer-0: convA(1), convB(2), init(3), mma(4 = profiled slot)
    int na = NN * FIN;
    convA_k<<<(na + 255) / 256, 256>>>(x, B.A2, NN, FIN);
    int nb = NHEADS * FIN * HID;
    convB_k<<<(nb + 255) / 256, 256>>>(W0, B.B1, FIN, HID);
    init_zero_k<<<(NN + 255) / 256, 256>>>(B.cnt, B.bsum, B.bsq);
    mma_gemm_k<<<ggrid, 256, NSTAGE * STAGEB>>>(B.A2, B.B1, asrc0, adst0, B.Hh,
                                                B.es, B.ed, NN, FIN);
    count_k<<<(NE + 255) / 256, 256>>>(dst, B.cnt);
    scan_k<<<1, 1024>>>(B.cnt, B.rowptr, B.fill);
    scatter_k<<<(NE + 255) / 256, 256>>>(dst, B.fill, B.eids);
    attn_k<<<attn_blocks, 256>>>(B.Hh, B.es, B.ed, rel0, aedge0, src, etype,
                                 edist, B.rowptr, B.eids, lg4, b0, nullptr, B.xb);

    int nb128 = (NN * HID + 255) / 256;

    for (int i = 0; i < 3; i++) {
        bn_stats_k<<<200, 128>>>(B.xb, B.bsum + i * HID, B.bsq + i * HID);
        bn_apply_k<<<nb128, 256>>>(B.xb, B.bsum + i * HID, B.bsq + i * HID,
                                   bn_g + i * HID, bn_b + i * HID, B.hin, B.A2);
        int nbm = NHEADS * HID * HID;
        convB_k<<<(nbm + 255) / 256, 256>>>(Wm + (size_t)i * NHEADS * HID * HID,
                                            B.B1, HID, HID);
        mma_gemm_k<<<ggrid, 256, NSTAGE * STAGEB>>>(
            B.A2, B.B1, asrcm + i * NHEADS * HID, adstm + i * NHEADS * HID,
            B.Hh, B.es, B.ed, NN, HID);
        attn_k<<<attn_blocks, 256>>>(B.Hh, B.es, B.ed, relm + i * NREL * 2,
                                     aedgem + i * NHEADS * 2, src, etype, edist,
                                     B.rowptr, B.eids, lg4, bm + i * HID, B.hin,
                                     B.xb);
    }

    // final layer
    bn_stats_k<<<200, 128>>>(B.xb, B.bsum + 3 * HID, B.bsq + 3 * HID);
    bn_apply_k<<<nb128, 256>>>(B.xb, B.bsum + 3 * HID, B.bsq + 3 * HID,
                               bn_g + 3 * HID, bn_b + 3 * HID, B.hin,
                               (__half*)nullptr);
    finL_k<<<(NN + 7) / 8, 256>>>(B.hin, WL, asrcL, adstL, B.h_buf, B.es, B.ed);
    lsm_k<<<attn_blocks, 256>>>(B.es, B.ed, relL, aedgeL, src, etype, edist,
                                B.rowptr, B.eids, lg4);
    aggF_k<<<attn_blocks, 256>>>(B.h_buf, lg4, src, B.eids, B.rowptr, bL,
                                 (float*)d_out);
}

// round 12
// speedup vs baseline: 1.0139x; 1.0139x over previous
#include <cuda_runtime.h>
#include <cuda_fp16.h>
#include <math.h>
#include <stdint.h>

#define NN 20000
#define NE 320000
#define NHEADS 4
#define NREL 40
#define FIN 768
#define HID 128
#define NCLS 9

// ---------------- scratch ---------------------------------------------------
__device__ __align__(16) float g_h[NN * NHEADS * HID];          // final-layer SIMT out
__device__ __align__(16) __half g_Hh[NN * NHEADS * HID];        // GEMM out fp16 [N,512]
__device__ __align__(16) float g_tmp[NN * NHEADS * HID];
__device__ __align__(16) float g_x[NN * HID];
__device__ __align__(16) float g_hin[NN * HID];
__device__ __align__(16) float g_es[NN * NHEADS];
__device__ __align__(16) float g_ed[NN * NHEADS];
__device__ __align__(16) float g_W[FIN * NHEADS * HID];
__device__ __align__(16) __half g_A2[NN * 2 * FIN];             // [M,2K] hi|lo fp16
__device__ __align__(16) __half g_B1[(NHEADS * HID) * FIN];     // [512,K] fp16
__device__ int g_cnt[NN];
__device__ int g_rowptr[NN + 1];
__device__ int g_fill[NN];
__device__ int g_eids[NE];
__device__ float g_bsum[4 * HID];
__device__ float g_bsq[4 * HID];

__device__ __forceinline__ int clampi(int v, int lo, int hi) {
    return v < lo ? lo : (v > hi ? hi : v);
}

__device__ __forceinline__ uint32_t smem_u32(const void* p) {
    uint32_t a;
    asm("{ .reg .u64 t; cvta.to.shared.u64 t, %1; cvt.u32.u64 %0, t; }"
        : "=r"(a) : "l"(p));
    return a;
}

__device__ __forceinline__ void ldsm_x4(uint32_t* r, uint32_t addr) {
    asm volatile("ldmatrix.sync.aligned.m8n8.x4.shared.b16 {%0,%1,%2,%3}, [%4];"
                 : "=r"(r[0]), "=r"(r[1]), "=r"(r[2]), "=r"(r[3]) : "r"(addr));
}

__device__ __forceinline__ void mma16816(float* d, const uint32_t* a, uint32_t b0,
                                         uint32_t b1) {
    asm volatile(
        "mma.sync.aligned.m16n8k16.row.col.f32.f16.f16.f32 "
        "{%0,%1,%2,%3}, {%4,%5,%6,%7}, {%8,%9}, {%0,%1,%2,%3};"
        : "+f"(d[0]), "+f"(d[1]), "+f"(d[2]), "+f"(d[3])
        : "r"(a[0]), "r"(a[1]), "r"(a[2]), "r"(a[3]), "r"(b0), "r"(b1));
}

__device__ __forceinline__ void cp16(uint32_t saddr, const void* g, bool pred) {
    int sz = pred ? 16 : 0;
    asm volatile("cp.async.cg.shared.global [%0], [%1], 16, %2;"
                 :: "r"(saddr), "l"(g), "r"(sz));
}
#define CP_COMMIT() asm volatile("cp.async.commit_group;" ::: "memory")
#define CP_WAIT2() asm volatile("cp.async.wait_group 2;" ::: "memory")
#define CP_WAIT1() asm volatile("cp.async.wait_group 1;" ::: "memory")
#define CP_WAIT0() asm volatile("cp.async.wait_group 0;" ::: "memory")

// ---------------- fp16 2-term GEMM, K-chunk 32, 3-stage, fp16 H, es/ed -----
#define SMS 40
#define TILEB 10240
#define STAGEB (3 * TILEB)
#define NSTAGE 3
__global__ void __launch_bounds__(256, 2)
mma_gemm_k(const __half* __restrict__ A2, const __half* __restrict__ B1,
           const float* __restrict__ a_s, const float* __restrict__ a_d,
           __half* __restrict__ H, float* __restrict__ es, float* __restrict__ ed,
           int M, int K) {
    extern __shared__ char sm[];
    uint32_t s0 = smem_u32(sm);
    int tid = threadIdx.x;
    int wid = tid >> 5;
    int lane = tid & 31;
    int warp_m = wid & 3;
    int warp_n = wid >> 2;
    int row0 = blockIdx.y * 128;
    int col0 = blockIdx.x * 128;

    float acc[2][8][4];
#pragma unroll
    for (int i = 0; i < 2; i++)
#pragma unroll
        for (int j = 0; j < 8; j++)
#pragma unroll
            for (int q = 0; q < 4; q++) acc[i][j][q] = 0.f;

    int ksz = K / 32;
    int lr = tid >> 1;
    int lq = (tid & 1) * 16;
    int gr = row0 + lr;
    bool aval = gr < M;
    const __half* Abase = A2 + (size_t)(aval ? gr : 0) * (2 * K);
    const __half* Bbase = B1 + (size_t)(col0 + lr) * K;
    uint32_t sA = (uint32_t)((lr * SMS + lq) * 2);

#define ISSUE_STAGE(c) do {                                              \
        int _kb = (c) * 32;                                              \
        uint32_t _b = s0 + ((c) % NSTAGE) * STAGEB;                      \
        const __half* _g;                                                \
        _g = Abase + _kb + lq;                                           \
        cp16(_b + 0 * TILEB + sA, _g, aval);                             \
        cp16(_b + 0 * TILEB + sA + 16, _g + 8, aval);                    \
        _g = Abase + K + _kb + lq;                                       \
        cp16(_b + 1 * TILEB + sA, _g, aval);                             \
        cp16(_b + 1 * TILEB + sA + 16, _g + 8, aval);                    \
        _g = Bbase + _kb + lq;                                           \
        cp16(_b + 2 * TILEB + sA, _g, true);                             \
        cp16(_b + 2 * TILEB + sA + 16, _g + 8, true);                    \
        CP_COMMIT();                                                     \
    } while (0)

    ISSUE_STAGE(0);
    if (ksz > 1) ISSUE_STAGE(1);
    for (int c = 0; c < ksz; c++) {
        if (c + 2 < ksz) {
            ISSUE_STAGE(c + 2);
            CP_WAIT2();
        } else if (c + 1 < ksz) {
            CP_WAIT1();
        } else {
            CP_WAIT0();
        }
        __syncthreads();
        uint32_t base = s0 + (c % NSTAGE) * STAGEB;
#pragma unroll
        for (int k16 = 0; k16 < 32; k16 += 16) {
            uint32_t koff = (uint32_t)((k16 + ((lane >> 4) << 3)) * 2);
            uint32_t ah[2][4], al[2][4];
#pragma unroll
            for (int mf = 0; mf < 2; mf++) {
                int m = warp_m * 32 + mf * 16 + (lane & 15);
                uint32_t ro = (uint32_t)(m * SMS * 2) + koff;
                ldsm_x4(ah[mf], base + 0 * TILEB + ro);
                ldsm_x4(al[mf], base + 1 * TILEB + ro);
            }
#pragma unroll
            for (int jp = 0; jp < 4; jp++) {
                int n = warp_n * 64 + jp * 16 + (lane & 15);
                uint32_t ro = (uint32_t)(n * SMS * 2) + koff;
                uint32_t bf[4];
                ldsm_x4(bf, base + 2 * TILEB + ro);
#pragma unroll
                for (int mf = 0; mf < 2; mf++) {
                    mma16816(acc[mf][jp * 2 + 0], ah[mf], bf[0], bf[2]);
                    mma16816(acc[mf][jp * 2 + 1], ah[mf], bf[1], bf[3]);
                    mma16816(acc[mf][jp * 2 + 0], al[mf], bf[0], bf[2]);
                    mma16816(acc[mf][jp * 2 + 1], al[mf], bf[1], bf[3]);
                }
            }
        }
        __syncthreads();
    }
#undef ISSUE_STAGE

    int g = lane >> 2, t = lane & 3;
#pragma unroll
    for (int mf = 0; mf < 2; mf++) {
#pragma unroll
        for (int nf = 0; nf < 8; nf++) {
            int col = col0 + warp_n * 64 + nf * 8 + t * 2;
            int r0 = row0 + warp_m * 32 + mf * 16 + g;
            if (r0 < M)
                *(__half2*)(H + (size_t)r0 * 512 + col) =
                    __floats2half2_rn(acc[mf][nf][0], acc[mf][nf][1]);
            int r1 = r0 + 8;
            if (r1 < M)
                *(__half2*)(H + (size_t)r1 * 512 + col) =
                    __floats2half2_rn(acc[mf][nf][2], acc[mf][nf][3]);
        }
    }

    // fused es/ed: head = blockIdx.x
    {
        const float* asg = a_s + blockIdx.x * 128;
        const float* adg = a_d + blockIdx.x * 128;
        float ps[2][2] = {{0.f, 0.f}, {0.f, 0.f}};
        float pd[2][2] = {{0.f, 0.f}, {0.f, 0.f}};
#pragma unroll
        for (int nf = 0; nf < 8; nf++) {
#pragma unroll
            for (int j = 0; j < 2; j++) {
                int cw = warp_n * 64 + nf * 8 + t * 2 + j;
                float av = __ldg(asg + cw);
                float dv = __ldg(adg + cw);
#pragma unroll
                for (int mf = 0; mf < 2; mf++) {
                    ps[mf][0] += acc[mf][nf][j] * av;
                    ps[mf][1] += acc[mf][nf][2 + j] * av;
                    pd[mf][0] += acc[mf][nf][j] * dv;
                    pd[mf][1] += acc[mf][nf][2 + j] * dv;
                }
            }
        }
#pragma unroll
        for (int mf = 0; mf < 2; mf++)
#pragma unroll
            for (int hf = 0; hf < 2; hf++) {
#pragma unroll
                for (int off = 1; off <= 2; off <<= 1) {
                    ps[mf][hf] += __shfl_xor_sync(0xffffffffu, ps[mf][hf], off);
                    pd[mf][hf] += __shfl_xor_sync(0xffffffffu, pd[mf][hf], off);
                }
            }
        float* se = (float*)sm;
        float* sd = se + 256;
        if (t == 0) {
#pragma unroll
            for (int mf = 0; mf < 2; mf++)
#pragma unroll
                for (int hf = 0; hf < 2; hf++) {
                    int row = warp_m * 32 + mf * 16 + g + hf * 8;
                    se[row * 2 + warp_n] = ps[mf][hf];
                    sd[row * 2 + warp_n] = pd[mf][hf];
                }
        }
        __syncthreads();
        if (tid < 128) {
            int grr = row0 + tid;
            if (grr < M) {
                es[grr * 4 + blockIdx.x] = se[tid * 2] + se[tid * 2 + 1];
                ed[grr * 4 + blockIdx.x] = sd[tid * 2] + sd[tid * 2 + 1];
            }
        }
    }
}

// ---------------- fp32 -> fp16 hi/lo split (layer 0 input) -----------------
__global__ void convA_k(const float* __restrict__ X, __half* __restrict__ A2,
                        int M, int K) {
    int i = blockIdx.x * blockDim.x + threadIdx.x;
    if (i >= M * K) return;
    int r = i / K, k = i - r * K;
    float v = X[i];
    __half h = __float2half_rn(v);
    __half l = __float2half_rn(v - __half2float(h));
    size_t base = (size_t)r * 2 * K;
    A2[base + k] = h;
    A2[base + K + k] = l;
}

// W [H,K,O] -> B1 [(h*O+o), K] fp16
__global__ void convB_k(const float* __restrict__ W, __half* __restrict__ B1,
                        int K, int O) {
    int idx = blockIdx.x * blockDim.x + threadIdx.x;
    int tot = NHEADS * K * O;
    if (idx >= tot) return;
    int o = idx % O;
    int f = (idx / O) % K;
    int h = idx / (O * K);
    B1[(size_t)(h * O + o) * K + f] = __float2half_rn(W[idx]);
}

// ---------------- init: zero cnt + bn stat buffers -------------------------
__global__ void init_zero_k(int* cnt, float* bsum, float* bsq) {
    int i = blockIdx.x * blockDim.x + threadIdx.x;
    if (i < NN) cnt[i] = 0;
    if (i < 4 * HID) { bsum[i] = 0.f; bsq[i] = 0.f; }
}

__global__ void count_k(const int* __restrict__ dst, int* __restrict__ cnt) {
    int e = blockIdx.x * blockDim.x + threadIdx.x;
    if (e < NE) atomicAdd(&cnt[clampi(dst[e], 0, NN - 1)], 1);
}

__global__ void scan_k(const int* __restrict__ cnt, int* __restrict__ rowptr,
                       int* __restrict__ fill) {
    __shared__ int sh[1024];
    int tid = threadIdx.x;
    int carry = 0;
    if (tid == 0) rowptr[0] = 0;
    for (int base = 0; base < NN; base += 1024) {
        int i = base + tid;
        int v = (i < NN) ? cnt[i] : 0;
        sh[tid] = v;
        __syncthreads();
        for (int off = 1; off < 1024; off <<= 1) {
            int t = (tid >= off) ? sh[tid - off] : 0;
            __syncthreads();
            sh[tid] += t;
            __syncthreads();
        }
        int incl = sh[tid];
        if (i < NN) {
            rowptr[i + 1] = carry + incl;
            fill[i] = carry + incl - v;
        }
        carry += sh[1023];
        __syncthreads();
    }
}

__global__ void scatter_k(const int* __restrict__ dst, int* __restrict__ fill,
                          int* __restrict__ eids) {
    int e = blockIdx.x * blockDim.x + threadIdx.x;
    if (e < NE) {
        int d = clampi(dst[e], 0, NN - 1);
        int pos = atomicAdd(&fill[d], 1);
        if (pos >= 0 && pos < NE) eids[pos] = e;
    }
}

// ---------------- weight reorder (final layer) -----------------------------
__global__ void reorder_k(const float* __restrict__ W, float* __restrict__ out,
                          int K, int O) {
    int idx = blockIdx.x * blockDim.x + threadIdx.x;
    int tot = NHEADS * K * O;
    if (idx >= tot) return;
    int o = idx % O;
    int f = (idx / O) % K;
    int h = idx / (O * K);
    out[f * (NHEADS * O) + h * O + o] = W[idx];
}

// ---------------- SIMT SGEMM (final small layer) ---------------------------
#define BM 128
#define BN 128
#define BK 8
__global__ __launch_bounds__(256)
void sgemm_k(const float* __restrict__ A, const float* __restrict__ B,
             float* __restrict__ C, int M, int N, int K) {
    __shared__ float As[BK][BM];
    __shared__ float Bs[BK][BN];
    int tid = threadIdx.x;
    int row0 = blockIdx.y * BM;
    int col0 = blockIdx.x * BN;

    int aRow = tid >> 1;
    int aCol = (tid & 1) * 4;
    int bRow = tid >> 5;
    int bCol = (tid & 31) * 4;
    int ty = tid >> 4;
    int tx = tid & 15;

    float acc[8][8];
#pragma unroll
    for (int i = 0; i < 8; i++)
#pragma unroll
        for (int j = 0; j < 8; j++) acc[i][j] = 0.f;

    for (int k0 = 0; k0 < K; k0 += BK) {
        float4 av = make_float4(0.f, 0.f, 0.f, 0.f);
        int gr = row0 + aRow;
        if (gr < M) av = *(const float4*)(A + (size_t)gr * K + k0 + aCol);
        As[aCol + 0][aRow] = av.x;
        As[aCol + 1][aRow] = av.y;
        As[aCol + 2][aRow] = av.z;
        As[aCol + 3][aRow] = av.w;

        float4 bv = make_float4(0.f, 0.f, 0.f, 0.f);
        int gc = col0 + bCol;
        if (gc + 3 < N) bv = *(const float4*)(B + (size_t)(k0 + bRow) * N + gc);
        Bs[bRow][bCol + 0] = bv.x;
        Bs[bRow][bCol + 1] = bv.y;
        Bs[bRow][bCol + 2] = bv.z;
        Bs[bRow][bCol + 3] = bv.w;
        __syncthreads();

#pragma unroll
        for (int k = 0; k < BK; k++) {
            float ra[8], rb[8];
#pragma unroll
            for (int i = 0; i < 8; i++) ra[i] = As[k][ty * 8 + i];
#pragma unroll
            for (int j = 0; j < 8; j++) rb[j] = Bs[k][tx * 8 + j];
#pragma unroll
            for (int i = 0; i < 8; i++)
#pragma unroll
                for (int j = 0; j < 8; j++) acc[i][j] += ra[i] * rb[j];
        }
        __syncthreads();
    }

#pragma unroll
    for (int i = 0; i < 8; i++) {
        int r = row0 + ty * 8 + i;
        if (r >= M) continue;
#pragma unroll
        for (int j = 0; j < 8; j++) {
            int c = col0 + tx * 8 + j;
            if (c < N) C[(size_t)r * N + c] = acc[i][j];
        }
    }
}

// ---------------- es/ed (final layer only) ---------------------------------
template <int O>
__global__ void esed_k(const float* __restrict__ h, const float* __restrict__ a_s,
                       const float* __restrict__ a_d, float* __restrict__ es,
                       float* __restrict__ ed) {
    int w = (blockIdx.x * blockDim.x + threadIdx.x) >> 5;
    int lane = threadIdx.x & 31;
    if (w >= NN * NHEADS) return;
    int hd = w % NHEADS;
    const float* hp = h + (size_t)w * O;
    float s = 0.f, d = 0.f;
    for (int k = lane; k < O; k += 32) {
        float v = hp[k];
        s += v * a_s[hd * O + k];
        d += v * a_d[hd * O + k];
    }
#pragma unroll
    for (int off = 16; off; off >>= 1) {
        s += __shfl_xor_sync(0xffffffffu, s, off);
        d += __shfl_xor_sync(0xffffffffu, d, off);
    }
    if (lane == 0) { es[w] = s; ed[w] = d; }
}

__device__ __forceinline__ float lrelu02(float v) { return v > 0.f ? v : 0.2f * v; }

// ---------------- fused attention (eetab smem, 2-edge-unrolled gather) -----
__global__ void attn_k(const __half* __restrict__ H, const float* __restrict__ es,
                       const float* __restrict__ ed, const float* __restrict__ rel,
                       const float* __restrict__ ae, const int* __restrict__ src,
                       const int* __restrict__ etype, const int* __restrict__ edist,
                       const int* __restrict__ rowptr, const int* __restrict__ eids,
                       float4* __restrict__ alpha, const float* __restrict__ b,
                       const float* __restrict__ resid, float* __restrict__ out) {
    __shared__ __align__(16) float eetab[NREL * NHEADS];
    int tid = threadIdx.x;
    if (tid < NREL * NHEADS) {
        int r = tid >> 2, hd = tid & 3;
        eetab[tid] = rel[r * 2] * ae[hd * 2] + rel[r * 2 + 1] * ae[hd * 2 + 1];
    }
    __syncthreads();

    int n = (blockIdx.x * blockDim.x + tid) >> 5;
    int lane = tid & 31;
    if (n >= NN) return;
    int beg = rowptr[n], end = rowptr[n + 1];
    float4 edn = *(const float4*)(ed + n * 4);

    // pass 1: logits + max
    float4 m = make_float4(-3.4e38f, -3.4e38f, -3.4e38f, -3.4e38f);
    for (int i = beg + lane; i < end; i += 32) {
        int e = eids[i];
        int s = clampi(src[e], 0, NN - 1);
        int t = clampi(etype[e], 0, NREL - 1);
        float4 a = *(const float4*)(es + s * 4);
        float4 c = *(const float4*)(eetab + t * 4);
        float4 lg;
        lg.x = lrelu02(a.x + edn.x + c.x);
        lg.y = lrelu02(a.y + edn.y + c.y);
        lg.z = lrelu02(a.z + edn.z + c.z);
        lg.w = lrelu02(a.w + edn.w + c.w);
        alpha[i] = lg;
        m.x = fmaxf(m.x, lg.x); m.y = fmaxf(m.y, lg.y);
        m.z = fmaxf(m.z, lg.z); m.w = fmaxf(m.w, lg.w);
    }
#pragma unroll
    for (int off = 16; off; off >>= 1) {
        m.x = fmaxf(m.x, __shfl_xor_sync(0xffffffffu, m.x, off));
        m.y = fmaxf(m.y, __shfl_xor_sync(0xffffffffu, m.y, off));
        m.z = fmaxf(m.z, __shfl_xor_sync(0xffffffffu, m.z, off));
        m.w = fmaxf(m.w, __shfl_xor_sync(0xffffffffu, m.w, off));
    }
    // pass 2: exp + den
    float4 den = make_float4(0.f, 0.f, 0.f, 0.f);
    for (int i = beg + lane; i < end; i += 32) {
        float4 v = alpha[i];
        float4 ex;
        ex.x = __expf(v.x - m.x); ex.y = __expf(v.y - m.y);
        ex.z = __expf(v.z - m.z); ex.w = __expf(v.w - m.w);
        alpha[i] = ex;
        den.x += ex.x; den.y += ex.y; den.z += ex.z; den.w += ex.w;
    }
#pragma unroll
    for (int off = 16; off; off >>= 1) {
        den.x += __shfl_xor_sync(0xffffffffu, den.x, off);
        den.y += __shfl_xor_sync(0xffffffffu, den.y, off);
        den.z += __shfl_xor_sync(0xffffffffu, den.z, off);
        den.w += __shfl_xor_sync(0xffffffffu, den.w, off);
    }
    float4 inv;
    inv.x = 1.0f / (den.x + 1e-16f); inv.y = 1.0f / (den.y + 1e-16f);
    inv.z = 1.0f / (den.z + 1e-16f); inv.w = 1.0f / (den.w + 1e-16f);
    __syncwarp();

    // pass 3: gather, 2-edge unrolled (independent loads -> 2x MLP)
    float2 accA[NHEADS], accB[NHEADS];
#pragma unroll
    for (int q = 0; q < NHEADS; q++) {
        accA[q] = make_float2(0.f, 0.f);
        accB[q] = make_float2(0.f, 0.f);
    }
    int i = beg;
    for (; i + 1 < end; i += 2) {
        int e0 = eids[i], e1 = eids[i + 1];
        int s0 = clampi(src[e0], 0, NN - 1);
        int s1 = clampi(src[e1], 0, NN - 1);
        float4 a0 = alpha[i], a1 = alpha[i + 1];
        float w0 = 1.0f / (1.0f + (float)edist[e0]);
        float w1 = 1.0f / (1.0f + (float)edist[e1]);
        const __half2* p0 = (const __half2*)(H + (size_t)s0 * 512);
        const __half2* p1 = (const __half2*)(H + (size_t)s1 * 512);
        __half2 h0[8], h1[8];
#pragma unroll
        for (int q = 0; q < NHEADS; q++) {
            h0[q * 2] = p0[q * 64 + lane];
            h0[q * 2 + 1] = p0[q * 64 + 32 + lane];
            h1[q * 2] = p1[q * 64 + lane];
            h1[q * 2 + 1] = p1[q * 64 + 32 + lane];
        }
        float aw0[4] = {a0.x * inv.x * w0, a0.y * inv.y * w0, a0.z * inv.z * w0,
                        a0.w * inv.w * w0};
        float aw1[4] = {a1.x * inv.x * w1, a1.y * inv.y * w1, a1.z * inv.z * w1,
                        a1.w * inv.w * w1};
#pragma unroll
        for (int q = 0; q < NHEADS; q++) {
            float2 fa0 = __half22float2(h0[q * 2]);
            float2 fb0 = __half22float2(h0[q * 2 + 1]);
            float2 fa1 = __half22float2(h1[q * 2]);
            float2 fb1 = __half22float2(h1[q * 2 + 1]);
            accA[q].x += aw0[q] * fa0.x + aw1[q] * fa1.x;
            accA[q].y += aw0[q] * fa0.y + aw1[q] * fa1.y;
            accB[q].x += aw0[q] * fb0.x + aw1[q] * fb1.x;
            accB[q].y += aw0[q] * fb0.y + aw1[q] * fb1.y;
        }
    }
    if (i < end) {
        int e = eids[i];
        int s = clampi(src[e], 0, NN - 1);
        float4 a = alpha[i];
        float w = 1.0f / (1.0f + (float)edist[e]);
        float aw[4] = {a.x * inv.x * w, a.y * inv.y * w, a.z * inv.z * w,
                       a.w * inv.w * w};
        const __half2* hs2 = (const __half2*)(H + (size_t)s * 512);
#pragma unroll
        for (int q = 0; q < NHEADS; q++) {
            float2 fa = __half22float2(hs2[q * 64 + lane]);
            float2 fb = __half22float2(hs2[q * 64 + 32 + lane]);
            accA[q].x += aw[q] * fa.x; accA[q].y += aw[q] * fa.y;
            accB[q].x += aw[q] * fb.x; accB[q].y += aw[q] * fb.y;
        }
    }
    {
        int oA = 2 * lane, oB = 64 + 2 * lane;
        float2 bA = *(const float2*)(b + oA);
        float2 bB = *(const float2*)(b + oB);
        float2 vA, vB;
        vA.x = 0.25f * (accA[0].x + accA[1].x + accA[2].x + accA[3].x) + bA.x;
        vA.y = 0.25f * (accA[0].y + accA[1].y + accA[2].y + accA[3].y) + bA.y;
        vB.x = 0.25f * (accB[0].x + accB[1].x + accB[2].x + accB[3].x) + bB.x;
        vB.y = 0.25f * (accB[0].y + accB[1].y + accB[2].y + accB[3].y) + bB.y;
        if (resid) {
            float2 rA = *(const float2*)(resid + (size_t)n * 128 + oA);
            float2 rB = *(const float2*)(resid + (size_t)n * 128 + oB);
            vA.x += rA.x; vA.y += rA.y; vB.x += rB.x; vB.y += rB.y;
        }
        *(float2*)(out + (size_t)n * 128 + oA) = vA;
        *(float2*)(out + (size_t)n * 128 + oB) = vB;
    }
}

// ---------------- final layer: fused logit+softmax+gather (O=9) ------------
__global__ void attnF_k(const float* __restrict__ h, const float* __restrict__ es,
                        const float* __restrict__ ed, const float* __restrict__ rel,
                        const float* __restrict__ ae, const int* __restrict__ src,
                        const int* __restrict__ etype, const int* __restrict__ edist,
                        const int* __restrict__ rowptr, const int* __restrict__ eids,
                        float4* __restrict__ alpha, const float* __restrict__ b,
                        float* __restrict__ out) {
    __shared__ __align__(16) float eetab[NREL * NHEADS];
    int tid = threadIdx.x;
    if (tid < NREL * NHEADS) {
        int r = tid >> 2, hd = tid & 3;
        eetab[tid] = rel[r * 2] * ae[hd * 2] + rel[r * 2 + 1] * ae[hd * 2 + 1];
    }
    __syncthreads();

    int n = (blockIdx.x * blockDim.x + tid) >> 5;
    int lane = tid & 31;
    if (n >= NN) return;
    int beg = rowptr[n], end = rowptr[n + 1];
    float4 edn = *(const float4*)(ed + n * 4);

    float4 m = make_float4(-3.4e38f, -3.4e38f, -3.4e38f, -3.4e38f);
    for (int i = beg + lane; i < end; i += 32) {
        int e = eids[i];
        int s = clampi(src[e], 0, NN - 1);
        int t = clampi(etype[e], 0, NREL - 1);
        float4 a = *(const float4*)(es + s * 4);
        float4 c = *(const float4*)(eetab + t * 4);
        float4 lg;
        lg.x = lrelu02(a.x + edn.x + c.x);
        lg.y = lrelu02(a.y + edn.y + c.y);
        lg.z = lrelu02(a.z + edn.z + c.z);
        lg.w = lrelu02(a.w + edn.w + c.w);
        alpha[i] = lg;
        m.x = fmaxf(m.x, lg.x); m.y = fmaxf(m.y, lg.y);
        m.z = fmaxf(m.z, lg.z); m.w = fmaxf(m.w, lg.w);
    }
#pragma unroll
    for (int off = 16; off; off >>= 1) {
        m.x = fmaxf(m.x, __shfl_xor_sync(0xffffffffu, m.x, off));
        m.y = fmaxf(m.y, __shfl_xor_sync(0xffffffffu, m.y, off));
        m.z = fmaxf(m.z, __shfl_xor_sync(0xffffffffu, m.z, off));
        m.w = fmaxf(m.w, __shfl_xor_sync(0xffffffffu, m.w, off));
    }
    float4 den = make_float4(0.f, 0.f, 0.f, 0.f);
    for (int i = beg + lane; i < end; i += 32) {
        float4 v = alpha[i];
        float4 ex;
        ex.x = __expf(v.x - m.x); ex.y = __expf(v.y - m.y);
        ex.z = __expf(v.z - m.z); ex.w = __expf(v.w - m.w);
        alpha[i] = ex;
        den.x += ex.x; den.y += ex.y; den.z += ex.z; den.w += ex.w;
    }
#pragma unroll
    for (int off = 16; off; off >>= 1) {
        den.x += __shfl_xor_sync(0xffffffffu, den.x, off);
        den.y += __shfl_xor_sync(0xffffffffu, den.y, off);
        den.z += __shfl_xor_sync(0xffffffffu, den.z, off);
        den.w += __shfl_xor_sync(0xffffffffu, den.w, off);
    }
    float4 inv;
    inv.x = 1.0f / (den.x + 1e-16f); inv.y = 1.0f / (den.y + 1e-16f);
    inv.z = 1.0f / (den.z + 1e-16f); inv.w = 1.0f / (den.w + 1e-16f);
    __syncwarp();

    float acc[NHEADS] = {0.f, 0.f, 0.f, 0.f};
    for (int i = beg; i < end; i++) {
        int e = eids[i];
        int s = clampi(src[e], 0, NN - 1);
        float4 a = alpha[i];
        float w = 1.0f / (1.0f + (float)edist[e]);
        float aw[4] = {a.x * inv.x * w, a.y * inv.y * w, a.z * inv.z * w,
                       a.w * inv.w * w};
        if (lane < NCLS) {
            const float* hs = h + (size_t)s * (NHEADS * NCLS);
#pragma unroll
            for (int q = 0; q < NHEADS; q++) acc[q] += aw[q] * hs[q * NCLS + lane];
        }
    }
    if (lane < NCLS) {
        float v = 0.25f * (acc[0] + acc[1] + acc[2] + acc[3]) + b[lane];
        out[(size_t)n * NCLS + lane] = v > 0.f ? v : 0.1f * v;
    }
}

// ---------------- batch norm -----------------------------------------------
__global__ void bn_stats_k(const float* __restrict__ x, float* __restrict__ sum,
                           float* __restrict__ sumsq) {
    int t = threadIdx.x;
    int rows_per = (NN + gridDim.x - 1) / gridDim.x;
    int r0 = blockIdx.x * rows_per;
    int r1 = min(r0 + rows_per, NN);
    float s = 0.f, q = 0.f;
    for (int r = r0; r < r1; r++) {
        float v = x[(size_t)r * HID + t];
        s += v;
        q += v * v;
    }
    atomicAdd(&sum[t], s);
    atomicAdd(&sumsq[t], q);
}

__global__ void bn_apply_k(const float* __restrict__ x, const float* __restrict__ sum,
                           const float* __restrict__ sumsq, const float* __restrict__ g,
                           const float* __restrict__ b, float* __restrict__ out,
                           __half* __restrict__ A2) {
    int i = blockIdx.x * blockDim.x + threadIdx.x;
    if (i >= NN * HID) return;
    int o = i & 127;
    int n = i >> 7;
    float mu = sum[o] * (1.0f / NN);
    float var = sumsq[o] * (1.0f / NN) - mu * mu;
    float v = (x[i] - mu) * rsqrtf(var + 1e-5f) * g[o] + b[o];
    v = v > 0.f ? v : 0.1f * v;
    out[i] = v;
    if (A2) {
        __half h = __float2half_rn(v);
        __half l = __float2half_rn(v - __half2float(h));
        size_t base = (size_t)n * 256;
        A2[base + o] = h;
        A2[base + 128 + o] = l;
    }
}

// ---------------- host orchestration ---------------------------------------
struct Bufs {
    float *h_buf, *tmp, *xb, *hin, *es, *ed, *Wb, *bsum, *bsq;
    __half *Hh, *A2, *B1;
    int *cnt, *rowptr, *fill, *eids;
};

extern "C" void kernel_launch(void* const* d_in, const int* in_sizes, int n_in,
                              void* d_out, int out_size) {
    const float* x = (const float*)d_in[0];
    const int* ei = (const int*)d_in[1];
    const int* etype = (const int*)d_in[2];
    const int* edist = (const int*)d_in[3];
    const float* W0 = (const float*)d_in[4];
    const float* asrc0 = (const float*)d_in[5];
    const float* adst0 = (const float*)d_in[6];
    const float* aedge0 = (const float*)d_in[7];
    const float* b0 = (const float*)d_in[8];
    const float* rel0 = (const float*)d_in[9];
    const float* Wm = (const float*)d_in[10];
    const float* asrcm = (const float*)d_in[11];
    const float* adstm = (const float*)d_in[12];
    const float* aedgem = (const float*)d_in[13];
    const float* bm = (const float*)d_in[14];
    const float* relm = (const float*)d_in[15];
    const float* WL = (const float*)d_in[16];
    const float* asrcL = (const float*)d_in[17];
    const float* adstL = (const float*)d_in[18];
    const float* aedgeL = (const float*)d_in[19];
    const float* bL = (const float*)d_in[20];
    const float* relL = (const float*)d_in[21];
    const float* bn_g = (const float*)d_in[22];
    const float* bn_b = (const float*)d_in[23];

    static bool attr_set = false;
    if (!attr_set) {
        cudaFuncSetAttribute(mma_gemm_k, cudaFuncAttributeMaxDynamicSharedMemorySize,
                             NSTAGE * STAGEB);
        attr_set = true;
    }

    Bufs B;
    cudaGetSymbolAddress((void**)&B.h_buf, g_h);
    cudaGetSymbolAddress((void**)&B.Hh, g_Hh);
    cudaGetSymbolAddress((void**)&B.tmp, g_tmp);
    cudaGetSymbolAddress((void**)&B.xb, g_x);
    cudaGetSymbolAddress((void**)&B.hin, g_hin);
    cudaGetSymbolAddress((void**)&B.es, g_es);
    cudaGetSymbolAddress((void**)&B.ed, g_ed);
    cudaGetSymbolAddress((void**)&B.Wb, g_W);
    cudaGetSymbolAddress((void**)&B.bsum, g_bsum);
    cudaGetSymbolAddress((void**)&B.bsq, g_bsq);
    cudaGetSymbolAddress((void**)&B.A2, g_A2);
    cudaGetSymbolAddress((void**)&B.B1, g_B1);
    cudaGetSymbolAddress((void**)&B.cnt, g_cnt);
    cudaGetSymbolAddress((void**)&B.rowptr, g_rowptr);
    cudaGetSymbolAddress((void**)&B.fill, g_fill);
    cudaGetSymbolAddress((void**)&B.eids, g_eids);

    const int* src = ei;
    const int* dst = ei + NE;
    float4* lg4 = (float4*)B.tmp;
    dim3 ggrid(4, (NN + 127) / 128);
    int attn_blocks = (NN * 32 + 255) / 256;

    // layer-0: convA(1), convB(2), init(3), mma(4 = profiled slot)
    int na = NN * FIN;
    convA_k<<<(na + 255) / 256, 256>>>(x, B.A2, NN, FIN);
    int nb = NHEADS * FIN * HID;
    convB_k<<<(nb + 255) / 256, 256>>>(W0, B.B1, FIN, HID);
    init_zero_k<<<(NN + 255) / 256, 256>>>(B.cnt, B.bsum, B.bsq);
    mma_gemm_k<<<ggrid, 256, NSTAGE * STAGEB>>>(B.A2, B.B1, asrc0, adst0, B.Hh,
                                                B.es, B.ed, NN, FIN);
    count_k<<<(NE + 255) / 256, 256>>>(dst, B.cnt);
    scan_k<<<1, 1024>>>(B.cnt, B.rowptr, B.fill);
    scatter_k<<<(NE + 255) / 256, 256>>>(dst, B.fill, B.eids);
    attn_k<<<attn_blocks, 256>>>(B.Hh, B.es, B.ed, rel0, aedge0, src, etype,
                                 edist, B.rowptr, B.eids, lg4, b0, nullptr, B.xb);

    int nb128 = (NN * HID + 255) / 256;

    for (int i = 0; i < 3; i++) {
        bn_stats_k<<<200, 128>>>(B.xb, B.bsum + i * HID, B.bsq + i * HID);
        bn_apply_k<<<nb128, 256>>>(B.xb, B.bsum + i * HID, B.bsq + i * HID,
                                   bn_g + i * HID, bn_b + i * HID, B.hin, B.A2);
        int nbm = NHEADS * HID * HID;
        convB_k<<<(nbm + 255) / 256, 256>>>(Wm + (size_t)i * NHEADS * HID * HID,
                                            B.B1, HID, HID);
        mma_gemm_k<<<ggrid, 256, NSTAGE * STAGEB>>>(
            B.A2, B.B1, asrcm + i * NHEADS * HID, adstm + i * NHEADS * HID,
            B.Hh, B.es, B.ed, NN, HID);
        attn_k<<<attn_blocks, 256>>>(B.Hh, B.es, B.ed, relm + i * NREL * 2,
                                     aedgem + i * NHEADS * 2, src, etype, edist,
                                     B.rowptr, B.eids, lg4, bm + i * HID, B.hin,
                                     B.xb);
    }

    // final layer
    bn_stats_k<<<200, 128>>>(B.xb, B.bsum + 3 * HID, B.bsq + 3 * HID);
    bn_apply_k<<<nb128, 256>>>(B.xb, B.bsum + 3 * HID, B.bsq + 3 * HID,
                               bn_g + 3 * HID, bn_b + 3 * HID, B.hin,
                               (__half*)nullptr);
    {
        int tot = NHEADS * HID * NCLS;
        reorder_k<<<(tot + 255) / 256, 256>>>(WL, B.Wb, HID, NCLS);
        int Ncols = NHEADS * NCLS;
        dim3 grid((Ncols + BN - 1) / BN, (NN + BM - 1) / BM);
        sgemm_k<<<grid, 256>>>(B.hin, B.Wb, B.h_buf, NN, Ncols, HID);
        int warps = NN * NHEADS;
        int blocks = (warps * 32 + 255) / 256;
        esed_k<NCLS><<<blocks, 256>>>(B.h_buf, asrcL, adstL, B.es, B.ed);
        attnF_k<<<attn_blocks, 256>>>(B.h_buf, B.es, B.ed, relL, aedgeL, src,
                                      etype, edist, B.rowptr, B.eids, lg4, bL,
                                      (float*)d_out);
    }
}

// round 13
// speedup vs baseline: 1.0379x; 1.0237x over previous
#include <cuda_runtime.h>
#include <cuda_fp16.h>
#include <math.h>
#include <stdint.h>

#define NN 20000
#define NE 320000
#define NHEADS 4
#define NREL 40
#define FIN 768
#define HID 128
#define NCLS 9

// ---------------- scratch ---------------------------------------------------
__device__ __align__(16) float g_h[NN * NHEADS * HID];          // final-layer SIMT out
__device__ __align__(16) __half g_Hh[NN * NHEADS * HID];        // GEMM out fp16 [N,512]
__device__ __align__(16) float g_tmp[NN * NHEADS * HID];
__device__ __align__(16) float g_x[NN * HID];
__device__ __align__(16) float g_hin[NN * HID];
__device__ __align__(16) float g_es[NN * NHEADS];
__device__ __align__(16) float g_ed[NN * NHEADS];
__device__ __align__(16) float g_W[FIN * NHEADS * HID];
__device__ __align__(16) __half g_A2[NN * 2 * FIN];             // [M,2K] hi|lo fp16
__device__ __align__(16) __half g_B1[(NHEADS * HID) * FIN];     // [512,K] fp16
__device__ int g_cnt[NN];
__device__ int g_rowptr[NN + 1];
__device__ int g_fill[NN];
__device__ int g_eids[NE];
__device__ float g_bsum[4 * HID];
__device__ float g_bsq[4 * HID];

__device__ __forceinline__ int clampi(int v, int lo, int hi) {
    return v < lo ? lo : (v > hi ? hi : v);
}

__device__ __forceinline__ uint32_t smem_u32(const void* p) {
    uint32_t a;
    asm("{ .reg .u64 t; cvta.to.shared.u64 t, %1; cvt.u32.u64 %0, t; }"
        : "=r"(a) : "l"(p));
    return a;
}

__device__ __forceinline__ void ldsm_x4(uint32_t* r, uint32_t addr) {
    asm volatile("ldmatrix.sync.aligned.m8n8.x4.shared.b16 {%0,%1,%2,%3}, [%4];"
                 : "=r"(r[0]), "=r"(r[1]), "=r"(r[2]), "=r"(r[3]) : "r"(addr));
}

__device__ __forceinline__ void mma16816(float* d, const uint32_t* a, uint32_t b0,
                                         uint32_t b1) {
    asm volatile(
        "mma.sync.aligned.m16n8k16.row.col.f32.f16.f16.f32 "
        "{%0,%1,%2,%3}, {%4,%5,%6,%7}, {%8,%9}, {%0,%1,%2,%3};"
        : "+f"(d[0]), "+f"(d[1]), "+f"(d[2]), "+f"(d[3])
        : "r"(a[0]), "r"(a[1]), "r"(a[2]), "r"(a[3]), "r"(b0), "r"(b1));
}

__device__ __forceinline__ void cp16(uint32_t saddr, const void* g, bool pred) {
    int sz = pred ? 16 : 0;
    asm volatile("cp.async.cg.shared.global [%0], [%1], 16, %2;"
                 :: "r"(saddr), "l"(g), "r"(sz));
}
#define CP_COMMIT() asm volatile("cp.async.commit_group;" ::: "memory")
#define CP_WAIT2() asm volatile("cp.async.wait_group 2;" ::: "memory")
#define CP_WAIT1() asm volatile("cp.async.wait_group 1;" ::: "memory")
#define CP_WAIT0() asm volatile("cp.async.wait_group 0;" ::: "memory")

// ---------------- fp16 2-term GEMM, K-chunk 32, 3-stage, fp16 H, es/ed -----
#define SMS 40
#define TILEB 10240
#define STAGEB (3 * TILEB)
#define NSTAGE 3
__global__ void __launch_bounds__(256, 2)
mma_gemm_k(const __half* __restrict__ A2, const __half* __restrict__ B1,
           const float* __restrict__ a_s, const float* __restrict__ a_d,
           __half* __restrict__ H, float* __restrict__ es, float* __restrict__ ed,
           int M, int K) {
    extern __shared__ char sm[];
    uint32_t s0 = smem_u32(sm);
    int tid = threadIdx.x;
    int wid = tid >> 5;
    int lane = tid & 31;
    int warp_m = wid & 3;
    int warp_n = wid >> 2;
    int row0 = blockIdx.y * 128;
    int col0 = blockIdx.x * 128;

    float acc[2][8][4];
#pragma unroll
    for (int i = 0; i < 2; i++)
#pragma unroll
        for (int j = 0; j < 8; j++)
#pragma unroll
            for (int q = 0; q < 4; q++) acc[i][j][q] = 0.f;

    int ksz = K / 32;
    int lr = tid >> 1;
    int lq = (tid & 1) * 16;
    int gr = row0 + lr;
    bool aval = gr < M;
    const __half* Abase = A2 + (size_t)(aval ? gr : 0) * (2 * K);
    const __half* Bbase = B1 + (size_t)(col0 + lr) * K;
    uint32_t sA = (uint32_t)((lr * SMS + lq) * 2);

#define ISSUE_STAGE(c) do {                                              \
        int _kb = (c) * 32;                                              \
        uint32_t _b = s0 + ((c) % NSTAGE) * STAGEB;                      \
        const __half* _g;                                                \
        _g = Abase + _kb + lq;                                           \
        cp16(_b + 0 * TILEB + sA, _g, aval);                             \
        cp16(_b + 0 * TILEB + sA + 16, _g + 8, aval);                    \
        _g = Abase + K + _kb + lq;                                       \
        cp16(_b + 1 * TILEB + sA, _g, aval);                             \
        cp16(_b + 1 * TILEB + sA + 16, _g + 8, aval);                    \
        _g = Bbase + _kb + lq;                                           \
        cp16(_b + 2 * TILEB + sA, _g, true);                             \
        cp16(_b + 2 * TILEB + sA + 16, _g + 8, true);                    \
        CP_COMMIT();                                                     \
    } while (0)

    ISSUE_STAGE(0);
    if (ksz > 1) ISSUE_STAGE(1);
    for (int c = 0; c < ksz; c++) {
        if (c + 2 < ksz) {
            ISSUE_STAGE(c + 2);
            CP_WAIT2();
        } else if (c + 1 < ksz) {
            CP_WAIT1();
        } else {
            CP_WAIT0();
        }
        __syncthreads();
        uint32_t base = s0 + (c % NSTAGE) * STAGEB;
#pragma unroll
        for (int k16 = 0; k16 < 32; k16 += 16) {
            uint32_t koff = (uint32_t)((k16 + ((lane >> 4) << 3)) * 2);
            uint32_t ah[2][4], al[2][4];
#pragma unroll
            for (int mf = 0; mf < 2; mf++) {
                int m = warp_m * 32 + mf * 16 + (lane & 15);
                uint32_t ro = (uint32_t)(m * SMS * 2) + koff;
                ldsm_x4(ah[mf], base + 0 * TILEB + ro);
                ldsm_x4(al[mf], base + 1 * TILEB + ro);
            }
#pragma unroll
            for (int jp = 0; jp < 4; jp++) {
                int n = warp_n * 64 + jp * 16 + (lane & 15);
                uint32_t ro = (uint32_t)(n * SMS * 2) + koff;
                uint32_t bf[4];
                ldsm_x4(bf, base + 2 * TILEB + ro);
#pragma unroll
                for (int mf = 0; mf < 2; mf++) {
                    mma16816(acc[mf][jp * 2 + 0], ah[mf], bf[0], bf[2]);
                    mma16816(acc[mf][jp * 2 + 1], ah[mf], bf[1], bf[3]);
                    mma16816(acc[mf][jp * 2 + 0], al[mf], bf[0], bf[2]);
                    mma16816(acc[mf][jp * 2 + 1], al[mf], bf[1], bf[3]);
                }
            }
        }
        __syncthreads();
    }
#undef ISSUE_STAGE

    int g = lane >> 2, t = lane & 3;
#pragma unroll
    for (int mf = 0; mf < 2; mf++) {
#pragma unroll
        for (int nf = 0; nf < 8; nf++) {
            int col = col0 + warp_n * 64 + nf * 8 + t * 2;
            int r0 = row0 + warp_m * 32 + mf * 16 + g;
            if (r0 < M)
                *(__half2*)(H + (size_t)r0 * 512 + col) =
                    __floats2half2_rn(acc[mf][nf][0], acc[mf][nf][1]);
            int r1 = r0 + 8;
            if (r1 < M)
                *(__half2*)(H + (size_t)r1 * 512 + col) =
                    __floats2half2_rn(acc[mf][nf][2], acc[mf][nf][3]);
        }
    }

    // fused es/ed: head = blockIdx.x
    {
        const float* asg = a_s + blockIdx.x * 128;
        const float* adg = a_d + blockIdx.x * 128;
        float ps[2][2] = {{0.f, 0.f}, {0.f, 0.f}};
        float pd[2][2] = {{0.f, 0.f}, {0.f, 0.f}};
#pragma unroll
        for (int nf = 0; nf < 8; nf++) {
#pragma unroll
            for (int j = 0; j < 2; j++) {
                int cw = warp_n * 64 + nf * 8 + t * 2 + j;
                float av = __ldg(asg + cw);
                float dv = __ldg(adg + cw);
#pragma unroll
                for (int mf = 0; mf < 2; mf++) {
                    ps[mf][0] += acc[mf][nf][j] * av;
                    ps[mf][1] += acc[mf][nf][2 + j] * av;
                    pd[mf][0] += acc[mf][nf][j] * dv;
                    pd[mf][1] += acc[mf][nf][2 + j] * dv;
                }
            }
        }
#pragma unroll
        for (int mf = 0; mf < 2; mf++)
#pragma unroll
            for (int hf = 0; hf < 2; hf++) {
#pragma unroll
                for (int off = 1; off <= 2; off <<= 1) {
                    ps[mf][hf] += __shfl_xor_sync(0xffffffffu, ps[mf][hf], off);
                    pd[mf][hf] += __shfl_xor_sync(0xffffffffu, pd[mf][hf], off);
                }
            }
        float* se = (float*)sm;
        float* sd = se + 256;
        if (t == 0) {
#pragma unroll
            for (int mf = 0; mf < 2; mf++)
#pragma unroll
                for (int hf = 0; hf < 2; hf++) {
                    int row = warp_m * 32 + mf * 16 + g + hf * 8;
                    se[row * 2 + warp_n] = ps[mf][hf];
                    sd[row * 2 + warp_n] = pd[mf][hf];
                }
        }
        __syncthreads();
        if (tid < 128) {
            int grr = row0 + tid;
            if (grr < M) {
                es[grr * 4 + blockIdx.x] = se[tid * 2] + se[tid * 2 + 1];
                ed[grr * 4 + blockIdx.x] = sd[tid * 2] + sd[tid * 2 + 1];
            }
        }
    }
}

// ---------------- fp32 -> fp16 hi/lo split (layer 0 input) -----------------
__global__ void convA_k(const float* __restrict__ X, __half* __restrict__ A2,
                        int M, int K) {
    int i = blockIdx.x * blockDim.x + threadIdx.x;
    if (i >= M * K) return;
    int r = i / K, k = i - r * K;
    float v = X[i];
    __half h = __float2half_rn(v);
    __half l = __float2half_rn(v - __half2float(h));
    size_t base = (size_t)r * 2 * K;
    A2[base + k] = h;
    A2[base + K + k] = l;
}

// W [H,K,O] -> B1 [(h*O+o), K] fp16
__global__ void convB_k(const float* __restrict__ W, __half* __restrict__ B1,
                        int K, int O) {
    int idx = blockIdx.x * blockDim.x + threadIdx.x;
    int tot = NHEADS * K * O;
    if (idx >= tot) return;
    int o = idx % O;
    int f = (idx / O) % K;
    int h = idx / (O * K);
    B1[(size_t)(h * O + o) * K + f] = __float2half_rn(W[idx]);
}

// ---------------- init: zero cnt + bn stat buffers -------------------------
__global__ void init_zero_k(int* cnt, float* bsum, float* bsq) {
    int i = blockIdx.x * blockDim.x + threadIdx.x;
    if (i < NN) cnt[i] = 0;
    if (i < 4 * HID) { bsum[i] = 0.f; bsq[i] = 0.f; }
}

__global__ void count_k(const int* __restrict__ dst, int* __restrict__ cnt) {
    int e = blockIdx.x * blockDim.x + threadIdx.x;
    if (e < NE) atomicAdd(&cnt[clampi(dst[e], 0, NN - 1)], 1);
}

__global__ void scan_k(const int* __restrict__ cnt, int* __restrict__ rowptr,
                       int* __restrict__ fill) {
    __shared__ int sh[1024];
    int tid = threadIdx.x;
    int carry = 0;
    if (tid == 0) rowptr[0] = 0;
    for (int base = 0; base < NN; base += 1024) {
        int i = base + tid;
        int v = (i < NN) ? cnt[i] : 0;
        sh[tid] = v;
        __syncthreads();
        for (int off = 1; off < 1024; off <<= 1) {
            int t = (tid >= off) ? sh[tid - off] : 0;
            __syncthreads();
            sh[tid] += t;
            __syncthreads();
        }
        int incl = sh[tid];
        if (i < NN) {
            rowptr[i + 1] = carry + incl;
            fill[i] = carry + incl - v;
        }
        carry += sh[1023];
        __syncthreads();
    }
}

__global__ void scatter_k(const int* __restrict__ dst, int* __restrict__ fill,
                          int* __restrict__ eids) {
    int e = blockIdx.x * blockDim.x + threadIdx.x;
    if (e < NE) {
        int d = clampi(dst[e], 0, NN - 1);
        int pos = atomicAdd(&fill[d], 1);
        if (pos >= 0 && pos < NE) eids[pos] = e;
    }
}

// ---------------- weight reorder (final layer) -----------------------------
__global__ void reorder_k(const float* __restrict__ W, float* __restrict__ out,
                          int K, int O) {
    int idx = blockIdx.x * blockDim.x + threadIdx.x;
    int tot = NHEADS * K * O;
    if (idx >= tot) return;
    int o = idx % O;
    int f = (idx / O) % K;
    int h = idx / (O * K);
    out[f * (NHEADS * O) + h * O + o] = W[idx];
}

// ---------------- SIMT SGEMM (final small layer) ---------------------------
#define BM 128
#define BN 128
#define BK 8
__global__ __launch_bounds__(256)
void sgemm_k(const float* __restrict__ A, const float* __restrict__ B,
             float* __restrict__ C, int M, int N, int K) {
    __shared__ float As[BK][BM];
    __shared__ float Bs[BK][BN];
    int tid = threadIdx.x;
    int row0 = blockIdx.y * BM;
    int col0 = blockIdx.x * BN;

    int aRow = tid >> 1;
    int aCol = (tid & 1) * 4;
    int bRow = tid >> 5;
    int bCol = (tid & 31) * 4;
    int ty = tid >> 4;
    int tx = tid & 15;

    float acc[8][8];
#pragma unroll
    for (int i = 0; i < 8; i++)
#pragma unroll
        for (int j = 0; j < 8; j++) acc[i][j] = 0.f;

    for (int k0 = 0; k0 < K; k0 += BK) {
        float4 av = make_float4(0.f, 0.f, 0.f, 0.f);
        int gr = row0 + aRow;
        if (gr < M) av = *(const float4*)(A + (size_t)gr * K + k0 + aCol);
        As[aCol + 0][aRow] = av.x;
        As[aCol + 1][aRow] = av.y;
        As[aCol + 2][aRow] = av.z;
        As[aCol + 3][aRow] = av.w;

        float4 bv = make_float4(0.f, 0.f, 0.f, 0.f);
        int gc = col0 + bCol;
        if (gc + 3 < N) bv = *(const float4*)(B + (size_t)(k0 + bRow) * N + gc);
        Bs[bRow][bCol + 0] = bv.x;
        Bs[bRow][bCol + 1] = bv.y;
        Bs[bRow][bCol + 2] = bv.z;
        Bs[bRow][bCol + 3] = bv.w;
        __syncthreads();

#pragma unroll
        for (int k = 0; k < BK; k++) {
            float ra[8], rb[8];
#pragma unroll
            for (int i = 0; i < 8; i++) ra[i] = As[k][ty * 8 + i];
#pragma unroll
            for (int j = 0; j < 8; j++) rb[j] = Bs[k][tx * 8 + j];
#pragma unroll
            for (int i = 0; i < 8; i++)
#pragma unroll
                for (int j = 0; j < 8; j++) acc[i][j] += ra[i] * rb[j];
        }
        __syncthreads();
    }

#pragma unroll
    for (int i = 0; i < 8; i++) {
        int r = row0 + ty * 8 + i;
        if (r >= M) continue;
#pragma unroll
        for (int j = 0; j < 8; j++) {
            int c = col0 + tx * 8 + j;
            if (c < N) C[(size_t)r * N + c] = acc[i][j];
        }
    }
}

// ---------------- es/ed (final layer only) ---------------------------------
template <int O>
__global__ void esed_k(const float* __restrict__ h, const float* __restrict__ a_s,
                       const float* __restrict__ a_d, float* __restrict__ es,
                       float* __restrict__ ed) {
    int w = (blockIdx.x * blockDim.x + threadIdx.x) >> 5;
    int lane = threadIdx.x & 31;
    if (w >= NN * NHEADS) return;
    int hd = w % NHEADS;
    const float* hp = h + (size_t)w * O;
    float s = 0.f, d = 0.f;
    for (int k = lane; k < O; k += 32) {
        float v = hp[k];
        s += v * a_s[hd * O + k];
        d += v * a_d[hd * O + k];
    }
#pragma unroll
    for (int off = 16; off; off >>= 1) {
        s += __shfl_xor_sync(0xffffffffu, s, off);
        d += __shfl_xor_sync(0xffffffffu, d, off);
    }
    if (lane == 0) { es[w] = s; ed[w] = d; }
}

__device__ __forceinline__ float lrelu02(float v) { return v > 0.f ? v : 0.2f * v; }

// ---------------- fused attention (eetab smem, simple gather) --------------
__global__ void attn_k(const __half* __restrict__ H, const float* __restrict__ es,
                       const float* __restrict__ ed, const float* __restrict__ rel,
                       const float* __restrict__ ae, const int* __restrict__ src,
                       const int* __restrict__ etype, const int* __restrict__ edist,
                       const int* __restrict__ rowptr, const int* __restrict__ eids,
                       float4* __restrict__ alpha, const float* __restrict__ b,
                       const float* __restrict__ resid, float* __restrict__ out) {
    __shared__ __align__(16) float eetab[NREL * NHEADS];
    int tid = threadIdx.x;
    if (tid < NREL * NHEADS) {
        int r = tid >> 2, hd = tid & 3;
        eetab[tid] = rel[r * 2] * ae[hd * 2] + rel[r * 2 + 1] * ae[hd * 2 + 1];
    }
    __syncthreads();

    int n = (blockIdx.x * blockDim.x + tid) >> 5;
    int lane = tid & 31;
    if (n >= NN) return;
    int beg = rowptr[n], end = rowptr[n + 1];
    float4 edn = *(const float4*)(ed + n * 4);

    // pass 1: logits + max
    float4 m = make_float4(-3.4e38f, -3.4e38f, -3.4e38f, -3.4e38f);
    for (int i = beg + lane; i < end; i += 32) {
        int e = eids[i];
        int s = clampi(src[e], 0, NN - 1);
        int t = clampi(etype[e], 0, NREL - 1);
        float4 a = *(const float4*)(es + s * 4);
        float4 c = *(const float4*)(eetab + t * 4);
        float4 lg;
        lg.x = lrelu02(a.x + edn.x + c.x);
        lg.y = lrelu02(a.y + edn.y + c.y);
        lg.z = lrelu02(a.z + edn.z + c.z);
        lg.w = lrelu02(a.w + edn.w + c.w);
        alpha[i] = lg;
        m.x = fmaxf(m.x, lg.x); m.y = fmaxf(m.y, lg.y);
        m.z = fmaxf(m.z, lg.z); m.w = fmaxf(m.w, lg.w);
    }
#pragma unroll
    for (int off = 16; off; off >>= 1) {
        m.x = fmaxf(m.x, __shfl_xor_sync(0xffffffffu, m.x, off));
        m.y = fmaxf(m.y, __shfl_xor_sync(0xffffffffu, m.y, off));
        m.z = fmaxf(m.z, __shfl_xor_sync(0xffffffffu, m.z, off));
        m.w = fmaxf(m.w, __shfl_xor_sync(0xffffffffu, m.w, off));
    }
    // pass 2: exp + den
    float4 den = make_float4(0.f, 0.f, 0.f, 0.f);
    for (int i = beg + lane; i < end; i += 32) {
        float4 v = alpha[i];
        float4 ex;
        ex.x = __expf(v.x - m.x); ex.y = __expf(v.y - m.y);
        ex.z = __expf(v.z - m.z); ex.w = __expf(v.w - m.w);
        alpha[i] = ex;
        den.x += ex.x; den.y += ex.y; den.z += ex.z; den.w += ex.w;
    }
#pragma unroll
    for (int off = 16; off; off >>= 1) {
        den.x += __shfl_xor_sync(0xffffffffu, den.x, off);
        den.y += __shfl_xor_sync(0xffffffffu, den.y, off);
        den.z += __shfl_xor_sync(0xffffffffu, den.z, off);
        den.w += __shfl_xor_sync(0xffffffffu, den.w, off);
    }
    float4 inv;
    inv.x = 1.0f / (den.x + 1e-16f); inv.y = 1.0f / (den.y + 1e-16f);
    inv.z = 1.0f / (den.z + 1e-16f); inv.w = 1.0f / (den.w + 1e-16f);
    __syncwarp();

    // pass 3: gather (half2 coalesced) + head-mean + bias + residual
    float2 accA[NHEADS], accB[NHEADS];
#pragma unroll
    for (int q = 0; q < NHEADS; q++) {
        accA[q] = make_float2(0.f, 0.f);
        accB[q] = make_float2(0.f, 0.f);
    }
    for (int i = beg; i < end; i++) {
        int e = eids[i];
        int s = clampi(src[e], 0, NN - 1);
        float4 a = alpha[i];
        float w = 1.0f / (1.0f + (float)edist[e]);
        float aw[4] = {a.x * inv.x * w, a.y * inv.y * w, a.z * inv.z * w,
                       a.w * inv.w * w};
        const __half2* hs2 = (const __half2*)(H + (size_t)s * 512);
#pragma unroll
        for (int q = 0; q < NHEADS; q++) {
            float2 fa = __half22float2(hs2[q * 64 + lane]);
            float2 fb = __half22float2(hs2[q * 64 + 32 + lane]);
            accA[q].x += aw[q] * fa.x; accA[q].y += aw[q] * fa.y;
            accB[q].x += aw[q] * fb.x; accB[q].y += aw[q] * fb.y;
        }
    }
    {
        int oA = 2 * lane, oB = 64 + 2 * lane;
        float2 bA = *(const float2*)(b + oA);
        float2 bB = *(const float2*)(b + oB);
        float2 vA, vB;
        vA.x = 0.25f * (accA[0].x + accA[1].x + accA[2].x + accA[3].x) + bA.x;
        vA.y = 0.25f * (accA[0].y + accA[1].y + accA[2].y + accA[3].y) + bA.y;
        vB.x = 0.25f * (accB[0].x + accB[1].x + accB[2].x + accB[3].x) + bB.x;
        vB.y = 0.25f * (accB[0].y + accB[1].y + accB[2].y + accB[3].y) + bB.y;
        if (resid) {
            float2 rA = *(const float2*)(resid + (size_t)n * 128 + oA);
            float2 rB = *(const float2*)(resid + (size_t)n * 128 + oB);
            vA.x += rA.x; vA.y += rA.y; vB.x += rB.x; vB.y += rB.y;
        }
        *(float2*)(out + (size_t)n * 128 + oA) = vA;
        *(float2*)(out + (size_t)n * 128 + oB) = vB;
    }
}

// ---------------- final layer: fused logit+softmax+gather (O=9) ------------
__global__ void attnF_k(const float* __restrict__ h, const float* __restrict__ es,
                        const float* __restrict__ ed, const float* __restrict__ rel,
                        const float* __restrict__ ae, const int* __restrict__ src,
                        const int* __restrict__ etype, const int* __restrict__ edist,
                        const int* __restrict__ rowptr, const int* __restrict__ eids,
                        float4* __restrict__ alpha, const float* __restrict__ b,
                        float* __restrict__ out) {
    __shared__ __align__(16) float eetab[NREL * NHEADS];
    int tid = threadIdx.x;
    if (tid < NREL * NHEADS) {
        int r = tid >> 2, hd = tid & 3;
        eetab[tid] = rel[r * 2] * ae[hd * 2] + rel[r * 2 + 1] * ae[hd * 2 + 1];
    }
    __syncthreads();

    int n = (blockIdx.x * blockDim.x + tid) >> 5;
    int lane = tid & 31;
    if (n >= NN) return;
    int beg = rowptr[n], end = rowptr[n + 1];
    float4 edn = *(const float4*)(ed + n * 4);

    float4 m = make_float4(-3.4e38f, -3.4e38f, -3.4e38f, -3.4e38f);
    for (int i = beg + lane; i < end; i += 32) {
        int e = eids[i];
        int s = clampi(src[e], 0, NN - 1);
        int t = clampi(etype[e], 0, NREL - 1);
        float4 a = *(const float4*)(es + s * 4);
        float4 c = *(const float4*)(eetab + t * 4);
        float4 lg;
        lg.x = lrelu02(a.x + edn.x + c.x);
        lg.y = lrelu02(a.y + edn.y + c.y);
        lg.z = lrelu02(a.z + edn.z + c.z);
        lg.w = lrelu02(a.w + edn.w + c.w);
        alpha[i] = lg;
        m.x = fmaxf(m.x, lg.x); m.y = fmaxf(m.y, lg.y);
        m.z = fmaxf(m.z, lg.z); m.w = fmaxf(m.w, lg.w);
    }
#pragma unroll
    for (int off = 16; off; off >>= 1) {
        m.x = fmaxf(m.x, __shfl_xor_sync(0xffffffffu, m.x, off));
        m.y = fmaxf(m.y, __shfl_xor_sync(0xffffffffu, m.y, off));
        m.z = fmaxf(m.z, __shfl_xor_sync(0xffffffffu, m.z, off));
        m.w = fmaxf(m.w, __shfl_xor_sync(0xffffffffu, m.w, off));
    }
    float4 den = make_float4(0.f, 0.f, 0.f, 0.f);
    for (int i = beg + lane; i < end; i += 32) {
        float4 v = alpha[i];
        float4 ex;
        ex.x = __expf(v.x - m.x); ex.y = __expf(v.y - m.y);
        ex.z = __expf(v.z - m.z); ex.w = __expf(v.w - m.w);
        alpha[i] = ex;
        den.x += ex.x; den.y += ex.y; den.z += ex.z; den.w += ex.w;
    }
#pragma unroll
    for (int off = 16; off; off >>= 1) {
        den.x += __shfl_xor_sync(0xffffffffu, den.x, off);
        den.y += __shfl_xor_sync(0xffffffffu, den.y, off);
        den.z += __shfl_xor_sync(0xffffffffu, den.z, off);
        den.w += __shfl_xor_sync(0xffffffffu, den.w, off);
    }
    float4 inv;
    inv.x = 1.0f / (den.x + 1e-16f); inv.y = 1.0f / (den.y + 1e-16f);
    inv.z = 1.0f / (den.z + 1e-16f); inv.w = 1.0f / (den.w + 1e-16f);
    __syncwarp();

    float acc[NHEADS] = {0.f, 0.f, 0.f, 0.f};
    for (int i = beg; i < end; i++) {
        int e = eids[i];
        int s = clampi(src[e], 0, NN - 1);
        float4 a = alpha[i];
        float w = 1.0f / (1.0f + (float)edist[e]);
        float aw[4] = {a.x * inv.x * w, a.y * inv.y * w, a.z * inv.z * w,
                       a.w * inv.w * w};
        if (lane < NCLS) {
            const float* hs = h + (size_t)s * (NHEADS * NCLS);
#pragma unroll
            for (int q = 0; q < NHEADS; q++) acc[q] += aw[q] * hs[q * NCLS + lane];
        }
    }
    if (lane < NCLS) {
        float v = 0.25f * (acc[0] + acc[1] + acc[2] + acc[3]) + b[lane];
        out[(size_t)n * NCLS + lane] = v > 0.f ? v : 0.1f * v;
    }
}

// ---------------- batch norm -----------------------------------------------
__global__ void bn_stats_k(const float* __restrict__ x, float* __restrict__ sum,
                           float* __restrict__ sumsq) {
    int t = threadIdx.x;
    int rows_per = (NN + gridDim.x - 1) / gridDim.x;
    int r0 = blockIdx.x * rows_per;
    int r1 = min(r0 + rows_per, NN);
    float s = 0.f, q = 0.f;
    for (int r = r0; r < r1; r++) {
        float v = x[(size_t)r * HID + t];
        s += v;
        q += v * v;
    }
    atomicAdd(&sum[t], s);
    atomicAdd(&sumsq[t], q);
}

__global__ void bn_apply_k(const float* __restrict__ x, const float* __restrict__ sum,
                           const float* __restrict__ sumsq, const float* __restrict__ g,
                           const float* __restrict__ b, float* __restrict__ out,
                           __half* __restrict__ A2) {
    int i = blockIdx.x * blockDim.x + threadIdx.x;
    if (i >= NN * HID) return;
    int o = i & 127;
    int n = i >> 7;
    float mu = sum[o] * (1.0f / NN);
    float var = sumsq[o] * (1.0f / NN) - mu * mu;
    float v = (x[i] - mu) * rsqrtf(var + 1e-5f) * g[o] + b[o];
    v = v > 0.f ? v : 0.1f * v;
    out[i] = v;
    if (A2) {
        __half h = __float2half_rn(v);
        __half l = __float2half_rn(v - __half2float(h));
        size_t base = (size_t)n * 256;
        A2[base + o] = h;
        A2[base + 128 + o] = l;
    }
}

// ---------------- host orchestration ---------------------------------------
struct Bufs {
    float *h_buf, *tmp, *xb, *hin, *es, *ed, *Wb, *bsum, *bsq;
    __half *Hh, *A2, *B1;
    int *cnt, *rowptr, *fill, *eids;
};

extern "C" void kernel_launch(void* const* d_in, const int* in_sizes, int n_in,
                              void* d_out, int out_size) {
    const float* x = (const float*)d_in[0];
    const int* ei = (const int*)d_in[1];
    const int* etype = (const int*)d_in[2];
    const int* edist = (const int*)d_in[3];
    const float* W0 = (const float*)d_in[4];
    const float* asrc0 = (const float*)d_in[5];
    const float* adst0 = (const float*)d_in[6];
    const float* aedge0 = (const float*)d_in[7];
    const float* b0 = (const float*)d_in[8];
    const float* rel0 = (const float*)d_in[9];
    const float* Wm = (const float*)d_in[10];
    const float* asrcm = (const float*)d_in[11];
    const float* adstm = (const float*)d_in[12];
    const float* aedgem = (const float*)d_in[13];
    const float* bm = (const float*)d_in[14];
    const float* relm = (const float*)d_in[15];
    const float* WL = (const float*)d_in[16];
    const float* asrcL = (const float*)d_in[17];
    const float* adstL = (const float*)d_in[18];
    const float* aedgeL = (const float*)d_in[19];
    const float* bL = (const float*)d_in[20];
    const float* relL = (const float*)d_in[21];
    const float* bn_g = (const float*)d_in[22];
    const float* bn_b = (const float*)d_in[23];

    static bool attr_set = false;
    if (!attr_set) {
        cudaFuncSetAttribute(mma_gemm_k, cudaFuncAttributeMaxDynamicSharedMemorySize,
                             NSTAGE * STAGEB);
        attr_set = true;
    }

    Bufs B;
    cudaGetSymbolAddress((void**)&B.h_buf, g_h);
    cudaGetSymbolAddress((void**)&B.Hh, g_Hh);
    cudaGetSymbolAddress((void**)&B.tmp, g_tmp);
    cudaGetSymbolAddress((void**)&B.xb, g_x);
    cudaGetSymbolAddress((void**)&B.hin, g_hin);
    cudaGetSymbolAddress((void**)&B.es, g_es);
    cudaGetSymbolAddress((void**)&B.ed, g_ed);
    cudaGetSymbolAddress((void**)&B.Wb, g_W);
    cudaGetSymbolAddress((void**)&B.bsum, g_bsum);
    cudaGetSymbolAddress((void**)&B.bsq, g_bsq);
    cudaGetSymbolAddress((void**)&B.A2, g_A2);
    cudaGetSymbolAddress((void**)&B.B1, g_B1);
    cudaGetSymbolAddress((void**)&B.cnt, g_cnt);
    cudaGetSymbolAddress((void**)&B.rowptr, g_rowptr);
    cudaGetSymbolAddress((void**)&B.fill, g_fill);
    cudaGetSymbolAddress((void**)&B.eids, g_eids);

    const int* src = ei;
    const int* dst = ei + NE;
    float4* lg4 = (float4*)B.tmp;
    dim3 ggrid(4, (NN + 127) / 128);
    int attn_blocks = (NN * 32 + 255) / 256;

    // layer-0: convA(1), convB(2), init(3), mma(4 = profiled slot)
    int na = NN * FIN;
    convA_k<<<(na + 255) / 256, 256>>>(x, B.A2, NN, FIN);
    int nb = NHEADS * FIN * HID;
    convB_k<<<(nb + 255) / 256, 256>>>(W0, B.B1, FIN, HID);
    init_zero_k<<<(NN + 255) / 256, 256>>>(B.cnt, B.bsum, B.bsq);
    mma_gemm_k<<<ggrid, 256, NSTAGE * STAGEB>>>(B.A2, B.B1, asrc0, adst0, B.Hh,
                                                B.es, B.ed, NN, FIN);
    count_k<<<(NE + 255) / 256, 256>>>(dst, B.cnt);
    scan_k<<<1, 1024>>>(B.cnt, B.rowptr, B.fill);
    scatter_k<<<(NE + 255) / 256, 256>>>(dst, B.fill, B.eids);
    attn_k<<<attn_blocks, 256>>>(B.Hh, B.es, B.ed, rel0, aedge0, src, etype,
                                 edist, B.rowptr, B.eids, lg4, b0, nullptr, B.xb);

    int nb128 = (NN * HID + 255) / 256;

    for (int i = 0; i < 3; i++) {
        bn_stats_k<<<200, 128>>>(B.xb, B.bsum + i * HID, B.bsq + i * HID);
        bn_apply_k<<<nb128, 256>>>(B.xb, B.bsum + i * HID, B.bsq + i * HID,
                                   bn_g + i * HID, bn_b + i * HID, B.hin, B.A2);
        int nbm = NHEADS * HID * HID;
        convB_k<<<(nbm + 255) / 256, 256>>>(Wm + (size_t)i * NHEADS * HID * HID,
                                            B.B1, HID, HID);
        mma_gemm_k<<<ggrid, 256, NSTAGE * STAGEB>>>(
            B.A2, B.B1, asrcm + i * NHEADS * HID, adstm + i * NHEADS * HID,
            B.Hh, B.es, B.ed, NN, HID);
        attn_k<<<attn_blocks, 256>>>(B.Hh, B.es, B.ed, relm + i * NREL * 2,
                                     aedgem + i * NHEADS * 2, src, etype, edist,
                                     B.rowptr, B.eids, lg4, bm + i * HID, B.hin,
                                     B.xb);
    }

    // final layer
    bn_stats_k<<<200, 128>>>(B.xb, B.bsum + 3 * HID, B.bsq + 3 * HID);
    bn_apply_k<<<nb128, 256>>>(B.xb, B.bsum + 3 * HID, B.bsq + 3 * HID,
                               bn_g + 3 * HID, bn_b + 3 * HID, B.hin,
                               (__half*)nullptr);
    {
        int tot = NHEADS * HID * NCLS;
        reorder_k<<<(tot + 255) / 256, 256>>>(WL, B.Wb, HID, NCLS);
        int Ncols = NHEADS * NCLS;
        dim3 grid((Ncols + BN - 1) / BN, (NN + BM - 1) / BM);
        sgemm_k<<<grid, 256>>>(B.hin, B.Wb, B.h_buf, NN, Ncols, HID);
        int warps = NN * NHEADS;
        int blocks = (warps * 32 + 255) / 256;
        esed_k<NCLS><<<blocks, 256>>>(B.h_buf, asrcL, adstL, B.es, B.ed);
        attnF_k<<<attn_blocks, 256>>>(B.h_buf, B.es, B.ed, relL, aedgeL, src,
                                      etype, edist, B.rowptr, B.eids, lg4, bL,
                                      (float*)d_out);
    }
}

// round 14
// speedup vs baseline: 1.0634x; 1.0245x over previous
#include <cuda_runtime.h>
#include <cuda_fp16.h>
#include <math.h>
#include <stdint.h>

#define NN 20000
#define NE 320000
#define NHEADS 4
#define NREL 40
#define FIN 768
#define HID 128
#define NCLS 9

// ---------------- scratch ---------------------------------------------------
__device__ __align__(16) float g_h[NN * NHEADS * HID];
__device__ __align__(16) __half g_Hh[NN * NHEADS * HID];
__device__ __align__(16) float g_tmp[NN * NHEADS * HID];
__device__ __align__(16) float g_x[NN * HID];
__device__ __align__(16) float g_hin[NN * HID];
__device__ __align__(16) float g_es[NN * NHEADS];
__device__ __align__(16) float g_ed[NN * NHEADS];
__device__ __align__(16) float g_W[FIN * NHEADS * HID];
__device__ __align__(16) __half g_A2[NN * 2 * FIN];
__device__ __align__(16) __half g_B1[(NHEADS * HID) * FIN];
__device__ int g_cnt[NN];
__device__ int g_rowptr[NN + 1];
__device__ int g_fill[NN];
__device__ int g_eids[NE];
__device__ float g_bsum[4 * HID];
__device__ float g_bsq[4 * HID];

__device__ __forceinline__ int clampi(int v, int lo, int hi) {
    return v < lo ? lo : (v > hi ? hi : v);
}

__device__ __forceinline__ uint32_t smem_u32(const void* p) {
    uint32_t a;
    asm("{ .reg .u64 t; cvta.to.shared.u64 t, %1; cvt.u32.u64 %0, t; }"
        : "=r"(a) : "l"(p));
    return a;
}

__device__ __forceinline__ void ldsm_x4(uint32_t* r, uint32_t addr) {
    asm volatile("ldmatrix.sync.aligned.m8n8.x4.shared.b16 {%0,%1,%2,%3}, [%4];"
                 : "=r"(r[0]), "=r"(r[1]), "=r"(r[2]), "=r"(r[3]) : "r"(addr));
}

__device__ __forceinline__ void mma16816(float* d, const uint32_t* a, uint32_t b0,
                                         uint32_t b1) {
    asm volatile(
        "mma.sync.aligned.m16n8k16.row.col.f32.f16.f16.f32 "
        "{%0,%1,%2,%3}, {%4,%5,%6,%7}, {%8,%9}, {%0,%1,%2,%3};"
        : "+f"(d[0]), "+f"(d[1]), "+f"(d[2]), "+f"(d[3])
        : "r"(a[0]), "r"(a[1]), "r"(a[2]), "r"(a[3]), "r"(b0), "r"(b1));
}

__device__ __forceinline__ void cp16(uint32_t saddr, const void* g, bool pred) {
    int sz = pred ? 16 : 0;
    asm volatile("cp.async.cg.shared.global [%0], [%1], 16, %2;"
                 :: "r"(saddr), "l"(g), "r"(sz));
}
#define CP_COMMIT() asm volatile("cp.async.commit_group;" ::: "memory")
#define CP_WAIT2() asm volatile("cp.async.wait_group 2;" ::: "memory")
#define CP_WAIT1() asm volatile("cp.async.wait_group 1;" ::: "memory")
#define CP_WAIT0() asm volatile("cp.async.wait_group 0;" ::: "memory")

// ---------------- fp16 2-term GEMM, K-chunk 32, 3-stage, fp16 H, es/ed -----
#define SMS 40
#define TILEB 10240
#define STAGEB (3 * TILEB)
#define NSTAGE 3
__global__ void __launch_bounds__(256, 2)
mma_gemm_k(const __half* __restrict__ A2, const __half* __restrict__ B1,
           const float* __restrict__ a_s, const float* __restrict__ a_d,
           __half* __restrict__ H, float* __restrict__ es, float* __restrict__ ed,
           int M, int K) {
    extern __shared__ char sm[];
    uint32_t s0 = smem_u32(sm);
    int tid = threadIdx.x;
    int wid = tid >> 5;
    int lane = tid & 31;
    int warp_m = wid & 3;
    int warp_n = wid >> 2;
    int row0 = blockIdx.y * 128;
    int col0 = blockIdx.x * 128;

    float acc[2][8][4];
#pragma unroll
    for (int i = 0; i < 2; i++)
#pragma unroll
        for (int j = 0; j < 8; j++)
#pragma unroll
            for (int q = 0; q < 4; q++) acc[i][j][q] = 0.f;

    int ksz = K / 32;
    int lr = tid >> 1;
    int lq = (tid & 1) * 16;
    int gr = row0 + lr;
    bool aval = gr < M;
    const __half* Abase = A2 + (size_t)(aval ? gr : 0) * (2 * K);
    const __half* Bbase = B1 + (size_t)(col0 + lr) * K;
    uint32_t sA = (uint32_t)((lr * SMS + lq) * 2);

#define ISSUE_STAGE(c) do {                                              \
        int _kb = (c) * 32;                                              \
        uint32_t _b = s0 + ((c) % NSTAGE) * STAGEB;                      \
        const __half* _g;                                                \
        _g = Abase + _kb + lq;                                           \
        cp16(_b + 0 * TILEB + sA, _g, aval);                             \
        cp16(_b + 0 * TILEB + sA + 16, _g + 8, aval);                    \
        _g = Abase + K + _kb + lq;                                       \
        cp16(_b + 1 * TILEB + sA, _g, aval);                             \
        cp16(_b + 1 * TILEB + sA + 16, _g + 8, aval);                    \
        _g = Bbase + _kb + lq;                                           \
        cp16(_b + 2 * TILEB + sA, _g, true);                             \
        cp16(_b + 2 * TILEB + sA + 16, _g + 8, true);                    \
        CP_COMMIT();                                                     \
    } while (0)

    ISSUE_STAGE(0);
    if (ksz > 1) ISSUE_STAGE(1);
    for (int c = 0; c < ksz; c++) {
        if (c + 2 < ksz) {
            ISSUE_STAGE(c + 2);
            CP_WAIT2();
        } else if (c + 1 < ksz) {
            CP_WAIT1();
        } else {
            CP_WAIT0();
        }
        __syncthreads();
        uint32_t base = s0 + (c % NSTAGE) * STAGEB;
#pragma unroll
        for (int k16 = 0; k16 < 32; k16 += 16) {
            uint32_t koff = (uint32_t)((k16 + ((lane >> 4) << 3)) * 2);
            uint32_t ah[2][4], al[2][4];
#pragma unroll
            for (int mf = 0; mf < 2; mf++) {
                int m = warp_m * 32 + mf * 16 + (lane & 15);
                uint32_t ro = (uint32_t)(m * SMS * 2) + koff;
                ldsm_x4(ah[mf], base + 0 * TILEB + ro);
                ldsm_x4(al[mf], base + 1 * TILEB + ro);
            }
#pragma unroll
            for (int jp = 0; jp < 4; jp++) {
                int n = warp_n * 64 + jp * 16 + (lane & 15);
                uint32_t ro = (uint32_t)(n * SMS * 2) + koff;
                uint32_t bf[4];
                ldsm_x4(bf, base + 2 * TILEB + ro);
#pragma unroll
                for (int mf = 0; mf < 2; mf++) {
                    mma16816(acc[mf][jp * 2 + 0], ah[mf], bf[0], bf[2]);
                    mma16816(acc[mf][jp * 2 + 1], ah[mf], bf[1], bf[3]);
                    mma16816(acc[mf][jp * 2 + 0], al[mf], bf[0], bf[2]);
                    mma16816(acc[mf][jp * 2 + 1], al[mf], bf[1], bf[3]);
                }
            }
        }
        __syncthreads();
    }
#undef ISSUE_STAGE

    int g = lane >> 2, t = lane & 3;
#pragma unroll
    for (int mf = 0; mf < 2; mf++) {
#pragma unroll
        for (int nf = 0; nf < 8; nf++) {
            int col = col0 + warp_n * 64 + nf * 8 + t * 2;
            int r0 = row0 + warp_m * 32 + mf * 16 + g;
            if (r0 < M)
                *(__half2*)(H + (size_t)r0 * 512 + col) =
                    __floats2half2_rn(acc[mf][nf][0], acc[mf][nf][1]);
            int r1 = r0 + 8;
            if (r1 < M)
                *(__half2*)(H + (size_t)r1 * 512 + col) =
                    __floats2half2_rn(acc[mf][nf][2], acc[mf][nf][3]);
        }
    }

    // fused es/ed: head = blockIdx.x
    {
        const float* asg = a_s + blockIdx.x * 128;
        const float* adg = a_d + blockIdx.x * 128;
        float ps[2][2] = {{0.f, 0.f}, {0.f, 0.f}};
        float pd[2][2] = {{0.f, 0.f}, {0.f, 0.f}};
#pragma unroll
        for (int nf = 0; nf < 8; nf++) {
#pragma unroll
            for (int j = 0; j < 2; j++) {
                int cw = warp_n * 64 + nf * 8 + t * 2 + j;
                float av = __ldg(asg + cw);
                float dv = __ldg(adg + cw);
#pragma unroll
                for (int mf = 0; mf < 2; mf++) {
                    ps[mf][0] += acc[mf][nf][j] * av;
                    ps[mf][1] += acc[mf][nf][2 + j] * av;
                    pd[mf][0] += acc[mf][nf][j] * dv;
                    pd[mf][1] += acc[mf][nf][2 + j] * dv;
                }
            }
        }
#pragma unroll
        for (int mf = 0; mf < 2; mf++)
#pragma unroll
            for (int hf = 0; hf < 2; hf++) {
#pragma unroll
                for (int off = 1; off <= 2; off <<= 1) {
                    ps[mf][hf] += __shfl_xor_sync(0xffffffffu, ps[mf][hf], off);
                    pd[mf][hf] += __shfl_xor_sync(0xffffffffu, pd[mf][hf], off);
                }
            }
        float* se = (float*)sm;
        float* sd = se + 256;
        if (t == 0) {
#pragma unroll
            for (int mf = 0; mf < 2; mf++)
#pragma unroll
                for (int hf = 0; hf < 2; hf++) {
                    int row = warp_m * 32 + mf * 16 + g + hf * 8;
                    se[row * 2 + warp_n] = ps[mf][hf];
                    sd[row * 2 + warp_n] = pd[mf][hf];
                }
        }
        __syncthreads();
        if (tid < 128) {
            int grr = row0 + tid;
            if (grr < M) {
                es[grr * 4 + blockIdx.x] = se[tid * 2] + se[tid * 2 + 1];
                ed[grr * 4 + blockIdx.x] = sd[tid * 2] + sd[tid * 2 + 1];
            }
        }
    }
}

// ---------------- fp32 -> fp16 hi/lo split (layer 0 input) -----------------
__global__ void convA_k(const float* __restrict__ X, __half* __restrict__ A2,
                        int M, int K) {
    int i = blockIdx.x * blockDim.x + threadIdx.x;
    if (i >= M * K) return;
    int r = i / K, k = i - r * K;
    float v = X[i];
    __half h = __float2half_rn(v);
    __half l = __float2half_rn(v - __half2float(h));
    size_t base = (size_t)r * 2 * K;
    A2[base + k] = h;
    A2[base + K + k] = l;
}

// W [H,K,O] -> B1 [(h*O+o), K] fp16
__global__ void convB_k(const float* __restrict__ W, __half* __restrict__ B1,
                        int K, int O) {
    int idx = blockIdx.x * blockDim.x + threadIdx.x;
    int tot = NHEADS * K * O;
    if (idx >= tot) return;
    int o = idx % O;
    int f = (idx / O) % K;
    int h = idx / (O * K);
    B1[(size_t)(h * O + o) * K + f] = __float2half_rn(W[idx]);
}

// ---------------- init: zero cnt + bn stat buffers -------------------------
__global__ void init_zero_k(int* cnt, float* bsum, float* bsq) {
    int i = blockIdx.x * blockDim.x + threadIdx.x;
    if (i < NN) cnt[i] = 0;
    if (i < 4 * HID) { bsum[i] = 0.f; bsq[i] = 0.f; }
}

__global__ void count_k(const int* __restrict__ dst, int* __restrict__ cnt) {
    int e = blockIdx.x * blockDim.x + threadIdx.x;
    if (e < NE) atomicAdd(&cnt[clampi(dst[e], 0, NN - 1)], 1);
}

__global__ void scan_k(const int* __restrict__ cnt, int* __restrict__ rowptr,
                       int* __restrict__ fill) {
    __shared__ int sh[1024];
    int tid = threadIdx.x;
    int carry = 0;
    if (tid == 0) rowptr[0] = 0;
    for (int base = 0; base < NN; base += 1024) {
        int i = base + tid;
        int v = (i < NN) ? cnt[i] : 0;
        sh[tid] = v;
        __syncthreads();
        for (int off = 1; off < 1024; off <<= 1) {
            int t = (tid >= off) ? sh[tid - off] : 0;
            __syncthreads();
            sh[tid] += t;
            __syncthreads();
        }
        int incl = sh[tid];
        if (i < NN) {
            rowptr[i + 1] = carry + incl;
            fill[i] = carry + incl - v;
        }
        carry += sh[1023];
        __syncthreads();
    }
}

__global__ void scatter_k(const int* __restrict__ dst, int* __restrict__ fill,
                          int* __restrict__ eids) {
    int e = blockIdx.x * blockDim.x + threadIdx.x;
    if (e < NE) {
        int d = clampi(dst[e], 0, NN - 1);
        int pos = atomicAdd(&fill[d], 1);
        if (pos >= 0 && pos < NE) eids[pos] = e;
    }
}

// ---------------- weight reorder (final layer) -----------------------------
__global__ void reorder_k(const float* __restrict__ W, float* __restrict__ out,
                          int K, int O) {
    int idx = blockIdx.x * blockDim.x + threadIdx.x;
    int tot = NHEADS * K * O;
    if (idx >= tot) return;
    int o = idx % O;
    int f = (idx / O) % K;
    int h = idx / (O * K);
    out[f * (NHEADS * O) + h * O + o] = W[idx];
}

// ---------------- SIMT SGEMM (final small layer) ---------------------------
#define BM 128
#define BN 128
#define BK 8
__global__ __launch_bounds__(256)
void sgemm_k(const float* __restrict__ A, const float* __restrict__ B,
             float* __restrict__ C, int M, int N, int K) {
    __shared__ float As[BK][BM];
    __shared__ float Bs[BK][BN];
    int tid = threadIdx.x;
    int row0 = blockIdx.y * BM;
    int col0 = blockIdx.x * BN;

    int aRow = tid >> 1;
    int aCol = (tid & 1) * 4;
    int bRow = tid >> 5;
    int bCol = (tid & 31) * 4;
    int ty = tid >> 4;
    int tx = tid & 15;

    float acc[8][8];
#pragma unroll
    for (int i = 0; i < 8; i++)
#pragma unroll
        for (int j = 0; j < 8; j++) acc[i][j] = 0.f;

    for (int k0 = 0; k0 < K; k0 += BK) {
        float4 av = make_float4(0.f, 0.f, 0.f, 0.f);
        int gr = row0 + aRow;
        if (gr < M) av = *(const float4*)(A + (size_t)gr * K + k0 + aCol);
        As[aCol + 0][aRow] = av.x;
        As[aCol + 1][aRow] = av.y;
        As[aCol + 2][aRow] = av.z;
        As[aCol + 3][aRow] = av.w;

        float4 bv = make_float4(0.f, 0.f, 0.f, 0.f);
        int gc = col0 + bCol;
        if (gc + 3 < N) bv = *(const float4*)(B + (size_t)(k0 + bRow) * N + gc);
        Bs[bRow][bCol + 0] = bv.x;
        Bs[bRow][bCol + 1] = bv.y;
        Bs[bRow][bCol + 2] = bv.z;
        Bs[bRow][bCol + 3] = bv.w;
        __syncthreads();

#pragma unroll
        for (int k = 0; k < BK; k++) {
            float ra[8], rb[8];
#pragma unroll
            for (int i = 0; i < 8; i++) ra[i] = As[k][ty * 8 + i];
#pragma unroll
            for (int j = 0; j < 8; j++) rb[j] = Bs[k][tx * 8 + j];
#pragma unroll
            for (int i = 0; i < 8; i++)
#pragma unroll
                for (int j = 0; j < 8; j++) acc[i][j] += ra[i] * rb[j];
        }
        __syncthreads();
    }

#pragma unroll
    for (int i = 0; i < 8; i++) {
        int r = row0 + ty * 8 + i;
        if (r >= M) continue;
#pragma unroll
        for (int j = 0; j < 8; j++) {
            int c = col0 + tx * 8 + j;
            if (c < N) C[(size_t)r * N + c] = acc[i][j];
        }
    }
}

// ---------------- es/ed (final layer only) ---------------------------------
template <int O>
__global__ void esed_k(const float* __restrict__ h, const float* __restrict__ a_s,
                       const float* __restrict__ a_d, float* __restrict__ es,
                       float* __restrict__ ed) {
    int w = (blockIdx.x * blockDim.x + threadIdx.x) >> 5;
    int lane = threadIdx.x & 31;
    if (w >= NN * NHEADS) return;
    int hd = w % NHEADS;
    const float* hp = h + (size_t)w * O;
    float s = 0.f, d = 0.f;
    for (int k = lane; k < O; k += 32) {
        float v = hp[k];
        s += v * a_s[hd * O + k];
        d += v * a_d[hd * O + k];
    }
#pragma unroll
    for (int off = 16; off; off >>= 1) {
        s += __shfl_xor_sync(0xffffffffu, s, off);
        d += __shfl_xor_sync(0xffffffffu, d, off);
    }
    if (lane == 0) { es[w] = s; ed[w] = d; }
}

__device__ __forceinline__ float lrelu02(float v) { return v > 0.f ? v : 0.2f * v; }

// ---------------- fused attention + output BN-stats ------------------------
// grid is exactly NN*32/256 blocks; every warp owns a valid node.
__global__ void attn_k(const __half* __restrict__ H, const float* __restrict__ es,
                       const float* __restrict__ ed, const float* __restrict__ rel,
                       const float* __restrict__ ae, const int* __restrict__ src,
                       const int* __restrict__ etype, const int* __restrict__ edist,
                       const int* __restrict__ rowptr, const int* __restrict__ eids,
                       float4* __restrict__ alpha, const float* __restrict__ b,
                       const float* __restrict__ resid, float* __restrict__ out,
                       float* __restrict__ bsum, float* __restrict__ bsq) {
    __shared__ __align__(16) float eetab[NREL * NHEADS];
    __shared__ float ssum[HID];
    __shared__ float ssq[HID];
    int tid = threadIdx.x;
    if (tid < NREL * NHEADS) {
        int r = tid >> 2, hd = tid & 3;
        eetab[tid] = rel[r * 2] * ae[hd * 2] + rel[r * 2 + 1] * ae[hd * 2 + 1];
    }
    if (tid < HID) { ssum[tid] = 0.f; ssq[tid] = 0.f; }
    __syncthreads();

    int n = (blockIdx.x * blockDim.x + tid) >> 5;
    int lane = tid & 31;
    int beg = rowptr[n], end = rowptr[n + 1];
    float4 edn = *(const float4*)(ed + n * 4);

    // pass 1: logits + max
    float4 m = make_float4(-3.4e38f, -3.4e38f, -3.4e38f, -3.4e38f);
    for (int i = beg + lane; i < end; i += 32) {
        int e = eids[i];
        int s = clampi(src[e], 0, NN - 1);
        int t = clampi(etype[e], 0, NREL - 1);
        float4 a = *(const float4*)(es + s * 4);
        float4 c = *(const float4*)(eetab + t * 4);
        float4 lg;
        lg.x = lrelu02(a.x + edn.x + c.x);
        lg.y = lrelu02(a.y + edn.y + c.y);
        lg.z = lrelu02(a.z + edn.z + c.z);
        lg.w = lrelu02(a.w + edn.w + c.w);
        alpha[i] = lg;
        m.x = fmaxf(m.x, lg.x); m.y = fmaxf(m.y, lg.y);
        m.z = fmaxf(m.z, lg.z); m.w = fmaxf(m.w, lg.w);
    }
#pragma unroll
    for (int off = 16; off; off >>= 1) {
        m.x = fmaxf(m.x, __shfl_xor_sync(0xffffffffu, m.x, off));
        m.y = fmaxf(m.y, __shfl_xor_sync(0xffffffffu, m.y, off));
        m.z = fmaxf(m.z, __shfl_xor_sync(0xffffffffu, m.z, off));
        m.w = fmaxf(m.w, __shfl_xor_sync(0xffffffffu, m.w, off));
    }
    // pass 2: exp + den
    float4 den = make_float4(0.f, 0.f, 0.f, 0.f);
    for (int i = beg + lane; i < end; i += 32) {
        float4 v = alpha[i];
        float4 ex;
        ex.x = __expf(v.x - m.x); ex.y = __expf(v.y - m.y);
        ex.z = __expf(v.z - m.z); ex.w = __expf(v.w - m.w);
        alpha[i] = ex;
        den.x += ex.x; den.y += ex.y; den.z += ex.z; den.w += ex.w;
    }
#pragma unroll
    for (int off = 16; off; off >>= 1) {
        den.x += __shfl_xor_sync(0xffffffffu, den.x, off);
        den.y += __shfl_xor_sync(0xffffffffu, den.y, off);
        den.z += __shfl_xor_sync(0xffffffffu, den.z, off);
        den.w += __shfl_xor_sync(0xffffffffu, den.w, off);
    }
    float4 inv;
    inv.x = 1.0f / (den.x + 1e-16f); inv.y = 1.0f / (den.y + 1e-16f);
    inv.z = 1.0f / (den.z + 1e-16f); inv.w = 1.0f / (den.w + 1e-16f);
    __syncwarp();

    // pass 3: gather (half2 coalesced) + head-mean + bias + residual
    float2 accA[NHEADS], accB[NHEADS];
#pragma unroll
    for (int q = 0; q < NHEADS; q++) {
        accA[q] = make_float2(0.f, 0.f);
        accB[q] = make_float2(0.f, 0.f);
    }
    for (int i = beg; i < end; i++) {
        int e = eids[i];
        int s = clampi(src[e], 0, NN - 1);
        float4 a = alpha[i];
        float w = 1.0f / (1.0f + (float)edist[e]);
        float aw[4] = {a.x * inv.x * w, a.y * inv.y * w, a.z * inv.z * w,
                       a.w * inv.w * w};
        const __half2* hs2 = (const __half2*)(H + (size_t)s * 512);
#pragma unroll
        for (int q = 0; q < NHEADS; q++) {
            float2 fa = __half22float2(hs2[q * 64 + lane]);
            float2 fb = __half22float2(hs2[q * 64 + 32 + lane]);
            accA[q].x += aw[q] * fa.x; accA[q].y += aw[q] * fa.y;
            accB[q].x += aw[q] * fb.x; accB[q].y += aw[q] * fb.y;
        }
    }
    {
        int oA = 2 * lane, oB = 64 + 2 * lane;
        float2 bA = *(const float2*)(b + oA);
        float2 bB = *(const float2*)(b + oB);
        float2 vA, vB;
        vA.x = 0.25f * (accA[0].x + accA[1].x + accA[2].x + accA[3].x) + bA.x;
        vA.y = 0.25f * (accA[0].y + accA[1].y + accA[2].y + accA[3].y) + bA.y;
        vB.x = 0.25f * (accB[0].x + accB[1].x + accB[2].x + accB[3].x) + bB.x;
        vB.y = 0.25f * (accB[0].y + accB[1].y + accB[2].y + accB[3].y) + bB.y;
        if (resid) {
            float2 rA = *(const float2*)(resid + (size_t)n * 128 + oA);
            float2 rB = *(const float2*)(resid + (size_t)n * 128 + oB);
            vA.x += rA.x; vA.y += rA.y; vB.x += rB.x; vB.y += rB.y;
        }
        *(float2*)(out + (size_t)n * 128 + oA) = vA;
        *(float2*)(out + (size_t)n * 128 + oB) = vB;

        // fused BN statistics of the layer output
        atomicAdd(&ssum[oA], vA.x);
        atomicAdd(&ssum[oA + 1], vA.y);
        atomicAdd(&ssum[oB], vB.x);
        atomicAdd(&ssum[oB + 1], vB.y);
        atomicAdd(&ssq[oA], vA.x * vA.x);
        atomicAdd(&ssq[oA + 1], vA.y * vA.y);
        atomicAdd(&ssq[oB], vB.x * vB.x);
        atomicAdd(&ssq[oB + 1], vB.y * vB.y);
    }
    __syncthreads();
    if (tid < HID) {
        atomicAdd(&bsum[tid], ssum[tid]);
        atomicAdd(&bsq[tid], ssq[tid]);
    }
}

// ---------------- final-layer softmax (standalone, eetab smem) -------------
__global__ void lsm_k(const float* __restrict__ es, const float* __restrict__ ed,
                      const float* __restrict__ rel, const float* __restrict__ ae,
                      const int* __restrict__ src, const int* __restrict__ etype,
                      const int* __restrict__ edist, const int* __restrict__ rowptr,
                      const int* __restrict__ eids, float4* __restrict__ alpha) {
    __shared__ __align__(16) float eetab[NREL * NHEADS];
    int tid = threadIdx.x;
    if (tid < NREL * NHEADS) {
        int r = tid >> 2, hd = tid & 3;
        eetab[tid] = rel[r * 2] * ae[hd * 2] + rel[r * 2 + 1] * ae[hd * 2 + 1];
    }
    __syncthreads();

    int n = (blockIdx.x * blockDim.x + tid) >> 5;
    int lane = tid & 31;
    if (n >= NN) return;
    int beg = rowptr[n], end = rowptr[n + 1];
    float4 edn = *(const float4*)(ed + n * 4);

    float4 m = make_float4(-3.4e38f, -3.4e38f, -3.4e38f, -3.4e38f);
    for (int i = beg + lane; i < end; i += 32) {
        int e = eids[i];
        int s = clampi(src[e], 0, NN - 1);
        int t = clampi(etype[e], 0, NREL - 1);
        float4 a = *(const float4*)(es + s * 4);
        float4 c = *(const float4*)(eetab + t * 4);
        float4 lg;
        lg.x = lrelu02(a.x + edn.x + c.x);
        lg.y = lrelu02(a.y + edn.y + c.y);
        lg.z = lrelu02(a.z + edn.z + c.z);
        lg.w = lrelu02(a.w + edn.w + c.w);
        alpha[i] = lg;
        m.x = fmaxf(m.x, lg.x); m.y = fmaxf(m.y, lg.y);
        m.z = fmaxf(m.z, lg.z); m.w = fmaxf(m.w, lg.w);
    }
#pragma unroll
    for (int off = 16; off; off >>= 1) {
        m.x = fmaxf(m.x, __shfl_xor_sync(0xffffffffu, m.x, off));
        m.y = fmaxf(m.y, __shfl_xor_sync(0xffffffffu, m.y, off));
        m.z = fmaxf(m.z, __shfl_xor_sync(0xffffffffu, m.z, off));
        m.w = fmaxf(m.w, __shfl_xor_sync(0xffffffffu, m.w, off));
    }
    float4 den = make_float4(0.f, 0.f, 0.f, 0.f);
    for (int i = beg + lane; i < end; i += 32) {
        float4 v = alpha[i];
        float4 ex;
        ex.x = __expf(v.x - m.x); ex.y = __expf(v.y - m.y);
        ex.z = __expf(v.z - m.z); ex.w = __expf(v.w - m.w);
        alpha[i] = ex;
        den.x += ex.x; den.y += ex.y; den.z += ex.z; den.w += ex.w;
    }
#pragma unroll
    for (int off = 16; off; off >>= 1) {
        den.x += __shfl_xor_sync(0xffffffffu, den.x, off);
        den.y += __shfl_xor_sync(0xffffffffu, den.y, off);
        den.z += __shfl_xor_sync(0xffffffffu, den.z, off);
        den.w += __shfl_xor_sync(0xffffffffu, den.w, off);
    }
    float4 inv;
    inv.x = 1.0f / (den.x + 1e-16f); inv.y = 1.0f / (den.y + 1e-16f);
    inv.z = 1.0f / (den.z + 1e-16f); inv.w = 1.0f / (den.w + 1e-16f);
    for (int i = beg + lane; i < end; i += 32) {
        float4 v = alpha[i];
        float w = 1.0f / (1.0f + (float)edist[eids[i]]);
        v.x *= inv.x * w; v.y *= inv.y * w;
        v.z *= inv.z * w; v.w *= inv.w * w;
        alpha[i] = v;
    }
}

// ---------------- final layer gather (O=9) + combine + lrelu ---------------
__global__ void aggF_k(const float* __restrict__ h, const float4* __restrict__ alpha4,
                       const int* __restrict__ src, const int* __restrict__ eids,
                       const int* __restrict__ rowptr, const float* __restrict__ b,
                       float* __restrict__ out) {
    int n = (blockIdx.x * blockDim.x + threadIdx.x) >> 5;
    int lane = threadIdx.x & 31;
    if (n >= NN) return;
    int beg = rowptr[n], end = rowptr[n + 1];
    float acc[NHEADS] = {0.f, 0.f, 0.f, 0.f};
    for (int i = beg; i < end; i++) {
        int e = eids[i];
        int s = clampi(src[e], 0, NN - 1);
        float4 a = alpha4[i];
        float aw[4] = {a.x, a.y, a.z, a.w};
        if (lane < NCLS) {
            const float* hs = h + (size_t)s * (NHEADS * NCLS);
#pragma unroll
            for (int q = 0; q < NHEADS; q++) acc[q] += aw[q] * hs[q * NCLS + lane];
        }
    }
    if (lane < NCLS) {
        float v = 0.25f * (acc[0] + acc[1] + acc[2] + acc[3]) + b[lane];
        out[(size_t)n * NCLS + lane] = v > 0.f ? v : 0.1f * v;
    }
}

// ---------------- batch norm apply -----------------------------------------
__global__ void bn_apply_k(const float* __restrict__ x, const float* __restrict__ sum,
                           const float* __restrict__ sumsq, const float* __restrict__ g,
                           const float* __restrict__ b, float* __restrict__ out,
                           __half* __restrict__ A2) {
    int i = blockIdx.x * blockDim.x + threadIdx.x;
    if (i >= NN * HID) return;
    int o = i & 127;
    int n = i >> 7;
    float mu = sum[o] * (1.0f / NN);
    float var = sumsq[o] * (1.0f / NN) - mu * mu;
    float v = (x[i] - mu) * rsqrtf(var + 1e-5f) * g[o] + b[o];
    v = v > 0.f ? v : 0.1f * v;
    out[i] = v;
    if (A2) {
        __half h = __float2half_rn(v);
        __half l = __float2half_rn(v - __half2float(h));
        size_t base = (size_t)n * 256;
        A2[base + o] = h;
        A2[base + 128 + o] = l;
    }
}

// ---------------- host orchestration ---------------------------------------
struct Bufs {
    float *h_buf, *tmp, *xb, *hin, *es, *ed, *Wb, *bsum, *bsq;
    __half *Hh, *A2, *B1;
    int *cnt, *rowptr, *fill, *eids;
};

extern "C" void kernel_launch(void* const* d_in, const int* in_sizes, int n_in,
                              void* d_out, int out_size) {
    const float* x = (const float*)d_in[0];
    const int* ei = (const int*)d_in[1];
    const int* etype = (const int*)d_in[2];
    const int* edist = (const int*)d_in[3];
    const float* W0 = (const float*)d_in[4];
    const float* asrc0 = (const float*)d_in[5];
    const float* adst0 = (const float*)d_in[6];
    const float* aedge0 = (const float*)d_in[7];
    const float* b0 = (const float*)d_in[8];
    const float* rel0 = (const float*)d_in[9];
    const float* Wm = (const float*)d_in[10];
    const float* asrcm = (const float*)d_in[11];
    const float* adstm = (const float*)d_in[12];
    const float* aedgem = (const float*)d_in[13];
    const float* bm = (const float*)d_in[14];
    const float* relm = (const float*)d_in[15];
    const float* WL = (const float*)d_in[16];
    const float* asrcL = (const float*)d_in[17];
    const float* adstL = (const float*)d_in[18];
    const float* aedgeL = (const float*)d_in[19];
    const float* bL = (const float*)d_in[20];
    const float* relL = (const float*)d_in[21];
    const float* bn_g = (const float*)d_in[22];
    const float* bn_b = (const float*)d_in[23];

    static bool attr_set = false;
    if (!attr_set) {
        cudaFuncSetAttribute(mma_gemm_k, cudaFuncAttributeMaxDynamicSharedMemorySize,
                             NSTAGE * STAGEB);
        attr_set = true;
    }

    Bufs B;
    cudaGetSymbolAddress((void**)&B.h_buf, g_h);
    cudaGetSymbolAddress((void**)&B.Hh, g_Hh);
    cudaGetSymbolAddress((void**)&B.tmp, g_tmp);
    cudaGetSymbolAddress((void**)&B.xb, g_x);
    cudaGetSymbolAddress((void**)&B.hin, g_hin);
    cudaGetSymbolAddress((void**)&B.es, g_es);
    cudaGetSymbolAddress((void**)&B.ed, g_ed);
    cudaGetSymbolAddress((void**)&B.Wb, g_W);
    cudaGetSymbolAddress((void**)&B.bsum, g_bsum);
    cudaGetSymbolAddress((void**)&B.bsq, g_bsq);
    cudaGetSymbolAddress((void**)&B.A2, g_A2);
    cudaGetSymbolAddress((void**)&B.B1, g_B1);
    cudaGetSymbolAddress((void**)&B.cnt, g_cnt);
    cudaGetSymbolAddress((void**)&B.rowptr, g_rowptr);
    cudaGetSymbolAddress((void**)&B.fill, g_fill);
    cudaGetSymbolAddress((void**)&B.eids, g_eids);

    const int* src = ei;
    const int* dst = ei + NE;
    float4* lg4 = (float4*)B.tmp;
    dim3 ggrid(4, (NN + 127) / 128);
    int attn_blocks = (NN * 32) / 256;  // exactly 2500, all warps valid

    // layer-0: convA(1), convB(2), init(3), mma(4 = profiled slot)
    int na = NN * FIN;
    convA_k<<<(na + 255) / 256, 256>>>(x, B.A2, NN, FIN);
    int nb = NHEADS * FIN * HID;
    convB_k<<<(nb + 255) / 256, 256>>>(W0, B.B1, FIN, HID);
    init_zero_k<<<(NN + 255) / 256, 256>>>(B.cnt, B.bsum, B.bsq);
    mma_gemm_k<<<ggrid, 256, NSTAGE * STAGEB>>>(B.A2, B.B1, asrc0, adst0, B.Hh,
                                                B.es, B.ed, NN, FIN);
    count_k<<<(NE + 255) / 256, 256>>>(dst, B.cnt);
    scan_k<<<1, 1024>>>(B.cnt, B.rowptr, B.fill);
    scatter_k<<<(NE + 255) / 256, 256>>>(dst, B.fill, B.eids);
    attn_k<<<attn_blocks, 256>>>(B.Hh, B.es, B.ed, rel0, aedge0, src, etype,
                                 edist, B.rowptr, B.eids, lg4, b0, nullptr, B.xb,
                                 B.bsum, B.bsq);

    int nb128 = (NN * HID + 255) / 256;

    for (int i = 0; i < 3; i++) {
        bn_apply_k<<<nb128, 256>>>(B.xb, B.bsum + i * HID, B.bsq + i * HID,
                                   bn_g + i * HID, bn_b + i * HID, B.hin, B.A2);
        int nbm = NHEADS * HID * HID;
        convB_k<<<(nbm + 255) / 256, 256>>>(Wm + (size_t)i * NHEADS * HID * HID,
                                            B.B1, HID, HID);
        mma_gemm_k<<<ggrid, 256, NSTAGE * STAGEB>>>(
            B.A2, B.B1, asrcm + i * NHEADS * HID, adstm + i * NHEADS * HID,
            B.Hh, B.es, B.ed, NN, HID);
        attn_k<<<attn_blocks, 256>>>(B.Hh, B.es, B.ed, relm + i * NREL * 2,
                                     aedgem + i * NHEADS * 2, src, etype, edist,
                                     B.rowptr, B.eids, lg4, bm + i * HID, B.hin,
                                     B.xb, B.bsum + (i + 1) * HID,
                                     B.bsq + (i + 1) * HID);
    }

    // final layer
    bn_apply_k<<<nb128, 256>>>(B.xb, B.bsum + 3 * HID, B.bsq + 3 * HID,
                               bn_g + 3 * HID, bn_b + 3 * HID, B.hin,
                               (__half*)nullptr);
    {
        int tot = NHEADS * HID * NCLS;
        reorder_k<<<(tot + 255) / 256, 256>>>(WL, B.Wb, HID, NCLS);
        int Ncols = NHEADS * NCLS;
        dim3 grid((Ncols + BN - 1) / BN, (NN + BM - 1) / BM);
        sgemm_k<<<grid, 256>>>(B.hin, B.Wb, B.h_buf, NN, Ncols, HID);
        int warps = NN * NHEADS;
        int blocks = (warps * 32 + 255) / 256;
        esed_k<NCLS><<<blocks, 256>>>(B.h_buf, asrcL, adstL, B.es, B.ed);
        lsm_k<<<(NN * 32 + 255) / 256, 256>>>(B.es, B.ed, relL, aedgeL, src,
                                              etype, edist, B.rowptr, B.eids, lg4);
        aggF_k<<<(NN * 32 + 255) / 256, 256>>>(B.h_buf, lg4, src, B.eids,
                                               B.rowptr, bL, (float*)d_out);
    }
}

// round 15
// speedup vs baseline: 1.1074x; 1.0414x over previous
#include <cuda_runtime.h>
#include <cuda_fp16.h>
#include <math.h>
#include <stdint.h>

#define NN 20000
#define NE 320000
#define NHEADS 4
#define NREL 40
#define FIN 768
#define HID 128
#define NCLS 9

// ---------------- scratch ---------------------------------------------------
__device__ __align__(16) float g_h[NN * NHEADS * HID];
__device__ __align__(16) __half g_Hh[NN * NHEADS * HID];
__device__ __align__(16) float g_tmp[NN * NHEADS * HID];
__device__ __align__(16) float g_x[NN * HID];
__device__ __align__(16) float g_hin[NN * HID];
__device__ __align__(16) float g_es[NN * NHEADS];
__device__ __align__(16) float g_ed[NN * NHEADS];
__device__ __align__(16) float g_W[FIN * NHEADS * HID];
__device__ __align__(16) __half g_A2[NN * 2 * FIN];
__device__ __align__(16) __half g_B1[(NHEADS * HID) * FIN];
__device__ int g_cnt[NN];
__device__ int g_rowptr[NN + 1];
__device__ int g_fill[NN];
__device__ int g_eids[NE];
__device__ float g_bsum[4 * HID];
__device__ float g_bsq[4 * HID];

__device__ __forceinline__ int clampi(int v, int lo, int hi) {
    return v < lo ? lo : (v > hi ? hi : v);
}

__device__ __forceinline__ uint32_t smem_u32(const void* p) {
    uint32_t a;
    asm("{ .reg .u64 t; cvta.to.shared.u64 t, %1; cvt.u32.u64 %0, t; }"
        : "=r"(a) : "l"(p));
    return a;
}

__device__ __forceinline__ void ldsm_x4(uint32_t* r, uint32_t addr) {
    asm volatile("ldmatrix.sync.aligned.m8n8.x4.shared.b16 {%0,%1,%2,%3}, [%4];"
                 : "=r"(r[0]), "=r"(r[1]), "=r"(r[2]), "=r"(r[3]) : "r"(addr));
}

__device__ __forceinline__ void mma16816(float* d, const uint32_t* a, uint32_t b0,
                                         uint32_t b1) {
    asm volatile(
        "mma.sync.aligned.m16n8k16.row.col.f32.f16.f16.f32 "
        "{%0,%1,%2,%3}, {%4,%5,%6,%7}, {%8,%9}, {%0,%1,%2,%3};"
        : "+f"(d[0]), "+f"(d[1]), "+f"(d[2]), "+f"(d[3])
        : "r"(a[0]), "r"(a[1]), "r"(a[2]), "r"(a[3]), "r"(b0), "r"(b1));
}

__device__ __forceinline__ void cp16(uint32_t saddr, const void* g, bool pred) {
    int sz = pred ? 16 : 0;
    asm volatile("cp.async.cg.shared.global [%0], [%1], 16, %2;"
                 :: "r"(saddr), "l"(g), "r"(sz));
}
#define CP_COMMIT() asm volatile("cp.async.commit_group;" ::: "memory")
#define CP_WAIT2() asm volatile("cp.async.wait_group 2;" ::: "memory")
#define CP_WAIT1() asm volatile("cp.async.wait_group 1;" ::: "memory")
#define CP_WAIT0() asm volatile("cp.async.wait_group 0;" ::: "memory")

// ---- fp16 GEMM, K-chunk 32, 3-stage, fp16 H, fused es/ed -------------------
// TERMS=2: A split hi/lo (2-term product). TERMS=1: hi only.
#define SMS 40
#define TILEB 10240
#define STAGEB (3 * TILEB)
#define NSTAGE 3
template <int TERMS>
__global__ void __launch_bounds__(256, 2)
mma_gemm_k(const __half* __restrict__ A2, const __half* __restrict__ B1,
           const float* __restrict__ a_s, const float* __restrict__ a_d,
           __half* __restrict__ H, float* __restrict__ es, float* __restrict__ ed,
           int M, int K) {
    extern __shared__ char sm[];
    uint32_t s0 = smem_u32(sm);
    int tid = threadIdx.x;
    int wid = tid >> 5;
    int lane = tid & 31;
    int warp_m = wid & 3;
    int warp_n = wid >> 2;
    int row0 = blockIdx.y * 128;
    int col0 = blockIdx.x * 128;

    float acc[2][8][4];
#pragma unroll
    for (int i = 0; i < 2; i++)
#pragma unroll
        for (int j = 0; j < 8; j++)
#pragma unroll
            for (int q = 0; q < 4; q++) acc[i][j][q] = 0.f;

    int ksz = K / 32;
    int lr = tid >> 1;
    int lq = (tid & 1) * 16;
    int gr = row0 + lr;
    bool aval = gr < M;
    const __half* Abase = A2 + (size_t)(aval ? gr : 0) * (2 * K);
    const __half* Bbase = B1 + (size_t)(col0 + lr) * K;
    uint32_t sA = (uint32_t)((lr * SMS + lq) * 2);

#define ISSUE_STAGE(c) do {                                              \
        int _kb = (c) * 32;                                              \
        uint32_t _b = s0 + ((c) % NSTAGE) * STAGEB;                      \
        const __half* _g;                                                \
        _g = Abase + _kb + lq;                                           \
        cp16(_b + 0 * TILEB + sA, _g, aval);                             \
        cp16(_b + 0 * TILEB + sA + 16, _g + 8, aval);                    \
        if (TERMS == 2) {                                                \
            _g = Abase + K + _kb + lq;                                   \
            cp16(_b + 1 * TILEB + sA, _g, aval);                         \
            cp16(_b + 1 * TILEB + sA + 16, _g + 8, aval);                \
        }                                                                \
        _g = Bbase + _kb + lq;                                           \
        cp16(_b + 2 * TILEB + sA, _g, true);                             \
        cp16(_b + 2 * TILEB + sA + 16, _g + 8, true);                    \
        CP_COMMIT();                                                     \
    } while (0)

    ISSUE_STAGE(0);
    if (ksz > 1) ISSUE_STAGE(1);
    for (int c = 0; c < ksz; c++) {
        if (c + 2 < ksz) {
            ISSUE_STAGE(c + 2);
            CP_WAIT2();
        } else if (c + 1 < ksz) {
            CP_WAIT1();
        } else {
            CP_WAIT0();
        }
        __syncthreads();
        uint32_t base = s0 + (c % NSTAGE) * STAGEB;
#pragma unroll
        for (int k16 = 0; k16 < 32; k16 += 16) {
            uint32_t koff = (uint32_t)((k16 + ((lane >> 4) << 3)) * 2);
            uint32_t ah[2][4], al[2][4];
#pragma unroll
            for (int mf = 0; mf < 2; mf++) {
                int m = warp_m * 32 + mf * 16 + (lane & 15);
                uint32_t ro = (uint32_t)(m * SMS * 2) + koff;
                ldsm_x4(ah[mf], base + 0 * TILEB + ro);
                if (TERMS == 2) ldsm_x4(al[mf], base + 1 * TILEB + ro);
            }
#pragma unroll
            for (int jp = 0; jp < 4; jp++) {
                int n = warp_n * 64 + jp * 16 + (lane & 15);
                uint32_t ro = (uint32_t)(n * SMS * 2) + koff;
                uint32_t bf[4];
                ldsm_x4(bf, base + 2 * TILEB + ro);
#pragma unroll
                for (int mf = 0; mf < 2; mf++) {
                    mma16816(acc[mf][jp * 2 + 0], ah[mf], bf[0], bf[2]);
                    mma16816(acc[mf][jp * 2 + 1], ah[mf], bf[1], bf[3]);
                    if (TERMS == 2) {
                        mma16816(acc[mf][jp * 2 + 0], al[mf], bf[0], bf[2]);
                        mma16816(acc[mf][jp * 2 + 1], al[mf], bf[1], bf[3]);
                    }
                }
            }
        }
        __syncthreads();
    }
#undef ISSUE_STAGE

    int g = lane >> 2, t = lane & 3;
#pragma unroll
    for (int mf = 0; mf < 2; mf++) {
#pragma unroll
        for (int nf = 0; nf < 8; nf++) {
            int col = col0 + warp_n * 64 + nf * 8 + t * 2;
            int r0 = row0 + warp_m * 32 + mf * 16 + g;
            if (r0 < M)
                *(__half2*)(H + (size_t)r0 * 512 + col) =
                    __floats2half2_rn(acc[mf][nf][0], acc[mf][nf][1]);
            int r1 = r0 + 8;
            if (r1 < M)
                *(__half2*)(H + (size_t)r1 * 512 + col) =
                    __floats2half2_rn(acc[mf][nf][2], acc[mf][nf][3]);
        }
    }

    // fused es/ed: head = blockIdx.x
    {
        const float* asg = a_s + blockIdx.x * 128;
        const float* adg = a_d + blockIdx.x * 128;
        float ps[2][2] = {{0.f, 0.f}, {0.f, 0.f}};
        float pd[2][2] = {{0.f, 0.f}, {0.f, 0.f}};
#pragma unroll
        for (int nf = 0; nf < 8; nf++) {
#pragma unroll
            for (int j = 0; j < 2; j++) {
                int cw = warp_n * 64 + nf * 8 + t * 2 + j;
                float av = __ldg(asg + cw);
                float dv = __ldg(adg + cw);
#pragma unroll
                for (int mf = 0; mf < 2; mf++) {
                    ps[mf][0] += acc[mf][nf][j] * av;
                    ps[mf][1] += acc[mf][nf][2 + j] * av;
                    pd[mf][0] += acc[mf][nf][j] * dv;
                    pd[mf][1] += acc[mf][nf][2 + j] * dv;
                }
            }
        }
#pragma unroll
        for (int mf = 0; mf < 2; mf++)
#pragma unroll
            for (int hf = 0; hf < 2; hf++) {
#pragma unroll
                for (int off = 1; off <= 2; off <<= 1) {
                    ps[mf][hf] += __shfl_xor_sync(0xffffffffu, ps[mf][hf], off);
                    pd[mf][hf] += __shfl_xor_sync(0xffffffffu, pd[mf][hf], off);
                }
            }
        float* se = (float*)sm;
        float* sd = se + 256;
        if (t == 0) {
#pragma unroll
            for (int mf = 0; mf < 2; mf++)
#pragma unroll
                for (int hf = 0; hf < 2; hf++) {
                    int row = warp_m * 32 + mf * 16 + g + hf * 8;
                    se[row * 2 + warp_n] = ps[mf][hf];
                    sd[row * 2 + warp_n] = pd[mf][hf];
                }
        }
        __syncthreads();
        if (tid < 128) {
            int grr = row0 + tid;
            if (grr < M) {
                es[grr * 4 + blockIdx.x] = se[tid * 2] + se[tid * 2 + 1];
                ed[grr * 4 + blockIdx.x] = sd[tid * 2] + sd[tid * 2 + 1];
            }
        }
    }
}

// ---------------- fp32 -> fp16 hi/lo split (layer 0 input) -----------------
__global__ void convA_k(const float* __restrict__ X, __half* __restrict__ A2,
                        int M, int K) {
    int i = blockIdx.x * blockDim.x + threadIdx.x;
    if (i >= M * K) return;
    int r = i / K, k = i - r * K;
    float v = X[i];
    __half h = __float2half_rn(v);
    __half l = __float2half_rn(v - __half2float(h));
    size_t base = (size_t)r * 2 * K;
    A2[base + k] = h;
    A2[base + K + k] = l;
}

// W [H,K,O] -> B1 [(h*O+o), K] fp16
__global__ void convB_k(const float* __restrict__ W, __half* __restrict__ B1,
                        int K, int O) {
    int idx = blockIdx.x * blockDim.x + threadIdx.x;
    int tot = NHEADS * K * O;
    if (idx >= tot) return;
    int o = idx % O;
    int f = (idx / O) % K;
    int h = idx / (O * K);
    B1[(size_t)(h * O + o) * K + f] = __float2half_rn(W[idx]);
}

// ---------------- init: zero cnt + bn stat buffers -------------------------
__global__ void init_zero_k(int* cnt, float* bsum, float* bsq) {
    int i = blockIdx.x * blockDim.x + threadIdx.x;
    if (i < NN) cnt[i] = 0;
    if (i < 4 * HID) { bsum[i] = 0.f; bsq[i] = 0.f; }
}

__global__ void count_k(const int* __restrict__ dst, int* __restrict__ cnt) {
    int e = blockIdx.x * blockDim.x + threadIdx.x;
    if (e < NE) atomicAdd(&cnt[clampi(dst[e], 0, NN - 1)], 1);
}

__global__ void scan_k(const int* __restrict__ cnt, int* __restrict__ rowptr,
                       int* __restrict__ fill) {
    __shared__ int sh[1024];
    int tid = threadIdx.x;
    int carry = 0;
    if (tid == 0) rowptr[0] = 0;
    for (int base = 0; base < NN; base += 1024) {
        int i = base + tid;
        int v = (i < NN) ? cnt[i] : 0;
        sh[tid] = v;
        __syncthreads();
        for (int off = 1; off < 1024; off <<= 1) {
            int t = (tid >= off) ? sh[tid - off] : 0;
            __syncthreads();
            sh[tid] += t;
            __syncthreads();
        }
        int incl = sh[tid];
        if (i < NN) {
            rowptr[i + 1] = carry + incl;
            fill[i] = carry + incl - v;
        }
        carry += sh[1023];
        __syncthreads();
    }
}

__global__ void scatter_k(const int* __restrict__ dst, int* __restrict__ fill,
                          int* __restrict__ eids) {
    int e = blockIdx.x * blockDim.x + threadIdx.x;
    if (e < NE) {
        int d = clampi(dst[e], 0, NN - 1);
        int pos = atomicAdd(&fill[d], 1);
        if (pos >= 0 && pos < NE) eids[pos] = e;
    }
}

// ---------------- weight reorder (final layer) -----------------------------
__global__ void reorder_k(const float* __restrict__ W, float* __restrict__ out,
                          int K, int O) {
    int idx = blockIdx.x * blockDim.x + threadIdx.x;
    int tot = NHEADS * K * O;
    if (idx >= tot) return;
    int o = idx % O;
    int f = (idx / O) % K;
    int h = idx / (O * K);
    out[f * (NHEADS * O) + h * O + o] = W[idx];
}

// ---------------- SIMT SGEMM (final small layer) ---------------------------
#define BM 128
#define BN 128
#define BK 8
__global__ __launch_bounds__(256)
void sgemm_k(const float* __restrict__ A, const float* __restrict__ B,
             float* __restrict__ C, int M, int N, int K) {
    __shared__ float As[BK][BM];
    __shared__ float Bs[BK][BN];
    int tid = threadIdx.x;
    int row0 = blockIdx.y * BM;
    int col0 = blockIdx.x * BN;

    int aRow = tid >> 1;
    int aCol = (tid & 1) * 4;
    int bRow = tid >> 5;
    int bCol = (tid & 31) * 4;
    int ty = tid >> 4;
    int tx = tid & 15;

    float acc[8][8];
#pragma unroll
    for (int i = 0; i < 8; i++)
#pragma unroll
        for (int j = 0; j < 8; j++) acc[i][j] = 0.f;

    for (int k0 = 0; k0 < K; k0 += BK) {
        float4 av = make_float4(0.f, 0.f, 0.f, 0.f);
        int gr = row0 + aRow;
        if (gr < M) av = *(const float4*)(A + (size_t)gr * K + k0 + aCol);
        As[aCol + 0][aRow] = av.x;
        As[aCol + 1][aRow] = av.y;
        As[aCol + 2][aRow] = av.z;
        As[aCol + 3][aRow] = av.w;

        float4 bv = make_float4(0.f, 0.f, 0.f, 0.f);
        int gc = col0 + bCol;
        if (gc + 3 < N) bv = *(const float4*)(B + (size_t)(k0 + bRow) * N + gc);
        Bs[bRow][bCol + 0] = bv.x;
        Bs[bRow][bCol + 1] = bv.y;
        Bs[bRow][bCol + 2] = bv.z;
        Bs[bRow][bCol + 3] = bv.w;
        __syncthreads();

#pragma unroll
        for (int k = 0; k < BK; k++) {
            float ra[8], rb[8];
#pragma unroll
            for (int i = 0; i < 8; i++) ra[i] = As[k][ty * 8 + i];
#pragma unroll
            for (int j = 0; j < 8; j++) rb[j] = Bs[k][tx * 8 + j];
#pragma unroll
            for (int i = 0; i < 8; i++)
#pragma unroll
                for (int j = 0; j < 8; j++) acc[i][j] += ra[i] * rb[j];
        }
        __syncthreads();
    }

#pragma unroll
    for (int i = 0; i < 8; i++) {
        int r = row0 + ty * 8 + i;
        if (r >= M) continue;
#pragma unroll
        for (int j = 0; j < 8; j++) {
            int c = col0 + tx * 8 + j;
            if (c < N) C[(size_t)r * N + c] = acc[i][j];
        }
    }
}

// ---------------- es/ed (final layer only) ---------------------------------
template <int O>
__global__ void esed_k(const float* __restrict__ h, const float* __restrict__ a_s,
                       const float* __restrict__ a_d, float* __restrict__ es,
                       float* __restrict__ ed) {
    int w = (blockIdx.x * blockDim.x + threadIdx.x) >> 5;
    int lane = threadIdx.x & 31;
    if (w >= NN * NHEADS) return;
    int hd = w % NHEADS;
    const float* hp = h + (size_t)w * O;
    float s = 0.f, d = 0.f;
    for (int k = lane; k < O; k += 32) {
        float v = hp[k];
        s += v * a_s[hd * O + k];
        d += v * a_d[hd * O + k];
    }
#pragma unroll
    for (int off = 16; off; off >>= 1) {
        s += __shfl_xor_sync(0xffffffffu, s, off);
        d += __shfl_xor_sync(0xffffffffu, d, off);
    }
    if (lane == 0) { es[w] = s; ed[w] = d; }
}

__device__ __forceinline__ float lrelu02(float v) { return v > 0.f ? v : 0.2f * v; }

// ---------------- fused attention + output BN-stats ------------------------
__global__ void attn_k(const __half* __restrict__ H, const float* __restrict__ es,
                       const float* __restrict__ ed, const float* __restrict__ rel,
                       const float* __restrict__ ae, const int* __restrict__ src,
                       const int* __restrict__ etype, const int* __restrict__ edist,
                       const int* __restrict__ rowptr, const int* __restrict__ eids,
                       float4* __restrict__ alpha, const float* __restrict__ b,
                       const float* __restrict__ resid, float* __restrict__ out,
                       float* __restrict__ bsum, float* __restrict__ bsq) {
    __shared__ __align__(16) float eetab[NREL * NHEADS];
    __shared__ float ssum[HID];
    __shared__ float ssq[HID];
    int tid = threadIdx.x;
    if (tid < NREL * NHEADS) {
        int r = tid >> 2, hd = tid & 3;
        eetab[tid] = rel[r * 2] * ae[hd * 2] + rel[r * 2 + 1] * ae[hd * 2 + 1];
    }
    if (tid < HID) { ssum[tid] = 0.f; ssq[tid] = 0.f; }
    __syncthreads();

    int n = (blockIdx.x * blockDim.x + tid) >> 5;
    int lane = tid & 31;
    int beg = rowptr[n], end = rowptr[n + 1];
    float4 edn = *(const float4*)(ed + n * 4);

    float4 m = make_float4(-3.4e38f, -3.4e38f, -3.4e38f, -3.4e38f);
    for (int i = beg + lane; i < end; i += 32) {
        int e = eids[i];
        int s = clampi(src[e], 0, NN - 1);
        int t = clampi(etype[e], 0, NREL - 1);
        float4 a = *(const float4*)(es + s * 4);
        float4 c = *(const float4*)(eetab + t * 4);
        float4 lg;
        lg.x = lrelu02(a.x + edn.x + c.x);
        lg.y = lrelu02(a.y + edn.y + c.y);
        lg.z = lrelu02(a.z + edn.z + c.z);
        lg.w = lrelu02(a.w + edn.w + c.w);
        alpha[i] = lg;
        m.x = fmaxf(m.x, lg.x); m.y = fmaxf(m.y, lg.y);
        m.z = fmaxf(m.z, lg.z); m.w = fmaxf(m.w, lg.w);
    }
#pragma unroll
    for (int off = 16; off; off >>= 1) {
        m.x = fmaxf(m.x, __shfl_xor_sync(0xffffffffu, m.x, off));
        m.y = fmaxf(m.y, __shfl_xor_sync(0xffffffffu, m.y, off));
        m.z = fmaxf(m.z, __shfl_xor_sync(0xffffffffu, m.z, off));
        m.w = fmaxf(m.w, __shfl_xor_sync(0xffffffffu, m.w, off));
    }
    float4 den = make_float4(0.f, 0.f, 0.f, 0.f);
    for (int i = beg + lane; i < end; i += 32) {
        float4 v = alpha[i];
        float4 ex;
        ex.x = __expf(v.x - m.x); ex.y = __expf(v.y - m.y);
        ex.z = __expf(v.z - m.z); ex.w = __expf(v.w - m.w);
        alpha[i] = ex;
        den.x += ex.x; den.y += ex.y; den.z += ex.z; den.w += ex.w;
    }
#pragma unroll
    for (int off = 16; off; off >>= 1) {
        den.x += __shfl_xor_sync(0xffffffffu, den.x, off);
        den.y += __shfl_xor_sync(0xffffffffu, den.y, off);
        den.z += __shfl_xor_sync(0xffffffffu, den.z, off);
        den.w += __shfl_xor_sync(0xffffffffu, den.w, off);
    }
    float4 inv;
    inv.x = 1.0f / (den.x + 1e-16f); inv.y = 1.0f / (den.y + 1e-16f);
    inv.z = 1.0f / (den.z + 1e-16f); inv.w = 1.0f / (den.w + 1e-16f);
    __syncwarp();

    float2 accA[NHEADS], accB[NHEADS];
#pragma unroll
    for (int q = 0; q < NHEADS; q++) {
        accA[q] = make_float2(0.f, 0.f);
        accB[q] = make_float2(0.f, 0.f);
    }
    for (int i = beg; i < end; i++) {
        int e = eids[i];
        int s = clampi(src[e], 0, NN - 1);
        float4 a = alpha[i];
        float w = 1.0f / (1.0f + (float)edist[e]);
        float aw[4] = {a.x * inv.x * w, a.y * inv.y * w, a.z * inv.z * w,
                       a.w * inv.w * w};
        const __half2* hs2 = (const __half2*)(H + (size_t)s * 512);
#pragma unroll
        for (int q = 0; q < NHEADS; q++) {
            float2 fa = __half22float2(hs2[q * 64 + lane]);
            float2 fb = __half22float2(hs2[q * 64 + 32 + lane]);
            accA[q].x += aw[q] * fa.x; accA[q].y += aw[q] * fa.y;
            accB[q].x += aw[q] * fb.x; accB[q].y += aw[q] * fb.y;
        }
    }
    {
        int oA = 2 * lane, oB = 64 + 2 * lane;
        float2 bA = *(const float2*)(b + oA);
        float2 bB = *(const float2*)(b + oB);
        float2 vA, vB;
        vA.x = 0.25f * (accA[0].x + accA[1].x + accA[2].x + accA[3].x) + bA.x;
        vA.y = 0.25f * (accA[0].y + accA[1].y + accA[2].y + accA[3].y) + bA.y;
        vB.x = 0.25f * (accB[0].x + accB[1].x + accB[2].x + accB[3].x) + bB.x;
        vB.y = 0.25f * (accB[0].y + accB[1].y + accB[2].y + accB[3].y) + bB.y;
        if (resid) {
            float2 rA = *(const float2*)(resid + (size_t)n * 128 + oA);
            float2 rB = *(const float2*)(resid + (size_t)n * 128 + oB);
            vA.x += rA.x; vA.y += rA.y; vB.x += rB.x; vB.y += rB.y;
        }
        *(float2*)(out + (size_t)n * 128 + oA) = vA;
        *(float2*)(out + (size_t)n * 128 + oB) = vB;

        atomicAdd(&ssum[oA], vA.x);
        atomicAdd(&ssum[oA + 1], vA.y);
        atomicAdd(&ssum[oB], vB.x);
        atomicAdd(&ssum[oB + 1], vB.y);
        atomicAdd(&ssq[oA], vA.x * vA.x);
        atomicAdd(&ssq[oA + 1], vA.y * vA.y);
        atomicAdd(&ssq[oB], vB.x * vB.x);
        atomicAdd(&ssq[oB + 1], vB.y * vB.y);
    }
    __syncthreads();
    if (tid < HID) {
        atomicAdd(&bsum[tid], ssum[tid]);
        atomicAdd(&bsq[tid], ssq[tid]);
    }
}

// ---------------- final-layer softmax (standalone, eetab smem) -------------
__global__ void lsm_k(const float* __restrict__ es, const float* __restrict__ ed,
                      const float* __restrict__ rel, const float* __restrict__ ae,
                      const int* __restrict__ src, const int* __restrict__ etype,
                      const int* __restrict__ edist, const int* __restrict__ rowptr,
                      const int* __restrict__ eids, float4* __restrict__ alpha) {
    __shared__ __align__(16) float eetab[NREL * NHEADS];
    int tid = threadIdx.x;
    if (tid < NREL * NHEADS) {
        int r = tid >> 2, hd = tid & 3;
        eetab[tid] = rel[r * 2] * ae[hd * 2] + rel[r * 2 + 1] * ae[hd * 2 + 1];
    }
    __syncthreads();

    int n = (blockIdx.x * blockDim.x + tid) >> 5;
    int lane = tid & 31;
    if (n >= NN) return;
    int beg = rowptr[n], end = rowptr[n + 1];
    float4 edn = *(const float4*)(ed + n * 4);

    float4 m = make_float4(-3.4e38f, -3.4e38f, -3.4e38f, -3.4e38f);
    for (int i = beg + lane; i < end; i += 32) {
        int e = eids[i];
        int s = clampi(src[e], 0, NN - 1);
        int t = clampi(etype[e], 0, NREL - 1);
        float4 a = *(const float4*)(es + s * 4);
        float4 c = *(const float4*)(eetab + t * 4);
        float4 lg;
        lg.x = lrelu02(a.x + edn.x + c.x);
        lg.y = lrelu02(a.y + edn.y + c.y);
        lg.z = lrelu02(a.z + edn.z + c.z);
        lg.w = lrelu02(a.w + edn.w + c.w);
        alpha[i] = lg;
        m.x = fmaxf(m.x, lg.x); m.y = fmaxf(m.y, lg.y);
        m.z = fmaxf(m.z, lg.z); m.w = fmaxf(m.w, lg.w);
    }
#pragma unroll
    for (int off = 16; off; off >>= 1) {
        m.x = fmaxf(m.x, __shfl_xor_sync(0xffffffffu, m.x, off));
        m.y = fmaxf(m.y, __shfl_xor_sync(0xffffffffu, m.y, off));
        m.z = fmaxf(m.z, __shfl_xor_sync(0xffffffffu, m.z, off));
        m.w = fmaxf(m.w, __shfl_xor_sync(0xffffffffu, m.w, off));
    }
    float4 den = make_float4(0.f, 0.f, 0.f, 0.f);
    for (int i = beg + lane; i < end; i += 32) {
        float4 v = alpha[i];
        float4 ex;
        ex.x = __expf(v.x - m.x); ex.y = __expf(v.y - m.y);
        ex.z = __expf(v.z - m.z); ex.w = __expf(v.w - m.w);
        alpha[i] = ex;
        den.x += ex.x; den.y += ex.y; den.z += ex.z; den.w += ex.w;
    }
#pragma unroll
    for (int off = 16; off; off >>= 1) {
        den.x += __shfl_xor_sync(0xffffffffu, den.x, off);
        den.y += __shfl_xor_sync(0xffffffffu, den.y, off);
        den.z += __shfl_xor_sync(0xffffffffu, den.z, off);
        den.w += __shfl_xor_sync(0xffffffffu, den.w, off);
    }
    float4 inv;
    inv.x = 1.0f / (den.x + 1e-16f); inv.y = 1.0f / (den.y + 1e-16f);
    inv.z = 1.0f / (den.z + 1e-16f); inv.w = 1.0f / (den.w + 1e-16f);
    for (int i = beg + lane; i < end; i += 32) {
        float4 v = alpha[i];
        float w = 1.0f / (1.0f + (float)edist[eids[i]]);
        v.x *= inv.x * w; v.y *= inv.y * w;
        v.z *= inv.z * w; v.w *= inv.w * w;
        alpha[i] = v;
    }
}

// ---------------- final layer gather (O=9) + combine + lrelu ---------------
__global__ void aggF_k(const float* __restrict__ h, const float4* __restrict__ alpha4,
                       const int* __restrict__ src, const int* __restrict__ eids,
                       const int* __restrict__ rowptr, const float* __restrict__ b,
                       float* __restrict__ out) {
    int n = (blockIdx.x * blockDim.x + threadIdx.x) >> 5;
    int lane = threadIdx.x & 31;
    if (n >= NN) return;
    int beg = rowptr[n], end = rowptr[n + 1];
    float acc[NHEADS] = {0.f, 0.f, 0.f, 0.f};
    for (int i = beg; i < end; i++) {
        int e = eids[i];
        int s = clampi(src[e], 0, NN - 1);
        float4 a = alpha4[i];
        float aw[4] = {a.x, a.y, a.z, a.w};
        if (lane < NCLS) {
            const float* hs = h + (size_t)s * (NHEADS * NCLS);
#pragma unroll
            for (int q = 0; q < NHEADS; q++) acc[q] += aw[q] * hs[q * NCLS + lane];
        }
    }
    if (lane < NCLS) {
        float v = 0.25f * (acc[0] + acc[1] + acc[2] + acc[3]) + b[lane];
        out[(size_t)n * NCLS + lane] = v > 0.f ? v : 0.1f * v;
    }
}

// ---------------- batch norm apply -----------------------------------------
__global__ void bn_apply_k(const float* __restrict__ x, const float* __restrict__ sum,
                           const float* __restrict__ sumsq, const float* __restrict__ g,
                           const float* __restrict__ b, float* __restrict__ out,
                           __half* __restrict__ A2) {
    int i = blockIdx.x * blockDim.x + threadIdx.x;
    if (i >= NN * HID) return;
    int o = i & 127;
    int n = i >> 7;
    float mu = sum[o] * (1.0f / NN);
    float var = sumsq[o] * (1.0f / NN) - mu * mu;
    float v = (x[i] - mu) * rsqrtf(var + 1e-5f) * g[o] + b[o];
    v = v > 0.f ? v : 0.1f * v;
    out[i] = v;
    if (A2) {
        __half h = __float2half_rn(v);
        __half l = __float2half_rn(v - __half2float(h));
        size_t base = (size_t)n * 256;
        A2[base + o] = h;
        A2[base + 128 + o] = l;
    }
}

// ---------------- host orchestration ---------------------------------------
struct Bufs {
    float *h_buf, *tmp, *xb, *hin, *es, *ed, *Wb, *bsum, *bsq;
    __half *Hh, *A2, *B1;
    int *cnt, *rowptr, *fill, *eids;
};

extern "C" void kernel_launch(void* const* d_in, const int* in_sizes, int n_in,
                              void* d_out, int out_size) {
    const float* x = (const float*)d_in[0];
    const int* ei = (const int*)d_in[1];
    const int* etype = (const int*)d_in[2];
    const int* edist = (const int*)d_in[3];
    const float* W0 = (const float*)d_in[4];
    const float* asrc0 = (const float*)d_in[5];
    const float* adst0 = (const float*)d_in[6];
    const float* aedge0 = (const float*)d_in[7];
    const float* b0 = (const float*)d_in[8];
    const float* rel0 = (const float*)d_in[9];
    const float* Wm = (const float*)d_in[10];
    const float* asrcm = (const float*)d_in[11];
    const float* adstm = (const float*)d_in[12];
    const float* aedgem = (const float*)d_in[13];
    const float* bm = (const float*)d_in[14];
    const float* relm = (const float*)d_in[15];
    const float* WL = (const float*)d_in[16];
    const float* asrcL = (const float*)d_in[17];
    const float* adstL = (const float*)d_in[18];
    const float* aedgeL = (const float*)d_in[19];
    const float* bL = (const float*)d_in[20];
    const float* relL = (const float*)d_in[21];
    const float* bn_g = (const float*)d_in[22];
    const float* bn_b = (const float*)d_in[23];

    static bool attr_set = false;
    if (!attr_set) {
        cudaFuncSetAttribute(mma_gemm_k<2>, cudaFuncAttributeMaxDynamicSharedMemorySize,
                             NSTAGE * STAGEB);
        cudaFuncSetAttribute(mma_gemm_k<1>, cudaFuncAttributeMaxDynamicSharedMemorySize,
                             NSTAGE * STAGEB);
        attr_set = true;
    }

    Bufs B;
    cudaGetSymbolAddress((void**)&B.h_buf, g_h);
    cudaGetSymbolAddress((void**)&B.Hh, g_Hh);
    cudaGetSymbolAddress((void**)&B.tmp, g_tmp);
    cudaGetSymbolAddress((void**)&B.xb, g_x);
    cudaGetSymbolAddress((void**)&B.hin, g_hin);
    cudaGetSymbolAddress((void**)&B.es, g_es);
    cudaGetSymbolAddress((void**)&B.ed, g_ed);
    cudaGetSymbolAddress((void**)&B.Wb, g_W);
    cudaGetSymbolAddress((void**)&B.bsum, g_bsum);
    cudaGetSymbolAddress((void**)&B.bsq, g_bsq);
    cudaGetSymbolAddress((void**)&B.A2, g_A2);
    cudaGetSymbolAddress((void**)&B.B1, g_B1);
    cudaGetSymbolAddress((void**)&B.cnt, g_cnt);
    cudaGetSymbolAddress((void**)&B.rowptr, g_rowptr);
    cudaGetSymbolAddress((void**)&B.fill, g_fill);
    cudaGetSymbolAddress((void**)&B.eids, g_eids);

    const int* src = ei;
    const int* dst = ei + NE;
    float4* lg4 = (float4*)B.tmp;
    dim3 ggrid(4, (NN + 127) / 128);
    int attn_blocks = (NN * 32) / 256;

    // layer-0: convA(1), convB(2), init(3), mma(4 = profiled slot)
    int na = NN * FIN;
    convA_k<<<(na + 255) / 256, 256>>>(x, B.A2, NN, FIN);
    int nb = NHEADS * FIN * HID;
    convB_k<<<(nb + 255) / 256, 256>>>(W0, B.B1, FIN, HID);
    init_zero_k<<<(NN + 255) / 256, 256>>>(B.cnt, B.bsum, B.bsq);
    mma_gemm_k<2><<<ggrid, 256, NSTAGE * STAGEB>>>(B.A2, B.B1, asrc0, adst0,
                                                   B.Hh, B.es, B.ed, NN, FIN);
    count_k<<<(NE + 255) / 256, 256>>>(dst, B.cnt);
    scan_k<<<1, 1024>>>(B.cnt, B.rowptr, B.fill);
    scatter_k<<<(NE + 255) / 256, 256>>>(dst, B.fill, B.eids);
    attn_k<<<attn_blocks, 256>>>(B.Hh, B.es, B.ed, rel0, aedge0, src, etype,
                                 edist, B.rowptr, B.eids, lg4, b0, nullptr, B.xb,
                                 B.bsum, B.bsq);

    int nb128 = (NN * HID + 255) / 256;

    for (int i = 0; i < 3; i++) {
        bn_apply_k<<<nb128, 256>>>(B.xb, B.bsum + i * HID, B.bsq + i * HID,
                                   bn_g + i * HID, bn_b + i * HID, B.hin, B.A2);
        int nbm = NHEADS * HID * HID;
        convB_k<<<(nbm + 255) / 256, 256>>>(Wm + (size_t)i * NHEADS * HID * HID,
                                            B.B1, HID, HID);
        mma_gemm_k<1><<<ggrid, 256, NSTAGE * STAGEB>>>(
            B.A2, B.B1, asrcm + i * NHEADS * HID, adstm + i * NHEADS * HID,
            B.Hh, B.es, B.ed, NN, HID);
        attn_k<<<attn_blocks, 256>>>(B.Hh, B.es, B.ed, relm + i * NREL * 2,
                                     aedgem + i * NHEADS * 2, src, etype, edist,
                                     B.rowptr, B.eids, lg4, bm + i * HID, B.hin,
                                     B.xb, B.bsum + (i + 1) * HID,
                                     B.bsq + (i + 1) * HID);
    }

    // final layer
    bn_apply_k<<<nb128, 256>>>(B.xb, B.bsum + 3 * HID, B.bsq + 3 * HID,
                               bn_g + 3 * HID, bn_b + 3 * HID, B.hin,
                               (__half*)nullptr);
    {
        int tot = NHEADS * HID * NCLS;
        reorder_k<<<(tot + 255) / 256, 256>>>(WL, B.Wb, HID, NCLS);
        int Ncols = NHEADS * NCLS;
        dim3 grid((Ncols + BN - 1) / BN, (NN + BM - 1) / BM);
        sgemm_k<<<grid, 256>>>(B.hin, B.Wb, B.h_buf, NN, Ncols, HID);
        int warps = NN * NHEADS;
        int blocks = (warps * 32 + 255) / 256;
        esed_k<NCLS><<<blocks, 256>>>(B.h_buf, asrcL, adstL, B.es, B.ed);
        lsm_k<<<(NN * 32 + 255) / 256, 256>>>(B.es, B.ed, relL, aedgeL, src,
                                              etype, edist, B.rowptr, B.eids, lg4);
        aggF_k<<<(NN * 32 + 255) / 256, 256>>>(B.h_buf, lg4, src, B.eids,
                                               B.rowptr, bL, (float*)d_out);
    }
}

// round 16
// speedup vs baseline: 1.2101x; 1.0928x over previous
#include <cuda_runtime.h>
#include <cuda_fp16.h>
#include <math.h>
#include <stdint.h>

#define NN 20000
#define NE 320000
#define NHEADS 4
#define NREL 40
#define FIN 768
#define HID 128
#define NCLS 9

// ---------------- scratch ---------------------------------------------------
__device__ __align__(16) float g_h[NN * NHEADS * HID];
__device__ __align__(16) __half g_Hh[NN * NHEADS * HID];
__device__ __align__(16) float g_tmp[NN * NHEADS * HID];
__device__ __align__(16) float g_x[NN * HID];
__device__ __align__(16) float g_hin[NN * HID];
__device__ __align__(16) float g_es[NN * NHEADS];
__device__ __align__(16) float g_ed[NN * NHEADS];
__device__ __align__(16) float g_W[FIN * NHEADS * HID];
__device__ __align__(16) __half g_A2[NN * 2 * FIN];
__device__ __align__(16) __half g_B1[(NHEADS * HID) * FIN];
__device__ int g_cnt[NN];
__device__ int g_rowptr[NN + 1];
__device__ int g_fill[NN];
__device__ int g_eids[NE];
__device__ float g_bsum[4 * HID];
__device__ float g_bsq[4 * HID];

__device__ __forceinline__ int clampi(int v, int lo, int hi) {
    return v < lo ? lo : (v > hi ? hi : v);
}

__device__ __forceinline__ uint32_t smem_u32(const void* p) {
    uint32_t a;
    asm("{ .reg .u64 t; cvta.to.shared.u64 t, %1; cvt.u32.u64 %0, t; }"
        : "=r"(a) : "l"(p));
    return a;
}

__device__ __forceinline__ void ldsm_x4(uint32_t* r, uint32_t addr) {
    asm volatile("ldmatrix.sync.aligned.m8n8.x4.shared.b16 {%0,%1,%2,%3}, [%4];"
                 : "=r"(r[0]), "=r"(r[1]), "=r"(r[2]), "=r"(r[3]) : "r"(addr));
}

__device__ __forceinline__ void mma16816(float* d, const uint32_t* a, uint32_t b0,
                                         uint32_t b1) {
    asm volatile(
        "mma.sync.aligned.m16n8k16.row.col.f32.f16.f16.f32 "
        "{%0,%1,%2,%3}, {%4,%5,%6,%7}, {%8,%9}, {%0,%1,%2,%3};"
        : "+f"(d[0]), "+f"(d[1]), "+f"(d[2]), "+f"(d[3])
        : "r"(a[0]), "r"(a[1]), "r"(a[2]), "r"(a[3]), "r"(b0), "r"(b1));
}

__device__ __forceinline__ void cp16(uint32_t saddr, const void* g, bool pred) {
    int sz = pred ? 16 : 0;
    asm volatile("cp.async.cg.shared.global [%0], [%1], 16, %2;"
                 :: "r"(saddr), "l"(g), "r"(sz));
}
#define CP_COMMIT() asm volatile("cp.async.commit_group;" ::: "memory")
#define CP_WAIT2() asm volatile("cp.async.wait_group 2;" ::: "memory")
#define CP_WAIT1() asm volatile("cp.async.wait_group 1;" ::: "memory")
#define CP_WAIT0() asm volatile("cp.async.wait_group 0;" ::: "memory")

// ---- fp16 GEMM, K-chunk 32, 3-stage, fp16 H, fused es/ed -------------------
// TERMS=2: A split hi/lo (2-term product). TERMS=1: hi only.
#define SMS 40
#define TILEB 10240
#define STAGEB (3 * TILEB)
#define NSTAGE 3
template <int TERMS>
__global__ void __launch_bounds__(256, 2)
mma_gemm_k(const __half* __restrict__ A2, const __half* __restrict__ B1,
           const float* __restrict__ a_s, const float* __restrict__ a_d,
           __half* __restrict__ H, float* __restrict__ es, float* __restrict__ ed,
           int M, int K) {
    extern __shared__ char sm[];
    uint32_t s0 = smem_u32(sm);
    int tid = threadIdx.x;
    int wid = tid >> 5;
    int lane = tid & 31;
    int warp_m = wid & 3;
    int warp_n = wid >> 2;
    int row0 = blockIdx.y * 128;
    int col0 = blockIdx.x * 128;

    float acc[2][8][4];
#pragma unroll
    for (int i = 0; i < 2; i++)
#pragma unroll
        for (int j = 0; j < 8; j++)
#pragma unroll
            for (int q = 0; q < 4; q++) acc[i][j][q] = 0.f;

    int ksz = K / 32;
    int lr = tid >> 1;
    int lq = (tid & 1) * 16;
    int gr = row0 + lr;
    bool aval = gr < M;
    const __half* Abase = A2 + (size_t)(aval ? gr : 0) * (2 * K);
    const __half* Bbase = B1 + (size_t)(col0 + lr) * K;
    uint32_t sA = (uint32_t)((lr * SMS + lq) * 2);

#define ISSUE_STAGE(c) do {                                              \
        int _kb = (c) * 32;                                              \
        uint32_t _b = s0 + ((c) % NSTAGE) * STAGEB;                      \
        const __half* _g;                                                \
        _g = Abase + _kb + lq;                                           \
        cp16(_b + 0 * TILEB + sA, _g, aval);                             \
        cp16(_b + 0 * TILEB + sA + 16, _g + 8, aval);                    \
        if (TERMS == 2) {                                                \
            _g = Abase + K + _kb + lq;                                   \
            cp16(_b + 1 * TILEB + sA, _g, aval);                         \
            cp16(_b + 1 * TILEB + sA + 16, _g + 8, aval);                \
        }                                                                \
        _g = Bbase + _kb + lq;                                           \
        cp16(_b + 2 * TILEB + sA, _g, true);                             \
        cp16(_b + 2 * TILEB + sA + 16, _g + 8, true);                    \
        CP_COMMIT();                                                     \
    } while (0)

    ISSUE_STAGE(0);
    if (ksz > 1) ISSUE_STAGE(1);
    for (int c = 0; c < ksz; c++) {
        if (c + 2 < ksz) {
            ISSUE_STAGE(c + 2);
            CP_WAIT2();
        } else if (c + 1 < ksz) {
            CP_WAIT1();
        } else {
            CP_WAIT0();
        }
        __syncthreads();
        uint32_t base = s0 + (c % NSTAGE) * STAGEB;
#pragma unroll
        for (int k16 = 0; k16 < 32; k16 += 16) {
            uint32_t koff = (uint32_t)((k16 + ((lane >> 4) << 3)) * 2);
            uint32_t ah[2][4], al[2][4];
#pragma unroll
            for (int mf = 0; mf < 2; mf++) {
                int m = warp_m * 32 + mf * 16 + (lane & 15);
                uint32_t ro = (uint32_t)(m * SMS * 2) + koff;
                ldsm_x4(ah[mf], base + 0 * TILEB + ro);
                if (TERMS == 2) ldsm_x4(al[mf], base + 1 * TILEB + ro);
            }
#pragma unroll
            for (int jp = 0; jp < 4; jp++) {
                int n = warp_n * 64 + jp * 16 + (lane & 15);
                uint32_t ro = (uint32_t)(n * SMS * 2) + koff;
                uint32_t bf[4];
                ldsm_x4(bf, base + 2 * TILEB + ro);
#pragma unroll
                for (int mf = 0; mf < 2; mf++) {
                    mma16816(acc[mf][jp * 2 + 0], ah[mf], bf[0], bf[2]);
                    mma16816(acc[mf][jp * 2 + 1], ah[mf], bf[1], bf[3]);
                    if (TERMS == 2) {
                        mma16816(acc[mf][jp * 2 + 0], al[mf], bf[0], bf[2]);
                        mma16816(acc[mf][jp * 2 + 1], al[mf], bf[1], bf[3]);
                    }
                }
            }
        }
        __syncthreads();
    }
#undef ISSUE_STAGE

    int g = lane >> 2, t = lane & 3;
#pragma unroll
    for (int mf = 0; mf < 2; mf++) {
#pragma unroll
        for (int nf = 0; nf < 8; nf++) {
            int col = col0 + warp_n * 64 + nf * 8 + t * 2;
            int r0 = row0 + warp_m * 32 + mf * 16 + g;
            if (r0 < M)
                *(__half2*)(H + (size_t)r0 * 512 + col) =
                    __floats2half2_rn(acc[mf][nf][0], acc[mf][nf][1]);
            int r1 = r0 + 8;
            if (r1 < M)
                *(__half2*)(H + (size_t)r1 * 512 + col) =
                    __floats2half2_rn(acc[mf][nf][2], acc[mf][nf][3]);
        }
    }

    // fused es/ed: head = blockIdx.x
    {
        const float* asg = a_s + blockIdx.x * 128;
        const float* adg = a_d + blockIdx.x * 128;
        float ps[2][2] = {{0.f, 0.f}, {0.f, 0.f}};
        float pd[2][2] = {{0.f, 0.f}, {0.f, 0.f}};
#pragma unroll
        for (int nf = 0; nf < 8; nf++) {
#pragma unroll
            for (int j = 0; j < 2; j++) {
                int cw = warp_n * 64 + nf * 8 + t * 2 + j;
                float av = __ldg(asg + cw);
                float dv = __ldg(adg + cw);
#pragma unroll
                for (int mf = 0; mf < 2; mf++) {
                    ps[mf][0] += acc[mf][nf][j] * av;
                    ps[mf][1] += acc[mf][nf][2 + j] * av;
                    pd[mf][0] += acc[mf][nf][j] * dv;
                    pd[mf][1] += acc[mf][nf][2 + j] * dv;
                }
            }
        }
#pragma unroll
        for (int mf = 0; mf < 2; mf++)
#pragma unroll
            for (int hf = 0; hf < 2; hf++) {
#pragma unroll
                for (int off = 1; off <= 2; off <<= 1) {
                    ps[mf][hf] += __shfl_xor_sync(0xffffffffu, ps[mf][hf], off);
                    pd[mf][hf] += __shfl_xor_sync(0xffffffffu, pd[mf][hf], off);
                }
            }
        float* se = (float*)sm;
        float* sd = se + 256;
        if (t == 0) {
#pragma unroll
            for (int mf = 0; mf < 2; mf++)
#pragma unroll
                for (int hf = 0; hf < 2; hf++) {
                    int row = warp_m * 32 + mf * 16 + g + hf * 8;
                    se[row * 2 + warp_n] = ps[mf][hf];
                    sd[row * 2 + warp_n] = pd[mf][hf];
                }
        }
        __syncthreads();
        if (tid < 128) {
            int grr = row0 + tid;
            if (grr < M) {
                es[grr * 4 + blockIdx.x] = se[tid * 2] + se[tid * 2 + 1];
                ed[grr * 4 + blockIdx.x] = sd[tid * 2] + sd[tid * 2 + 1];
            }
        }
    }
}

// ---------------- fp32 -> fp16 (hi only; layer 0 input) --------------------
__global__ void convA_k(const float* __restrict__ X, __half* __restrict__ A2,
                        int M, int K) {
    int i = blockIdx.x * blockDim.x + threadIdx.x;
    if (i >= M * K) return;
    int r = i / K, k = i - r * K;
    A2[(size_t)r * 2 * K + k] = __float2half_rn(X[i]);
}

// W [H,K,O] -> B1 [(h*O+o), K] fp16
__global__ void convB_k(const float* __restrict__ W, __half* __restrict__ B1,
                        int K, int O) {
    int idx = blockIdx.x * blockDim.x + threadIdx.x;
    int tot = NHEADS * K * O;
    if (idx >= tot) return;
    int o = idx % O;
    int f = (idx / O) % K;
    int h = idx / (O * K);
    B1[(size_t)(h * O + o) * K + f] = __float2half_rn(W[idx]);
}

// ---------------- init: zero cnt + bn stat buffers -------------------------
__global__ void init_zero_k(int* cnt, float* bsum, float* bsq) {
    int i = blockIdx.x * blockDim.x + threadIdx.x;
    if (i < NN) cnt[i] = 0;
    if (i < 4 * HID) { bsum[i] = 0.f; bsq[i] = 0.f; }
}

__global__ void count_k(const int* __restrict__ dst, int* __restrict__ cnt) {
    int e = blockIdx.x * blockDim.x + threadIdx.x;
    if (e < NE) atomicAdd(&cnt[clampi(dst[e], 0, NN - 1)], 1);
}

__global__ void scan_k(const int* __restrict__ cnt, int* __restrict__ rowptr,
                       int* __restrict__ fill) {
    __shared__ int sh[1024];
    int tid = threadIdx.x;
    int carry = 0;
    if (tid == 0) rowptr[0] = 0;
    for (int base = 0; base < NN; base += 1024) {
        int i = base + tid;
        int v = (i < NN) ? cnt[i] : 0;
        sh[tid] = v;
        __syncthreads();
        for (int off = 1; off < 1024; off <<= 1) {
            int t = (tid >= off) ? sh[tid - off] : 0;
            __syncthreads();
            sh[tid] += t;
            __syncthreads();
        }
        int incl = sh[tid];
        if (i < NN) {
            rowptr[i + 1] = carry + incl;
            fill[i] = carry + incl - v;
        }
        carry += sh[1023];
        __syncthreads();
    }
}

__global__ void scatter_k(const int* __restrict__ dst, int* __restrict__ fill,
                          int* __restrict__ eids) {
    int e = blockIdx.x * blockDim.x + threadIdx.x;
    if (e < NE) {
        int d = clampi(dst[e], 0, NN - 1);
        int pos = atomicAdd(&fill[d], 1);
        if (pos >= 0 && pos < NE) eids[pos] = e;
    }
}

// ---------------- weight reorder (final layer) -----------------------------
__global__ void reorder_k(const float* __restrict__ W, float* __restrict__ out,
                          int K, int O) {
    int idx = blockIdx.x * blockDim.x + threadIdx.x;
    int tot = NHEADS * K * O;
    if (idx >= tot) return;
    int o = idx % O;
    int f = (idx / O) % K;
    int h = idx / (O * K);
    out[f * (NHEADS * O) + h * O + o] = W[idx];
}

// ---------------- SIMT SGEMM (final small layer) ---------------------------
#define BM 128
#define BN 128
#define BK 8
__global__ __launch_bounds__(256)
void sgemm_k(const float* __restrict__ A, const float* __restrict__ B,
             float* __restrict__ C, int M, int N, int K) {
    __shared__ float As[BK][BM];
    __shared__ float Bs[BK][BN];
    int tid = threadIdx.x;
    int row0 = blockIdx.y * BM;
    int col0 = blockIdx.x * BN;

    int aRow = tid >> 1;
    int aCol = (tid & 1) * 4;
    int bRow = tid >> 5;
    int bCol = (tid & 31) * 4;
    int ty = tid >> 4;
    int tx = tid & 15;

    float acc[8][8];
#pragma unroll
    for (int i = 0; i < 8; i++)
#pragma unroll
        for (int j = 0; j < 8; j++) acc[i][j] = 0.f;

    for (int k0 = 0; k0 < K; k0 += BK) {
        float4 av = make_float4(0.f, 0.f, 0.f, 0.f);
        int gr = row0 + aRow;
        if (gr < M) av = *(const float4*)(A + (size_t)gr * K + k0 + aCol);
        As[aCol + 0][aRow] = av.x;
        As[aCol + 1][aRow] = av.y;
        As[aCol + 2][aRow] = av.z;
        As[aCol + 3][aRow] = av.w;

        float4 bv = make_float4(0.f, 0.f, 0.f, 0.f);
        int gc = col0 + bCol;
        if (gc + 3 < N) bv = *(const float4*)(B + (size_t)(k0 + bRow) * N + gc);
        Bs[bRow][bCol + 0] = bv.x;
        Bs[bRow][bCol + 1] = bv.y;
        Bs[bRow][bCol + 2] = bv.z;
        Bs[bRow][bCol + 3] = bv.w;
        __syncthreads();

#pragma unroll
        for (int k = 0; k < BK; k++) {
            float ra[8], rb[8];
#pragma unroll
            for (int i = 0; i < 8; i++) ra[i] = As[k][ty * 8 + i];
#pragma unroll
            for (int j = 0; j < 8; j++) rb[j] = Bs[k][tx * 8 + j];
#pragma unroll
            for (int i = 0; i < 8; i++)
#pragma unroll
                for (int j = 0; j < 8; j++) acc[i][j] += ra[i] * rb[j];
        }
        __syncthreads();
    }

#pragma unroll
    for (int i = 0; i < 8; i++) {
        int r = row0 + ty * 8 + i;
        if (r >= M) continue;
#pragma unroll
        for (int j = 0; j < 8; j++) {
            int c = col0 + tx * 8 + j;
            if (c < N) C[(size_t)r * N + c] = acc[i][j];
        }
    }
}

// ---------------- es/ed (final layer only) ---------------------------------
template <int O>
__global__ void esed_k(const float* __restrict__ h, const float* __restrict__ a_s,
                       const float* __restrict__ a_d, float* __restrict__ es,
                       float* __restrict__ ed) {
    int w = (blockIdx.x * blockDim.x + threadIdx.x) >> 5;
    int lane = threadIdx.x & 31;
    if (w >= NN * NHEADS) return;
    int hd = w % NHEADS;
    const float* hp = h + (size_t)w * O;
    float s = 0.f, d = 0.f;
    for (int k = lane; k < O; k += 32) {
        float v = hp[k];
        s += v * a_s[hd * O + k];
        d += v * a_d[hd * O + k];
    }
#pragma unroll
    for (int off = 16; off; off >>= 1) {
        s += __shfl_xor_sync(0xffffffffu, s, off);
        d += __shfl_xor_sync(0xffffffffu, d, off);
    }
    if (lane == 0) { es[w] = s; ed[w] = d; }
}

__device__ __forceinline__ float lrelu02(float v) { return v > 0.f ? v : 0.2f * v; }

// ---------------- fused attention + output BN-stats ------------------------
__global__ void attn_k(const __half* __restrict__ H, const float* __restrict__ es,
                       const float* __restrict__ ed, const float* __restrict__ rel,
                       const float* __restrict__ ae, const int* __restrict__ src,
                       const int* __restrict__ etype, const int* __restrict__ edist,
                       const int* __restrict__ rowptr, const int* __restrict__ eids,
                       float4* __restrict__ alpha, const float* __restrict__ b,
                       const float* __restrict__ resid, float* __restrict__ out,
                       float* __restrict__ bsum, float* __restrict__ bsq) {
    __shared__ __align__(16) float eetab[NREL * NHEADS];
    __shared__ float ssum[HID];
    __shared__ float ssq[HID];
    int tid = threadIdx.x;
    if (tid < NREL * NHEADS) {
        int r = tid >> 2, hd = tid & 3;
        eetab[tid] = rel[r * 2] * ae[hd * 2] + rel[r * 2 + 1] * ae[hd * 2 + 1];
    }
    if (tid < HID) { ssum[tid] = 0.f; ssq[tid] = 0.f; }
    __syncthreads();

    int n = (blockIdx.x * blockDim.x + tid) >> 5;
    int lane = tid & 31;
    int beg = rowptr[n], end = rowptr[n + 1];
    float4 edn = *(const float4*)(ed + n * 4);

    float4 m = make_float4(-3.4e38f, -3.4e38f, -3.4e38f, -3.4e38f);
    for (int i = beg + lane; i < end; i += 32) {
        int e = eids[i];
        int s = clampi(src[e], 0, NN - 1);
        int t = clampi(etype[e], 0, NREL - 1);
        float4 a = *(const float4*)(es + s * 4);
        float4 c = *(const float4*)(eetab + t * 4);
        float4 lg;
        lg.x = lrelu02(a.x + edn.x + c.x);
        lg.y = lrelu02(a.y + edn.y + c.y);
        lg.z = lrelu02(a.z + edn.z + c.z);
        lg.w = lrelu02(a.w + edn.w + c.w);
        alpha[i] = lg;
        m.x = fmaxf(m.x, lg.x); m.y = fmaxf(m.y, lg.y);
        m.z = fmaxf(m.z, lg.z); m.w = fmaxf(m.w, lg.w);
    }
#pragma unroll
    for (int off = 16; off; off >>= 1) {
        m.x = fmaxf(m.x, __shfl_xor_sync(0xffffffffu, m.x, off));
        m.y = fmaxf(m.y, __shfl_xor_sync(0xffffffffu, m.y, off));
        m.z = fmaxf(m.z, __shfl_xor_sync(0xffffffffu, m.z, off));
        m.w = fmaxf(m.w, __shfl_xor_sync(0xffffffffu, m.w, off));
    }
    float4 den = make_float4(0.f, 0.f, 0.f, 0.f);
    for (int i = beg + lane; i < end; i += 32) {
        float4 v = alpha[i];
        float4 ex;
        ex.x = __expf(v.x - m.x); ex.y = __expf(v.y - m.y);
        ex.z = __expf(v.z - m.z); ex.w = __expf(v.w - m.w);
        alpha[i] = ex;
        den.x += ex.x; den.y += ex.y; den.z += ex.z; den.w += ex.w;
    }
#pragma unroll
    for (int off = 16; off; off >>= 1) {
        den.x += __shfl_xor_sync(0xffffffffu, den.x, off);
        den.y += __shfl_xor_sync(0xffffffffu, den.y, off);
        den.z += __shfl_xor_sync(0xffffffffu, den.z, off);
        den.w += __shfl_xor_sync(0xffffffffu, den.w, off);
    }
    float4 inv;
    inv.x = 1.0f / (den.x + 1e-16f); inv.y = 1.0f / (den.y + 1e-16f);
    inv.z = 1.0f / (den.z + 1e-16f); inv.w = 1.0f / (den.w + 1e-16f);
    __syncwarp();

    float2 accA[NHEADS], accB[NHEADS];
#pragma unroll
    for (int q = 0; q < NHEADS; q++) {
        accA[q] = make_float2(0.f, 0.f);
        accB[q] = make_float2(0.f, 0.f);
    }
    for (int i = beg; i < end; i++) {
        int e = eids[i];
        int s = clampi(src[e], 0, NN - 1);
        float4 a = alpha[i];
        float w = 1.0f / (1.0f + (float)edist[e]);
        float aw[4] = {a.x * inv.x * w, a.y * inv.y * w, a.z * inv.z * w,
                       a.w * inv.w * w};
        const __half2* hs2 = (const __half2*)(H + (size_t)s * 512);
#pragma unroll
        for (int q = 0; q < NHEADS; q++) {
            float2 fa = __half22float2(hs2[q * 64 + lane]);
            float2 fb = __half22float2(hs2[q * 64 + 32 + lane]);
            accA[q].x += aw[q] * fa.x; accA[q].y += aw[q] * fa.y;
            accB[q].x += aw[q] * fb.x; accB[q].y += aw[q] * fb.y;
        }
    }
    {
        int oA = 2 * lane, oB = 64 + 2 * lane;
        float2 bA = *(const float2*)(b + oA);
        float2 bB = *(const float2*)(b + oB);
        float2 vA, vB;
        vA.x = 0.25f * (accA[0].x + accA[1].x + accA[2].x + accA[3].x) + bA.x;
        vA.y = 0.25f * (accA[0].y + accA[1].y + accA[2].y + accA[3].y) + bA.y;
        vB.x = 0.25f * (accB[0].x + accB[1].x + accB[2].x + accB[3].x) + bB.x;
        vB.y = 0.25f * (accB[0].y + accB[1].y + accB[2].y + accB[3].y) + bB.y;
        if (resid) {
            float2 rA = *(const float2*)(resid + (size_t)n * 128 + oA);
            float2 rB = *(const float2*)(resid + (size_t)n * 128 + oB);
            vA.x += rA.x; vA.y += rA.y; vB.x += rB.x; vB.y += rB.y;
        }
        *(float2*)(out + (size_t)n * 128 + oA) = vA;
        *(float2*)(out + (size_t)n * 128 + oB) = vB;

        atomicAdd(&ssum[oA], vA.x);
        atomicAdd(&ssum[oA + 1], vA.y);
        atomicAdd(&ssum[oB], vB.x);
        atomicAdd(&ssum[oB + 1], vB.y);
        atomicAdd(&ssq[oA], vA.x * vA.x);
        atomicAdd(&ssq[oA + 1], vA.y * vA.y);
        atomicAdd(&ssq[oB], vB.x * vB.x);
        atomicAdd(&ssq[oB + 1], vB.y * vB.y);
    }
    __syncthreads();
    if (tid < HID) {
        atomicAdd(&bsum[tid], ssum[tid]);
        atomicAdd(&bsq[tid], ssq[tid]);
    }
}

// ---------------- final-layer softmax (standalone, eetab smem) -------------
__global__ void lsm_k(const float* __restrict__ es, const float* __restrict__ ed,
                      const float* __restrict__ rel, const float* __restrict__ ae,
                      const int* __restrict__ src, const int* __restrict__ etype,
                      const int* __restrict__ edist, const int* __restrict__ rowptr,
                      const int* __restrict__ eids, float4* __restrict__ alpha) {
    __shared__ __align__(16) float eetab[NREL * NHEADS];
    int tid = threadIdx.x;
    if (tid < NREL * NHEADS) {
        int r = tid >> 2, hd = tid & 3;
        eetab[tid] = rel[r * 2] * ae[hd * 2] + rel[r * 2 + 1] * ae[hd * 2 + 1];
    }
    __syncthreads();

    int n = (blockIdx.x * blockDim.x + tid) >> 5;
    int lane = tid & 31;
    if (n >= NN) return;
    int beg = rowptr[n], end = rowptr[n + 1];
    float4 edn = *(const float4*)(ed + n * 4);

    float4 m = make_float4(-3.4e38f, -3.4e38f, -3.4e38f, -3.4e38f);
    for (int i = beg + lane; i < end; i += 32) {
        int e = eids[i];
        int s = clampi(src[e], 0, NN - 1);
        int t = clampi(etype[e], 0, NREL - 1);
        float4 a = *(const float4*)(es + s * 4);
        float4 c = *(const float4*)(eetab + t * 4);
        float4 lg;
        lg.x = lrelu02(a.x + edn.x + c.x);
        lg.y = lrelu02(a.y + edn.y + c.y);
        lg.z = lrelu02(a.z + edn.z + c.z);
        lg.w = lrelu02(a.w + edn.w + c.w);
        alpha[i] = lg;
        m.x = fmaxf(m.x, lg.x); m.y = fmaxf(m.y, lg.y);
        m.z = fmaxf(m.z, lg.z); m.w = fmaxf(m.w, lg.w);
    }
#pragma unroll
    for (int off = 16; off; off >>= 1) {
        m.x = fmaxf(m.x, __shfl_xor_sync(0xffffffffu, m.x, off));
        m.y = fmaxf(m.y, __shfl_xor_sync(0xffffffffu, m.y, off));
        m.z = fmaxf(m.z, __shfl_xor_sync(0xffffffffu, m.z, off));
        m.w = fmaxf(m.w, __shfl_xor_sync(0xffffffffu, m.w, off));
    }
    float4 den = make_float4(0.f, 0.f, 0.f, 0.f);
    for (int i = beg + lane; i < end; i += 32) {
        float4 v = alpha[i];
        float4 ex;
        ex.x = __expf(v.x - m.x); ex.y = __expf(v.y - m.y);
        ex.z = __expf(v.z - m.z); ex.w = __expf(v.w - m.w);
        alpha[i] = ex;
        den.x += ex.x; den.y += ex.y; den.z += ex.z; den.w += ex.w;
    }
#pragma unroll
    for (int off = 16; off; off >>= 1) {
        den.x += __shfl_xor_sync(0xffffffffu, den.x, off);
        den.y += __shfl_xor_sync(0xffffffffu, den.y, off);
        den.z += __shfl_xor_sync(0xffffffffu, den.z, off);
        den.w += __shfl_xor_sync(0xffffffffu, den.w, off);
    }
    float4 inv;
    inv.x = 1.0f / (den.x + 1e-16f); inv.y = 1.0f / (den.y + 1e-16f);
    inv.z = 1.0f / (den.z + 1e-16f); inv.w = 1.0f / (den.w + 1e-16f);
    for (int i = beg + lane; i < end; i += 32) {
        float4 v = alpha[i];
        float w = 1.0f / (1.0f + (float)edist[eids[i]]);
        v.x *= inv.x * w; v.y *= inv.y * w;
        v.z *= inv.z * w; v.w *= inv.w * w;
        alpha[i] = v;
    }
}

// ---------------- final layer gather (O=9) + combine + lrelu ---------------
__global__ void aggF_k(const float* __restrict__ h, const float4* __restrict__ alpha4,
                       const int* __restrict__ src, const int* __restrict__ eids,
                       const int* __restrict__ rowptr, const float* __restrict__ b,
                       float* __restrict__ out) {
    int n = (blockIdx.x * blockDim.x + threadIdx.x) >> 5;
    int lane = threadIdx.x & 31;
    if (n >= NN) return;
    int beg = rowptr[n], end = rowptr[n + 1];
    float acc[NHEADS] = {0.f, 0.f, 0.f, 0.f};
    for (int i = beg; i < end; i++) {
        int e = eids[i];
        int s = clampi(src[e], 0, NN - 1);
        float4 a = alpha4[i];
        float aw[4] = {a.x, a.y, a.z, a.w};
        if (lane < NCLS) {
            const float* hs = h + (size_t)s * (NHEADS * NCLS);
#pragma unroll
            for (int q = 0; q < NHEADS; q++) acc[q] += aw[q] * hs[q * NCLS + lane];
        }
    }
    if (lane < NCLS) {
        float v = 0.25f * (acc[0] + acc[1] + acc[2] + acc[3]) + b[lane];
        out[(size_t)n * NCLS + lane] = v > 0.f ? v : 0.1f * v;
    }
}

// ---------------- batch norm apply (hi-only fp16 out) ----------------------
__global__ void bn_apply_k(const float* __restrict__ x, const float* __restrict__ sum,
                           const float* __restrict__ sumsq, const float* __restrict__ g,
                           const float* __restrict__ b, float* __restrict__ out,
                           __half* __restrict__ A2) {
    int i = blockIdx.x * blockDim.x + threadIdx.x;
    if (i >= NN * HID) return;
    int o = i & 127;
    int n = i >> 7;
    float mu = sum[o] * (1.0f / NN);
    float var = sumsq[o] * (1.0f / NN) - mu * mu;
    float v = (x[i] - mu) * rsqrtf(var + 1e-5f) * g[o] + b[o];
    v = v > 0.f ? v : 0.1f * v;
    out[i] = v;
    if (A2) A2[(size_t)n * 256 + o] = __float2half_rn(v);
}

// ---------------- host orchestration ---------------------------------------
struct Bufs {
    float *h_buf, *tmp, *xb, *hin, *es, *ed, *Wb, *bsum, *bsq;
    __half *Hh, *A2, *B1;
    int *cnt, *rowptr, *fill, *eids;
};

extern "C" void kernel_launch(void* const* d_in, const int* in_sizes, int n_in,
                              void* d_out, int out_size) {
    const float* x = (const float*)d_in[0];
    const int* ei = (const int*)d_in[1];
    const int* etype = (const int*)d_in[2];
    const int* edist = (const int*)d_in[3];
    const float* W0 = (const float*)d_in[4];
    const float* asrc0 = (const float*)d_in[5];
    const float* adst0 = (const float*)d_in[6];
    const float* aedge0 = (const float*)d_in[7];
    const float* b0 = (const float*)d_in[8];
    const float* rel0 = (const float*)d_in[9];
    const float* Wm = (const float*)d_in[10];
    const float* asrcm = (const float*)d_in[11];
    const float* adstm = (const float*)d_in[12];
    const float* aedgem = (const float*)d_in[13];
    const float* bm = (const float*)d_in[14];
    const float* relm = (const float*)d_in[15];
    const float* WL = (const float*)d_in[16];
    const float* asrcL = (const float*)d_in[17];
    const float* adstL = (const float*)d_in[18];
    const float* aedgeL = (const float*)d_in[19];
    const float* bL = (const float*)d_in[20];
    const float* relL = (const float*)d_in[21];
    const float* bn_g = (const float*)d_in[22];
    const float* bn_b = (const float*)d_in[23];

    static bool attr_set = false;
    if (!attr_set) {
        cudaFuncSetAttribute(mma_gemm_k<1>, cudaFuncAttributeMaxDynamicSharedMemorySize,
                             NSTAGE * STAGEB);
        cudaFuncSetAttribute(mma_gemm_k<2>, cudaFuncAttributeMaxDynamicSharedMemorySize,
                             NSTAGE * STAGEB);
        attr_set = true;
    }

    Bufs B;
    cudaGetSymbolAddress((void**)&B.h_buf, g_h);
    cudaGetSymbolAddress((void**)&B.Hh, g_Hh);
    cudaGetSymbolAddress((void**)&B.tmp, g_tmp);
    cudaGetSymbolAddress((void**)&B.xb, g_x);
    cudaGetSymbolAddress((void**)&B.hin, g_hin);
    cudaGetSymbolAddress((void**)&B.es, g_es);
    cudaGetSymbolAddress((void**)&B.ed, g_ed);
    cudaGetSymbolAddress((void**)&B.Wb, g_W);
    cudaGetSymbolAddress((void**)&B.bsum, g_bsum);
    cudaGetSymbolAddress((void**)&B.bsq, g_bsq);
    cudaGetSymbolAddress((void**)&B.A2, g_A2);
    cudaGetSymbolAddress((void**)&B.B1, g_B1);
    cudaGetSymbolAddress((void**)&B.cnt, g_cnt);
    cudaGetSymbolAddress((void**)&B.rowptr, g_rowptr);
    cudaGetSymbolAddress((void**)&B.fill, g_fill);
    cudaGetSymbolAddress((void**)&B.eids, g_eids);

    const int* src = ei;
    const int* dst = ei + NE;
    float4* lg4 = (float4*)B.tmp;
    dim3 ggrid(4, (NN + 127) / 128);
    int attn_blocks = (NN * 32) / 256;

    // layer-0: convA(1), convB(2), init(3), mma(4 = profiled slot)
    int na = NN * FIN;
    convA_k<<<(na + 255) / 256, 256>>>(x, B.A2, NN, FIN);
    int nb = NHEADS * FIN * HID;
    convB_k<<<(nb + 255) / 256, 256>>>(W0, B.B1, FIN, HID);
    init_zero_k<<<(NN + 255) / 256, 256>>>(B.cnt, B.bsum, B.bsq);
    mma_gemm_k<1><<<ggrid, 256, NSTAGE * STAGEB>>>(B.A2, B.B1, asrc0, adst0,
                                                   B.Hh, B.es, B.ed, NN, FIN);
    count_k<<<(NE + 255) / 256, 256>>>(dst, B.cnt);
    scan_k<<<1, 1024>>>(B.cnt, B.rowptr, B.fill);
    scatter_k<<<(NE + 255) / 256, 256>>>(dst, B.fill, B.eids);
    attn_k<<<attn_blocks, 256>>>(B.Hh, B.es, B.ed, rel0, aedge0, src, etype,
                                 edist, B.rowptr, B.eids, lg4, b0, nullptr, B.xb,
                                 B.bsum, B.bsq);

    int nb128 = (NN * HID + 255) / 256;

    for (int i = 0; i < 3; i++) {
        bn_apply_k<<<nb128, 256>>>(B.xb, B.bsum + i * HID, B.bsq + i * HID,
                                   bn_g + i * HID, bn_b + i * HID, B.hin, B.A2);
        int nbm = NHEADS * HID * HID;
        convB_k<<<(nbm + 255) / 256, 256>>>(Wm + (size_t)i * NHEADS * HID * HID,
                                            B.B1, HID, HID);
        mma_gemm_k<1><<<ggrid, 256, NSTAGE * STAGEB>>>(
            B.A2, B.B1, asrcm + i * NHEADS * HID, adstm + i * NHEADS * HID,
            B.Hh, B.es, B.ed, NN, HID);
        attn_k<<<attn_blocks, 256>>>(B.Hh, B.es, B.ed, relm + i * NREL * 2,
                                     aedgem + i * NHEADS * 2, src, etype, edist,
                                     B.rowptr, B.eids, lg4, bm + i * HID, B.hin,
                                     B.xb, B.bsum + (i + 1) * HID,
                                     B.bsq + (i + 1) * HID);
    }

    // final layer
    bn_apply_k<<<nb128, 256>>>(B.xb, B.bsum + 3 * HID, B.bsq + 3 * HID,
                               bn_g + 3 * HID, bn_b + 3 * HID, B.hin,
                               (__half*)nullptr);
    {
        int tot = NHEADS * HID * NCLS;
        reorder_k<<<(tot + 255) / 256, 256>>>(WL, B.Wb, HID, NCLS);
        int Ncols = NHEADS * NCLS;
        dim3 grid((Ncols + BN - 1) / BN, (NN + BM - 1) / BM);
        sgemm_k<<<grid, 256>>>(B.hin, B.Wb, B.h_buf, NN, Ncols, HID);
        int warps = NN * NHEADS;
        int blocks = (warps * 32 + 255) / 256;
        esed_k<NCLS><<<blocks, 256>>>(B.h_buf, asrcL, adstL, B.es, B.ed);
        lsm_k<<<(NN * 32 + 255) / 256, 256>>>(B.es, B.ed, relL, aedgeL, src,
                                              etype, edist, B.rowptr, B.eids, lg4);
        aggF_k<<<(NN * 32 + 255) / 256, 256>>>(B.h_buf, lg4, src, B.eids,
                                               B.rowptr, bL, (float*)d_out);
    }
}